// round 1
// baseline (speedup 1.0000x reference)
#include <cuda_runtime.h>
#include <cuda_bf16.h>
#include <math.h>

// Problem constants
#define B_    2
#define S_    2048
#define DIM_  2048
#define NH_   16
#define QLR_  768
#define KVLR_ 512
#define NOPE_ 128
#define ROPE_ 64
#define VDIM_ 128
#define IH_   16
#define IHD_  128
#define ITOPK_ 512
#define BS_   (B_*S_)   // 4096

// ---------------- scratch (device globals; no allocation allowed) -------------
__device__ float g_qr[BS_*QLR_];                    // 12.6MB
__device__ float g_q[BS_*NH_*(NOPE_+ROPE_)];        // 50MB
__device__ float g_kvfull[BS_*(KVLR_+ROPE_)];       // 9.4MB
__device__ float g_kv[BS_*KVLR_];                   // 8MB
__device__ float g_kpe[BS_*ROPE_];                  // 1MB
__device__ float g_qabs[BS_*NH_*KVLR_];             // 134MB
__device__ float g_qi[BS_*IH_*IHD_];                // 33.5MB
__device__ float g_ki[BS_*IHD_];                    // 2MB
__device__ float g_wts[BS_*IH_];                    // 0.26MB
__device__ float g_iscore[B_*S_*S_];                // 33.5MB
__device__ int   g_topk[BS_*ITOPK_];                // 8MB
__device__ float g_omid[BS_*NH_*KVLR_];             // 134MB
__device__ float g_o2[BS_*NH_*VDIM_];               // 33.5MB

// ---------------- generic GEMM: C[M,N] = A[M,K] @ B[N,K]^T --------------------
// 64x64 tile, 256 threads, 4x4 micro-tile, K-tile 16. z-batched via strides.
__global__ void gemm_bt(const float* __restrict__ A, int lda, long aZ,
                        const float* __restrict__ Bm, int ldb, long bZ,
                        float* __restrict__ C, int ldc, long cZ,
                        int M, int N, int K) {
    A  += (long)blockIdx.z * aZ;
    Bm += (long)blockIdx.z * bZ;
    C  += (long)blockIdx.z * cZ;
    int n0 = blockIdx.x * 64, m0 = blockIdx.y * 64;
    __shared__ float As[16][65];
    __shared__ float Bs[16][65];
    int tid = threadIdx.x;
    int tx = tid & 15, ty = tid >> 4;
    int kl = tid & 15, ml = tid >> 4;
    float acc[4][4];
#pragma unroll
    for (int i = 0; i < 4; i++)
#pragma unroll
        for (int j = 0; j < 4; j++) acc[i][j] = 0.f;

    for (int k0 = 0; k0 < K; k0 += 16) {
#pragma unroll
        for (int r = 0; r < 4; r++) {
            int mm = ml + 16*r;
            int gm = m0 + mm, gk = k0 + kl, gn = n0 + mm;
            As[kl][mm] = (gm < M && gk < K) ? A[(long)gm*lda + gk] : 0.f;
            Bs[kl][mm] = (gn < N && gk < K) ? Bm[(long)gn*ldb + gk] : 0.f;
        }
        __syncthreads();
#pragma unroll
        for (int kk = 0; kk < 16; kk++) {
            float a[4], bb[4];
#pragma unroll
            for (int i = 0; i < 4; i++) a[i]  = As[kk][ty + 16*i];
#pragma unroll
            for (int j = 0; j < 4; j++) bb[j] = Bs[kk][tx + 16*j];
#pragma unroll
            for (int i = 0; i < 4; i++)
#pragma unroll
                for (int j = 0; j < 4; j++) acc[i][j] += a[i]*bb[j];
        }
        __syncthreads();
    }
#pragma unroll
    for (int i = 0; i < 4; i++)
#pragma unroll
        for (int j = 0; j < 4; j++) {
            int gm = m0 + ty + 16*i, gn = n0 + tx + 16*j;
            if (gm < M && gn < N) C[(long)gm*ldc + gn] = acc[i][j];
        }
}

// C[M,N] = A[M,K] @ B[K,N]  (B row-major, not transposed)
__global__ void gemm_nn(const float* __restrict__ A, int lda, long aZ,
                        const float* __restrict__ Bm, int ldb, long bZ,
                        float* __restrict__ C, int ldc, long cZ,
                        int M, int N, int K) {
    A  += (long)blockIdx.z * aZ;
    Bm += (long)blockIdx.z * bZ;
    C  += (long)blockIdx.z * cZ;
    int n0 = blockIdx.x * 64, m0 = blockIdx.y * 64;
    __shared__ float As[16][65];
    __shared__ float Bs[16][65];
    int tid = threadIdx.x;
    int tx = tid & 15, ty = tid >> 4;
    int kl = tid & 15, ml = tid >> 4;
    int nl = tid & 63, k2 = tid >> 6;
    float acc[4][4];
#pragma unroll
    for (int i = 0; i < 4; i++)
#pragma unroll
        for (int j = 0; j < 4; j++) acc[i][j] = 0.f;

    for (int k0 = 0; k0 < K; k0 += 16) {
#pragma unroll
        for (int r = 0; r < 4; r++) {
            int mm = ml + 16*r;
            int gm = m0 + mm, gk = k0 + kl;
            As[kl][mm] = (gm < M && gk < K) ? A[(long)gm*lda + gk] : 0.f;
            int kk2 = k2 + 4*r;
            int gk2 = k0 + kk2, gn = n0 + nl;
            Bs[kk2][nl] = (gk2 < K && gn < N) ? Bm[(long)gk2*ldb + gn] : 0.f;
        }
        __syncthreads();
#pragma unroll
        for (int kk = 0; kk < 16; kk++) {
            float a[4], bb[4];
#pragma unroll
            for (int i = 0; i < 4; i++) a[i]  = As[kk][ty + 16*i];
#pragma unroll
            for (int j = 0; j < 4; j++) bb[j] = Bs[kk][tx + 16*j];
#pragma unroll
            for (int i = 0; i < 4; i++)
#pragma unroll
                for (int j = 0; j < 4; j++) acc[i][j] += a[i]*bb[j];
        }
        __syncthreads();
    }
#pragma unroll
    for (int i = 0; i < 4; i++)
#pragma unroll
        for (int j = 0; j < 4; j++) {
            int gm = m0 + ty + 16*i, gn = n0 + tx + 16*j;
            if (gm < M && gn < N) C[(long)gm*ldc + gn] = acc[i][j];
        }
}

// ---------------- elementwise / norm / rope -----------------------------------
__global__ void rmsnorm_kernel(float* __restrict__ x, const float* __restrict__ w, int L) {
    int row = blockIdx.x, tid = threadIdx.x;
    float* pr = x + (long)row * L;
    float ss = 0.f;
    for (int i = tid; i < L; i += 256) { float v = pr[i]; ss += v*v; }
    __shared__ float red[256];
    red[tid] = ss; __syncthreads();
    for (int o = 128; o > 0; o >>= 1) { if (tid < o) red[tid] += red[tid+o]; __syncthreads(); }
    float inv = rsqrtf(red[0] / (float)L + 1e-6f);
    for (int i = tid; i < L; i += 256) pr[i] = w[i] * pr[i] * inv;
}

__global__ void kvpost_kernel(const float* __restrict__ kvfull, const float* __restrict__ w,
                              const float* __restrict__ fcos, const float* __restrict__ fsin,
                              float* __restrict__ kv, float* __restrict__ kpe) {
    int row = blockIdx.x, s = row & (S_-1), tid = threadIdx.x;
    const float* src = kvfull + (long)row * 576;
    float ss = 0.f;
    for (int i = tid; i < 512; i += 256) { float v = src[i]; ss += v*v; }
    __shared__ float red[256];
    red[tid] = ss; __syncthreads();
    for (int o = 128; o > 0; o >>= 1) { if (tid < o) red[tid] += red[tid+o]; __syncthreads(); }
    float inv = rsqrtf(red[0] / 512.f + 1e-6f);
    for (int i = tid; i < 512; i += 256) kv[(long)row*512 + i] = w[i] * src[i] * inv;
    if (tid < 32) {
        float x1 = src[512 + tid], x2 = src[544 + tid];
        float c = fcos[s*32 + tid], sn = fsin[s*32 + tid];
        kpe[(long)row*64 + tid]      = x1*c - x2*sn;
        kpe[(long)row*64 + 32 + tid] = x1*sn + x2*c;
    }
}

__global__ void kipost_kernel(float* __restrict__ ki, const float* __restrict__ w,
                              const float* __restrict__ bvec,
                              const float* __restrict__ fcos, const float* __restrict__ fsin) {
    int row = blockIdx.x, s = row & (S_-1), tid = threadIdx.x; // 128 threads
    float* pr = ki + (long)row * 128;
    float v = pr[tid];
    __shared__ float red[128];
    red[tid] = v; __syncthreads();
    for (int o = 64; o > 0; o >>= 1) { if (tid < o) red[tid] += red[tid+o]; __syncthreads(); }
    float mean = red[0] / 128.f;
    __syncthreads();
    float d = v - mean;
    red[tid] = d*d; __syncthreads();
    for (int o = 64; o > 0; o >>= 1) { if (tid < o) red[tid] += red[tid+o]; __syncthreads(); }
    float var = red[0] / 128.f;
    __syncthreads();
    float y = d * rsqrtf(var + 1e-6f) * w[tid] + bvec[tid];
    __shared__ float yb[128];
    yb[tid] = y; __syncthreads();
    float outv;
    if (tid < 32) {
        float c = fcos[s*32 + tid], sn = fsin[s*32 + tid];
        outv = yb[tid]*c - yb[tid+32]*sn;
    } else if (tid < 64) {
        int i = tid - 32;
        float c = fcos[s*32 + i], sn = fsin[s*32 + i];
        outv = yb[i]*sn + yb[tid]*c;
    } else {
        outv = y;
    }
    pr[tid] = outv;
}

// rope on q[..., 128:192] per head (layout [BS][16][192])
__global__ void rope_q_kernel(float* __restrict__ q, const float* __restrict__ fcos,
                              const float* __restrict__ fsin) {
    int idx = blockIdx.x * blockDim.x + threadIdx.x;
    if (idx >= BS_*16*32) return;
    int i = idx & 31, h = (idx >> 5) & 15, bs = idx >> 9;
    int s = bs & (S_-1);
    long base = (long)bs*3072 + h*192 + 128;
    float x1 = q[base + i], x2 = q[base + 32 + i];
    float c = fcos[s*32 + i], sn = fsin[s*32 + i];
    q[base + i]      = x1*c - x2*sn;
    q[base + 32 + i] = x1*sn + x2*c;
}

// rope on qi[..., 0:64] per head (layout [BS][16][128])
__global__ void rope_qi_kernel(float* __restrict__ qi, const float* __restrict__ fcos,
                               const float* __restrict__ fsin) {
    int idx = blockIdx.x * blockDim.x + threadIdx.x;
    if (idx >= BS_*16*32) return;
    int i = idx & 31, h = (idx >> 5) & 15, bs = idx >> 9;
    int s = bs & (S_-1);
    long base = (long)bs*2048 + h*128;
    float x1 = qi[base + i], x2 = qi[base + 32 + i];
    float c = fcos[s*32 + i], sn = fsin[s*32 + i];
    qi[base + i]      = x1*c - x2*sn;
    qi[base + 32 + i] = x1*sn + x2*c;
}

// ---------------- indexer score ------------------------------------------------
// iscore[b][s][t] = sum_h relu(qi[b,s,h,:] . ki[b,t,:]) * w[b,s,h] + mask[s][t]
__global__ void iscore_kernel(const float* __restrict__ qi, const float* __restrict__ ki,
                              const float* __restrict__ wts, const float* __restrict__ mask,
                              float* __restrict__ iscore) {
    int b = blockIdx.z;
    int s0 = blockIdx.y * 64, t0 = blockIdx.x * 64;
    int tid = threadIdx.x;
    if (t0 > s0 + 63) {
        // fully causal-masked tile: score is dominated by the -1e9 mask
        for (int i = tid; i < 64*64; i += 256) {
            int m = i >> 6, n = i & 63;
            int s = s0 + m, t = t0 + n;
            iscore[((long)b*S_ + s)*S_ + t] = mask[(long)s*S_ + t];
        }
        return;
    }
    int tx = tid & 15, ty = tid >> 4;
    int kl = tid & 15, ml = tid >> 4;
    __shared__ float qs[16][65];
    __shared__ float ks[16][65];
    __shared__ float ws_s[16][64];
    const float IW_SCALE = rsqrtf(2048.0f); // IH^-.5 * IHD^-.5
    for (int i = tid; i < 16*64; i += 256) {
        int m = i >> 4, h = i & 15;
        ws_s[h][m] = wts[((long)(b*S_ + s0 + m))*16 + h] * IW_SCALE;
    }
    float acc[4][4];
#pragma unroll
    for (int i = 0; i < 4; i++)
#pragma unroll
        for (int j = 0; j < 4; j++) acc[i][j] = 0.f;
    __syncthreads();

    for (int h = 0; h < 16; h++) {
        float dot[4][4];
#pragma unroll
        for (int i = 0; i < 4; i++)
#pragma unroll
            for (int j = 0; j < 4; j++) dot[i][j] = 0.f;
        for (int d0 = 0; d0 < 128; d0 += 16) {
#pragma unroll
            for (int r = 0; r < 4; r++) {
                int mm = ml + 16*r;
                qs[kl][mm] = qi[((long)(b*S_ + s0 + mm))*2048 + h*128 + d0 + kl];
                ks[kl][mm] = ki[((long)(b*S_ + t0 + mm))*128 + d0 + kl];
            }
            __syncthreads();
#pragma unroll
            for (int kk = 0; kk < 16; kk++) {
                float a[4], bb[4];
#pragma unroll
                for (int i = 0; i < 4; i++) a[i]  = qs[kk][ty + 16*i];
#pragma unroll
                for (int j = 0; j < 4; j++) bb[j] = ks[kk][tx + 16*j];
#pragma unroll
                for (int i = 0; i < 4; i++)
#pragma unroll
                    for (int j = 0; j < 4; j++) dot[i][j] += a[i]*bb[j];
            }
            __syncthreads();
        }
#pragma unroll
        for (int i = 0; i < 4; i++) {
            float w = ws_s[h][ty + 16*i];
#pragma unroll
            for (int j = 0; j < 4; j++) acc[i][j] += fmaxf(dot[i][j], 0.f) * w;
        }
    }
#pragma unroll
    for (int i = 0; i < 4; i++)
#pragma unroll
        for (int j = 0; j < 4; j++) {
            int s = s0 + ty + 16*i, t = t0 + tx + 16*j;
            iscore[((long)b*S_ + s)*S_ + t] = acc[i][j] + mask[(long)s*S_ + t];
        }
}

// ---------------- exact top-512 per row (radix select, deterministic) ---------
__global__ void topk_kernel(const float* __restrict__ iscore, int* __restrict__ out) {
    int row = blockIdx.x;
    const float* p = iscore + (long)row * S_;
    int tid = threadIdx.x; // 256
    __shared__ unsigned int hist[256];
    __shared__ unsigned int s_prefix;
    __shared__ int s_rem;
    __shared__ int sgt[257], seq[257];
    if (tid == 0) { s_prefix = 0u; s_rem = ITOPK_; }
    __syncthreads();
    for (int pass = 0; pass < 4; pass++) {
        hist[tid] = 0u;
        __syncthreads();
        int shift = 24 - 8*pass;
        unsigned int pref = s_prefix;
        for (int e = 0; e < 8; e++) {
            int j = tid*8 + e;
            unsigned int u = __float_as_uint(p[j]);
            unsigned int k = (u & 0x80000000u) ? ~u : (u | 0x80000000u);
            bool ok = (pass == 0) || (((k ^ pref) >> (shift + 8)) == 0u);
            if (ok) atomicAdd(&hist[(k >> shift) & 255u], 1u);
        }
        __syncthreads();
        if (tid == 0) {
            int rem = s_rem;
            unsigned int cum = 0; int bin = 0;
            for (int bb = 255; bb >= 0; bb--) {
                if (cum + hist[bb] >= (unsigned)rem) { bin = bb; break; }
                cum += hist[bb];
            }
            s_rem = rem - (int)cum;
            s_prefix = s_prefix | ((unsigned)bin << shift);
        }
        __syncthreads();
    }
    unsigned int kth = s_prefix;
    int cgt = 0, ceq = 0;
    for (int e = 0; e < 8; e++) {
        int j = tid*8 + e;
        unsigned int u = __float_as_uint(p[j]);
        unsigned int k = (u & 0x80000000u) ? ~u : (u | 0x80000000u);
        cgt += (k > kth); ceq += (k == kth);
    }
    sgt[tid] = cgt; seq[tid] = ceq;
    __syncthreads();
    if (tid == 0) {
        int ag = 0, ae = 0;
        for (int i = 0; i < 256; i++) {
            int tg = sgt[i], te = seq[i];
            sgt[i] = ag; seq[i] = ae;
            ag += tg; ae += te;
        }
        sgt[256] = ag;
    }
    __syncthreads();
    int total_gt = sgt[256];
    int pgt = sgt[tid];
    int peq = total_gt + seq[tid];
    int* o = out + (long)row * ITOPK_;
    for (int e = 0; e < 8; e++) {
        int j = tid*8 + e;
        unsigned int u = __float_as_uint(p[j]);
        unsigned int k = (u & 0x80000000u) ? ~u : (u | 0x80000000u);
        if (k > kth) { o[pgt++] = j; }
        else if (k == kth) { if (peq < ITOPK_) o[peq] = j; peq++; }
    }
}

// ---------------- sparse attention (per (b,s), all 16 heads) -------------------
// smem: qabs[16][512] | qpe[16][64] | scores[16][512] | topk[512]
#define ATTN_SMEM ((8192 + 1024 + 8192) * 4 + 512 * 4)
__global__ void attn_kernel(const float* __restrict__ q,
                            const float* __restrict__ qabs,
                            const float* __restrict__ kv,
                            const float* __restrict__ kpe,
                            const int* __restrict__ topk,
                            float* __restrict__ omid) {
    extern __shared__ float sm[];
    float* qas  = sm;            // 8192
    float* qpes = qas + 8192;    // 1024
    float* sc   = qpes + 1024;   // 8192
    int*   tl   = (int*)(sc + 8192); // 512
    int bs = blockIdx.x, b = bs >> 11, s = bs & (S_-1);
    int tid = threadIdx.x;

    for (int i = tid; i < 8192; i += 256) qas[i] = qabs[(long)bs*8192 + i];
    for (int i = tid; i < 1024; i += 256) {
        int h = i >> 6, r = i & 63;
        qpes[i] = q[(long)bs*3072 + h*192 + 128 + r];
    }
    for (int j = tid; j < 512; j += 256) tl[j] = topk[(long)bs*512 + j];
    __syncthreads();

    // phase 1: scores (two topk slots per thread)
    {
        int j0 = tid, j1 = tid + 256;
        int t0 = tl[j0], t1 = tl[j1];
        bool v0 = (t0 <= s), v1 = (t1 <= s);
        const float4* k0 = (const float4*)(kv + ((long)(b*S_ + (v0 ? t0 : 0)))*512);
        const float4* k1 = (const float4*)(kv + ((long)(b*S_ + (v1 ? t1 : 0)))*512);
        float a0[16], a1[16];
#pragma unroll
        for (int h = 0; h < 16; h++) { a0[h] = 0.f; a1[h] = 0.f; }
        for (int d4 = 0; d4 < 128; d4++) {
            float4 x0 = k0[d4], x1 = k1[d4];
#pragma unroll
            for (int h = 0; h < 16; h++) {
                const float* qh = qas + h*512 + d4*4;
                float q0 = qh[0], q1v = qh[1], q2 = qh[2], q3 = qh[3];
                a0[h] += x0.x*q0 + x0.y*q1v + x0.z*q2 + x0.w*q3;
                a1[h] += x1.x*q0 + x1.y*q1v + x1.z*q2 + x1.w*q3;
            }
        }
        const float4* p0 = (const float4*)(kpe + ((long)(b*S_ + (v0 ? t0 : 0)))*64);
        const float4* p1 = (const float4*)(kpe + ((long)(b*S_ + (v1 ? t1 : 0)))*64);
        for (int d4 = 0; d4 < 16; d4++) {
            float4 x0 = p0[d4], x1 = p1[d4];
#pragma unroll
            for (int h = 0; h < 16; h++) {
                const float* qh = qpes + h*64 + d4*4;
                float q0 = qh[0], q1v = qh[1], q2 = qh[2], q3 = qh[3];
                a0[h] += x0.x*q0 + x0.y*q1v + x0.z*q2 + x0.w*q3;
                a1[h] += x1.x*q0 + x1.y*q1v + x1.z*q2 + x1.w*q3;
            }
        }
        const float scale = rsqrtf(192.0f);
#pragma unroll
        for (int h = 0; h < 16; h++) {
            sc[h*512 + j0] = v0 ? a0[h]*scale : -1e30f;
            sc[h*512 + j1] = v1 ? a1[h]*scale : -1e30f;
        }
    }
    __syncthreads();

    // phase 2: softmax (warp handles 2 heads)
    {
        int warp = tid >> 5, lane = tid & 31;
        for (int h = warp*2; h <= warp*2 + 1; h++) {
            float m = -1e30f;
            for (int j = lane; j < 512; j += 32) m = fmaxf(m, sc[h*512 + j]);
#pragma unroll
            for (int o = 16; o > 0; o >>= 1) m = fmaxf(m, __shfl_xor_sync(0xffffffffu, m, o));
            float ss = 0.f;
            for (int j = lane; j < 512; j += 32) {
                float e = expf(sc[h*512 + j] - m);
                sc[h*512 + j] = e;
                ss += e;
            }
#pragma unroll
            for (int o = 16; o > 0; o >>= 1) ss += __shfl_xor_sync(0xffffffffu, ss, o);
            float inv = 1.f / ss;
            for (int j = lane; j < 512; j += 32) sc[h*512 + j] *= inv;
        }
    }
    __syncthreads();

    // phase 3: o[h][c] = sum_j p[h][j] * kv[t_j][c]; thread owns columns c, c+256
    {
        int c = tid;
        float a0[16], a1[16];
#pragma unroll
        for (int h = 0; h < 16; h++) { a0[h] = 0.f; a1[h] = 0.f; }
#pragma unroll 2
        for (int j = 0; j < 512; j++) {
            int t = tl[j];
            if (t > s) continue; // uniform branch; p is exactly 0 there anyway
            const float* kr = kv + ((long)(b*S_ + t))*512;
            float v0 = kr[c], v1 = kr[c + 256];
#pragma unroll
            for (int h = 0; h < 16; h++) {
                float pp = sc[h*512 + j];
                a0[h] += pp*v0; a1[h] += pp*v1;
            }
        }
#pragma unroll
        for (int h = 0; h < 16; h++) {
            omid[(long)bs*8192 + h*512 + c]       = a0[h];
            omid[(long)bs*8192 + h*512 + c + 256] = a1[h];
        }
    }
}

// ---------------- host orchestration ------------------------------------------
extern "C" void kernel_launch(void* const* d_in, const int* in_sizes, int n_in,
                              void* d_out, int out_size) {
    const float* x      = (const float*)d_in[0];
    const float* fcos   = (const float*)d_in[1];
    const float* fsin   = (const float*)d_in[2];
    const float* mask   = (const float*)d_in[3];
    const float* wq_a   = (const float*)d_in[4];
    const float* qnw    = (const float*)d_in[5];
    const float* wq_b   = (const float*)d_in[6];
    const float* wkv_a  = (const float*)d_in[7];
    const float* kvnw   = (const float*)d_in[8];
    const float* wkv_b  = (const float*)d_in[9];
    const float* wo     = (const float*)d_in[10];
    const float* iwqb   = (const float*)d_in[11];
    const float* iwk    = (const float*)d_in[12];
    const float* iknw   = (const float*)d_in[13];
    const float* iknb   = (const float*)d_in[14];
    const float* iwp    = (const float*)d_in[15];
    float* out = (float*)d_out;

    float *qr, *q, *kvfull, *kv, *kpe, *qabs, *qi, *ki, *wts, *iscore, *omid, *o2;
    int* topkb;
    cudaGetSymbolAddress((void**)&qr,     g_qr);
    cudaGetSymbolAddress((void**)&q,      g_q);
    cudaGetSymbolAddress((void**)&kvfull, g_kvfull);
    cudaGetSymbolAddress((void**)&kv,     g_kv);
    cudaGetSymbolAddress((void**)&kpe,    g_kpe);
    cudaGetSymbolAddress((void**)&qabs,   g_qabs);
    cudaGetSymbolAddress((void**)&qi,     g_qi);
    cudaGetSymbolAddress((void**)&ki,     g_ki);
    cudaGetSymbolAddress((void**)&wts,    g_wts);
    cudaGetSymbolAddress((void**)&iscore, g_iscore);
    cudaGetSymbolAddress((void**)&topkb,  g_topk);
    cudaGetSymbolAddress((void**)&omid,   g_omid);
    cudaGetSymbolAddress((void**)&o2,     g_o2);

    cudaFuncSetAttribute(attn_kernel, cudaFuncAttributeMaxDynamicSharedMemorySize, ATTN_SMEM);

    // qr = rmsnorm(x @ wq_a^T)
    gemm_bt<<<dim3(12, 64, 1), 256>>>(x, 2048, 0, wq_a, 2048, 0, qr, 768, 0, 4096, 768, 2048);
    rmsnorm_kernel<<<4096, 256>>>(qr, qnw, 768);
    // q = qr @ wq_b^T, rope on pe slots
    gemm_bt<<<dim3(48, 64, 1), 256>>>(qr, 768, 0, wq_b, 768, 0, q, 3072, 0, 4096, 3072, 768);
    rope_q_kernel<<<(BS_*16*32 + 255)/256, 256>>>(q, fcos, fsin);
    // kv path
    gemm_bt<<<dim3(9, 64, 1), 256>>>(x, 2048, 0, wkv_a, 2048, 0, kvfull, 576, 0, 4096, 576, 2048);
    kvpost_kernel<<<4096, 256>>>(kvfull, kvnw, fcos, fsin, kv, kpe);
    // q_abs[bs,h,:] = q_nope[bs,h,:] @ wkv_b3[h,:128,:]   (batched over h)
    gemm_nn<<<dim3(8, 64, 16), 256>>>(q, 3072, 192, wkv_b, 512, 256*512, qabs, 8192, 512,
                                      4096, 512, 128);
    // indexer
    gemm_bt<<<dim3(32, 64, 1), 256>>>(qr, 768, 0, iwqb, 768, 0, qi, 2048, 0, 4096, 2048, 768);
    rope_qi_kernel<<<(BS_*16*32 + 255)/256, 256>>>(qi, fcos, fsin);
    gemm_bt<<<dim3(2, 64, 1), 256>>>(x, 2048, 0, iwk, 2048, 0, ki, 128, 0, 4096, 128, 2048);
    kipost_kernel<<<4096, 128>>>(ki, iknw, iknb, fcos, fsin);
    gemm_bt<<<dim3(1, 64, 1), 256>>>(x, 2048, 0, iwp, 2048, 0, wts, 16, 0, 4096, 16, 2048);
    iscore_kernel<<<dim3(32, 32, 2), 256>>>(qi, ki, wts, mask, iscore);
    topk_kernel<<<4096, 256>>>(iscore, topkb);
    // sparse attention
    attn_kernel<<<4096, 256, ATTN_SMEM>>>(q, qabs, kv, kpe, topkb, omid);
    // o2[bs,h*128+d] = omid[bs,h,:] @ wkv_b3[h,128:,:]^T  (batched over h)
    gemm_bt<<<dim3(2, 64, 16), 256>>>(omid, 8192, 512, wkv_b + 128*512, 512, 256*512,
                                      o2, 2048, 128, 4096, 128, 512);
    // out = o2 @ wo^T
    gemm_bt<<<dim3(32, 64, 1), 256>>>(o2, 2048, 0, wo, 2048, 0, out, 2048, 0, 4096, 2048, 2048);
}

// round 3
// speedup vs baseline: 1.2593x; 1.2593x over previous
#include <cuda_runtime.h>
#include <cuda_bf16.h>
#include <math.h>
#include <stdint.h>

// Problem constants
#define B_    2
#define S_    2048
#define DIM_  2048
#define NH_   16
#define QLR_  768
#define KVLR_ 512
#define NOPE_ 128
#define ROPE_ 64
#define VDIM_ 128
#define IH_   16
#define IHD_  128
#define ITOPK_ 512
#define BS_   (B_*S_)   // 4096

// ---------------- scratch (device globals; no allocation allowed) -------------
__device__ float g_qr[BS_*QLR_];
__device__ float g_q[BS_*NH_*(NOPE_+ROPE_)];
__device__ float g_kvfull[BS_*(KVLR_+ROPE_)];
__device__ float g_kv[BS_*KVLR_];
__device__ float g_kpe[BS_*ROPE_];
__device__ float g_qabs[BS_*NH_*KVLR_];
__device__ float g_qi[BS_*IH_*IHD_];
__device__ float g_ki[BS_*IHD_];
__device__ float g_wts[BS_*IH_];
__device__ float g_iscore[B_*S_*S_];
__device__ int   g_topk[BS_*ITOPK_];
__device__ float g_omid[BS_*NH_*KVLR_];
__device__ float g_o2[BS_*NH_*VDIM_];
__device__ float g_wkvbT[16*512*128];   // transposed wkv_b[:, :128, :] -> [h][c][d]

// =================== bf16 helpers =============================================
__device__ __forceinline__ uint32_t pack_hi(float x, float y) {
    __nv_bfloat162 p;
    p.x = __float2bfloat16_rn(x);
    p.y = __float2bfloat16_rn(y);
    return *(uint32_t*)&p;
}
__device__ __forceinline__ uint32_t pack_lo(float x, float y) {
    __nv_bfloat16 hx = __float2bfloat16_rn(x);
    __nv_bfloat16 hy = __float2bfloat16_rn(y);
    __nv_bfloat162 p;
    p.x = __float2bfloat16_rn(x - __bfloat162float(hx));
    p.y = __float2bfloat16_rn(y - __bfloat162float(hy));
    return *(uint32_t*)&p;
}
__device__ __forceinline__ void mma16816(float* c, const uint32_t* a, const uint32_t* b) {
    asm volatile("mma.sync.aligned.m16n8k16.row.col.f32.bf16.bf16.f32 "
        "{%0,%1,%2,%3}, {%4,%5,%6,%7}, {%8,%9}, {%0,%1,%2,%3};"
        : "+f"(c[0]), "+f"(c[1]), "+f"(c[2]), "+f"(c[3])
        : "r"(a[0]), "r"(a[1]), "r"(a[2]), "r"(a[3]), "r"(b[0]), "r"(b[1]));
}
// word-granularity swizzled smem address: tile is 128 rows x 16 words (32 bf16)
__device__ __forceinline__ int sw_addr(int row, int w) {
    return row*16 + (w ^ ((((row)>>1)&3)<<2));
}

// =================== tensor-core GEMM (bf16x3): C[M,N]=A[M,K]@B[N,K]^T ========
// CTA tile 128x128, Kc=32, 256 threads (8 warps as 2Mx4N), warp tile 64x32.
// smem: 2 stages x 4 tiles (Ahi,Alo,Bhi,Blo) x 8KB = 64KB.
#define GM_SMEM 65536

__global__ void __launch_bounds__(256, 1)
gemm_mma(const float* __restrict__ A, int lda, long aZ,
         const float* __restrict__ Bm, int ldb, long bZ,
         float* __restrict__ C, int ldc, long cZ,
         int M, int N, int K) {
    extern __shared__ uint32_t smw[];
    A  += (long)blockIdx.z * aZ;
    Bm += (long)blockIdx.z * bZ;
    C  += (long)blockIdx.z * cZ;
    int m0 = blockIdx.y * 128, n0 = blockIdx.x * 128;
    int tid = threadIdx.x, lane = tid & 31, wid = tid >> 5;
    int wm = wid >> 2, wn = wid & 3;             // warp grid 2 x 4
    int g = lane >> 2, tig = lane & 3;

    float acc[4][4][4];
#pragma unroll
    for (int i = 0; i < 4; i++)
#pragma unroll
        for (int j = 0; j < 4; j++)
#pragma unroll
            for (int r = 0; r < 4; r++) acc[i][j][r] = 0.f;

    int arow = tid >> 1, acol = (tid & 1) * 16;  // 16 consecutive floats per thread
    int nch = K >> 5;

    float4 ra[4], rb[4];
    // ---- load chunk 0 into regs
    {
        const float* ap = A + (long)(m0 + arow)*lda + acol;
        bool aok = (m0 + arow) < M;
#pragma unroll
        for (int i = 0; i < 4; i++)
            ra[i] = aok ? *(const float4*)(ap + i*4) : make_float4(0.f,0.f,0.f,0.f);
        const float* bp = Bm + (long)(n0 + arow)*ldb + acol;
        bool bok = (n0 + arow) < N;
#pragma unroll
        for (int i = 0; i < 4; i++)
            rb[i] = bok ? *(const float4*)(bp + i*4) : make_float4(0.f,0.f,0.f,0.f);
    }

    for (int it = 0; it < nch; it++) {
        int stg = it & 1;
        uint32_t* sAhi = smw + stg*8192;
        uint32_t* sAlo = sAhi + 2048;
        uint32_t* sBhi = sAhi + 4096;
        uint32_t* sBlo = sAhi + 6144;
        // ---- store staged regs (chunk it) to smem, hi/lo split
        {
            uint32_t hw[8], lw[8];
#pragma unroll
            for (int i = 0; i < 4; i++) {
                hw[i*2]   = pack_hi(ra[i].x, ra[i].y);
                hw[i*2+1] = pack_hi(ra[i].z, ra[i].w);
                lw[i*2]   = pack_lo(ra[i].x, ra[i].y);
                lw[i*2+1] = pack_lo(ra[i].z, ra[i].w);
            }
            int g0 = (((tid&1)*2 + 0) ^ ((arow>>1)&3)) * 4;
            int g1 = (((tid&1)*2 + 1) ^ ((arow>>1)&3)) * 4;
            uint32_t* dst = sAhi + arow*16;
            *(uint4*)(dst + g0) = make_uint4(hw[0],hw[1],hw[2],hw[3]);
            *(uint4*)(dst + g1) = make_uint4(hw[4],hw[5],hw[6],hw[7]);
            dst = sAlo + arow*16;
            *(uint4*)(dst + g0) = make_uint4(lw[0],lw[1],lw[2],lw[3]);
            *(uint4*)(dst + g1) = make_uint4(lw[4],lw[5],lw[6],lw[7]);
#pragma unroll
            for (int i = 0; i < 4; i++) {
                hw[i*2]   = pack_hi(rb[i].x, rb[i].y);
                hw[i*2+1] = pack_hi(rb[i].z, rb[i].w);
                lw[i*2]   = pack_lo(rb[i].x, rb[i].y);
                lw[i*2+1] = pack_lo(rb[i].z, rb[i].w);
            }
            dst = sBhi + arow*16;
            *(uint4*)(dst + g0) = make_uint4(hw[0],hw[1],hw[2],hw[3]);
            *(uint4*)(dst + g1) = make_uint4(hw[4],hw[5],hw[6],hw[7]);
            dst = sBlo + arow*16;
            *(uint4*)(dst + g0) = make_uint4(lw[0],lw[1],lw[2],lw[3]);
            *(uint4*)(dst + g1) = make_uint4(lw[4],lw[5],lw[6],lw[7]);
        }
        __syncthreads();
        // ---- prefetch next chunk into regs (overlaps with mma below)
        if (it + 1 < nch) {
            int gk = (it + 1) << 5;
            const float* ap = A + (long)(m0 + arow)*lda + gk + acol;
            bool aok = (m0 + arow) < M;
#pragma unroll
            for (int i = 0; i < 4; i++)
                ra[i] = aok ? *(const float4*)(ap + i*4) : make_float4(0.f,0.f,0.f,0.f);
            const float* bp = Bm + (long)(n0 + arow)*ldb + gk + acol;
            bool bok = (n0 + arow) < N;
#pragma unroll
            for (int i = 0; i < 4; i++)
                rb[i] = bok ? *(const float4*)(bp + i*4) : make_float4(0.f,0.f,0.f,0.f);
        }
        // ---- compute on this stage
#pragma unroll
        for (int ks = 0; ks < 2; ks++) {
            uint32_t bh[4][2], bl[4][2];
#pragma unroll
            for (int nt = 0; nt < 4; nt++) {
                int nrow = wn*32 + nt*8 + g;
                int w0 = ks*8 + tig;
                bh[nt][0] = sBhi[sw_addr(nrow, w0)];
                bh[nt][1] = sBhi[sw_addr(nrow, w0+4)];
                bl[nt][0] = sBlo[sw_addr(nrow, w0)];
                bl[nt][1] = sBlo[sw_addr(nrow, w0+4)];
            }
#pragma unroll
            for (int mt = 0; mt < 4; mt++) {
                int ar = wm*64 + mt*16 + g;
                int w0 = ks*8 + tig;
                uint32_t ah[4], al[4];
                ah[0] = sAhi[sw_addr(ar,   w0)];
                ah[1] = sAhi[sw_addr(ar+8, w0)];
                ah[2] = sAhi[sw_addr(ar,   w0+4)];
                ah[3] = sAhi[sw_addr(ar+8, w0+4)];
                al[0] = sAlo[sw_addr(ar,   w0)];
                al[1] = sAlo[sw_addr(ar+8, w0)];
                al[2] = sAlo[sw_addr(ar,   w0+4)];
                al[3] = sAlo[sw_addr(ar+8, w0+4)];
#pragma unroll
                for (int nt = 0; nt < 4; nt++) {
                    mma16816(acc[mt][nt], ah, bh[nt]);
                    mma16816(acc[mt][nt], ah, bl[nt]);
                    mma16816(acc[mt][nt], al, bh[nt]);
                }
            }
        }
        __syncthreads();
    }
    // ---- epilogue
#pragma unroll
    for (int mt = 0; mt < 4; mt++) {
#pragma unroll
        for (int nt = 0; nt < 4; nt++) {
            int r0 = m0 + wm*64 + mt*16 + g;
            int c0 = n0 + wn*32 + nt*8 + tig*2;
            if (c0 < N) {
                if (r0 < M)
                    *(float2*)(C + (long)r0*ldc + c0) = make_float2(acc[mt][nt][0], acc[mt][nt][1]);
                if (r0 + 8 < M)
                    *(float2*)(C + (long)(r0+8)*ldc + c0) = make_float2(acc[mt][nt][2], acc[mt][nt][3]);
            }
        }
    }
}

// transpose wkv_b[:, :128, :] -> wt[h][c][d]
__global__ void transpose_wkvb(const float* __restrict__ w, float* __restrict__ wt) {
    int idx = blockIdx.x * 256 + threadIdx.x;
    if (idx >= 16*128*512) return;
    int c = idx & 511, d = (idx >> 9) & 127, h = idx >> 16;
    wt[h*65536 + c*128 + d] = w[h*131072 + d*512 + c];
}

// ---------------- generic fp32 GEMM: C[M,N] = A[M,K] @ B[N,K]^T ---------------
__global__ void gemm_bt(const float* __restrict__ A, int lda, long aZ,
                        const float* __restrict__ Bm, int ldb, long bZ,
                        float* __restrict__ C, int ldc, long cZ,
                        int M, int N, int K) {
    A  += (long)blockIdx.z * aZ;
    Bm += (long)blockIdx.z * bZ;
    C  += (long)blockIdx.z * cZ;
    int n0 = blockIdx.x * 64, m0 = blockIdx.y * 64;
    __shared__ float As[16][65];
    __shared__ float Bs[16][65];
    int tid = threadIdx.x;
    int tx = tid & 15, ty = tid >> 4;
    int kl = tid & 15, ml = tid >> 4;
    float acc[4][4];
#pragma unroll
    for (int i = 0; i < 4; i++)
#pragma unroll
        for (int j = 0; j < 4; j++) acc[i][j] = 0.f;

    for (int k0 = 0; k0 < K; k0 += 16) {
#pragma unroll
        for (int r = 0; r < 4; r++) {
            int mm = ml + 16*r;
            int gm = m0 + mm, gk = k0 + kl, gn = n0 + mm;
            As[kl][mm] = (gm < M && gk < K) ? A[(long)gm*lda + gk] : 0.f;
            Bs[kl][mm] = (gn < N && gk < K) ? Bm[(long)gn*ldb + gk] : 0.f;
        }
        __syncthreads();
#pragma unroll
        for (int kk = 0; kk < 16; kk++) {
            float a[4], bb[4];
#pragma unroll
            for (int i = 0; i < 4; i++) a[i]  = As[kk][ty + 16*i];
#pragma unroll
            for (int j = 0; j < 4; j++) bb[j] = Bs[kk][tx + 16*j];
#pragma unroll
            for (int i = 0; i < 4; i++)
#pragma unroll
                for (int j = 0; j < 4; j++) acc[i][j] += a[i]*bb[j];
        }
        __syncthreads();
    }
#pragma unroll
    for (int i = 0; i < 4; i++)
#pragma unroll
        for (int j = 0; j < 4; j++) {
            int gm = m0 + ty + 16*i, gn = n0 + tx + 16*j;
            if (gm < M && gn < N) C[(long)gm*ldc + gn] = acc[i][j];
        }
}

// ---------------- elementwise / norm / rope -----------------------------------
__global__ void rmsnorm_kernel(float* __restrict__ x, const float* __restrict__ w, int L) {
    int row = blockIdx.x, tid = threadIdx.x;
    float* pr = x + (long)row * L;
    float ss = 0.f;
    for (int i = tid; i < L; i += 256) { float v = pr[i]; ss += v*v; }
    __shared__ float red[256];
    red[tid] = ss; __syncthreads();
    for (int o = 128; o > 0; o >>= 1) { if (tid < o) red[tid] += red[tid+o]; __syncthreads(); }
    float inv = rsqrtf(red[0] / (float)L + 1e-6f);
    for (int i = tid; i < L; i += 256) pr[i] = w[i] * pr[i] * inv;
}

__global__ void kvpost_kernel(const float* __restrict__ kvfull, const float* __restrict__ w,
                              const float* __restrict__ fcos, const float* __restrict__ fsin,
                              float* __restrict__ kv, float* __restrict__ kpe) {
    int row = blockIdx.x, s = row & (S_-1), tid = threadIdx.x;
    const float* src = kvfull + (long)row * 576;
    float ss = 0.f;
    for (int i = tid; i < 512; i += 256) { float v = src[i]; ss += v*v; }
    __shared__ float red[256];
    red[tid] = ss; __syncthreads();
    for (int o = 128; o > 0; o >>= 1) { if (tid < o) red[tid] += red[tid+o]; __syncthreads(); }
    float inv = rsqrtf(red[0] / 512.f + 1e-6f);
    for (int i = tid; i < 512; i += 256) kv[(long)row*512 + i] = w[i] * src[i] * inv;
    if (tid < 32) {
        float x1 = src[512 + tid], x2 = src[544 + tid];
        float c = fcos[s*32 + tid], sn = fsin[s*32 + tid];
        kpe[(long)row*64 + tid]      = x1*c - x2*sn;
        kpe[(long)row*64 + 32 + tid] = x1*sn + x2*c;
    }
}

__global__ void kipost_kernel(float* __restrict__ ki, const float* __restrict__ w,
                              const float* __restrict__ bvec,
                              const float* __restrict__ fcos, const float* __restrict__ fsin) {
    int row = blockIdx.x, s = row & (S_-1), tid = threadIdx.x; // 128 threads
    float* pr = ki + (long)row * 128;
    float v = pr[tid];
    __shared__ float red[128];
    red[tid] = v; __syncthreads();
    for (int o = 64; o > 0; o >>= 1) { if (tid < o) red[tid] += red[tid+o]; __syncthreads(); }
    float mean = red[0] / 128.f;
    __syncthreads();
    float d = v - mean;
    red[tid] = d*d; __syncthreads();
    for (int o = 64; o > 0; o >>= 1) { if (tid < o) red[tid] += red[tid+o]; __syncthreads(); }
    float var = red[0] / 128.f;
    __syncthreads();
    float y = d * rsqrtf(var + 1e-6f) * w[tid] + bvec[tid];
    __shared__ float yb[128];
    yb[tid] = y; __syncthreads();
    float outv;
    if (tid < 32) {
        float c = fcos[s*32 + tid], sn = fsin[s*32 + tid];
        outv = yb[tid]*c - yb[tid+32]*sn;
    } else if (tid < 64) {
        int i = tid - 32;
        float c = fcos[s*32 + i], sn = fsin[s*32 + i];
        outv = yb[i]*sn + yb[tid]*c;
    } else {
        outv = y;
    }
    pr[tid] = outv;
}

__global__ void rope_q_kernel(float* __restrict__ q, const float* __restrict__ fcos,
                              const float* __restrict__ fsin) {
    int idx = blockIdx.x * blockDim.x + threadIdx.x;
    if (idx >= BS_*16*32) return;
    int i = idx & 31, h = (idx >> 5) & 15, bs = idx >> 9;
    int s = bs & (S_-1);
    long base = (long)bs*3072 + h*192 + 128;
    float x1 = q[base + i], x2 = q[base + 32 + i];
    float c = fcos[s*32 + i], sn = fsin[s*32 + i];
    q[base + i]      = x1*c - x2*sn;
    q[base + 32 + i] = x1*sn + x2*c;
}

__global__ void rope_qi_kernel(float* __restrict__ qi, const float* __restrict__ fcos,
                               const float* __restrict__ fsin) {
    int idx = blockIdx.x * blockDim.x + threadIdx.x;
    if (idx >= BS_*16*32) return;
    int i = idx & 31, h = (idx >> 5) & 15, bs = idx >> 9;
    int s = bs & (S_-1);
    long base = (long)bs*2048 + h*128;
    float x1 = qi[base + i], x2 = qi[base + 32 + i];
    float c = fcos[s*32 + i], sn = fsin[s*32 + i];
    qi[base + i]      = x1*c - x2*sn;
    qi[base + 32 + i] = x1*sn + x2*c;
}

// ---------------- indexer score ------------------------------------------------
__global__ void iscore_kernel(const float* __restrict__ qi, const float* __restrict__ ki,
                              const float* __restrict__ wts, const float* __restrict__ mask,
                              float* __restrict__ iscore) {
    int b = blockIdx.z;
    int s0 = blockIdx.y * 64, t0 = blockIdx.x * 64;
    int tid = threadIdx.x;
    if (t0 > s0 + 63) {
        for (int i = tid; i < 64*64; i += 256) {
            int m = i >> 6, n = i & 63;
            int s = s0 + m, t = t0 + n;
            iscore[((long)b*S_ + s)*S_ + t] = mask[(long)s*S_ + t];
        }
        return;
    }
    int tx = tid & 15, ty = tid >> 4;
    int kl = tid & 15, ml = tid >> 4;
    __shared__ float qs[16][65];
    __shared__ float ks[16][65];
    __shared__ float ws_s[16][64];
    const float IW_SCALE = rsqrtf(2048.0f);
    for (int i = tid; i < 16*64; i += 256) {
        int m = i >> 4, h = i & 15;
        ws_s[h][m] = wts[((long)(b*S_ + s0 + m))*16 + h] * IW_SCALE;
    }
    float acc[4][4];
#pragma unroll
    for (int i = 0; i < 4; i++)
#pragma unroll
        for (int j = 0; j < 4; j++) acc[i][j] = 0.f;
    __syncthreads();

    for (int h = 0; h < 16; h++) {
        float dot[4][4];
#pragma unroll
        for (int i = 0; i < 4; i++)
#pragma unroll
            for (int j = 0; j < 4; j++) dot[i][j] = 0.f;
        for (int d0 = 0; d0 < 128; d0 += 16) {
#pragma unroll
            for (int r = 0; r < 4; r++) {
                int mm = ml + 16*r;
                qs[kl][mm] = qi[((long)(b*S_ + s0 + mm))*2048 + h*128 + d0 + kl];
                ks[kl][mm] = ki[((long)(b*S_ + t0 + mm))*128 + d0 + kl];
            }
            __syncthreads();
#pragma unroll
            for (int kk = 0; kk < 16; kk++) {
                float a[4], bb[4];
#pragma unroll
                for (int i = 0; i < 4; i++) a[i]  = qs[kk][ty + 16*i];
#pragma unroll
                for (int j = 0; j < 4; j++) bb[j] = ks[kk][tx + 16*j];
#pragma unroll
                for (int i = 0; i < 4; i++)
#pragma unroll
                    for (int j = 0; j < 4; j++) dot[i][j] += a[i]*bb[j];
            }
            __syncthreads();
        }
#pragma unroll
        for (int i = 0; i < 4; i++) {
            float w = ws_s[h][ty + 16*i];
#pragma unroll
            for (int j = 0; j < 4; j++) acc[i][j] += fmaxf(dot[i][j], 0.f) * w;
        }
    }
#pragma unroll
    for (int i = 0; i < 4; i++)
#pragma unroll
        for (int j = 0; j < 4; j++) {
            int s = s0 + ty + 16*i, t = t0 + tx + 16*j;
            iscore[((long)b*S_ + s)*S_ + t] = acc[i][j] + mask[(long)s*S_ + t];
        }
}

// ---------------- exact top-512 per row (radix select, deterministic) ---------
__global__ void topk_kernel(const float* __restrict__ iscore, int* __restrict__ out) {
    int row = blockIdx.x;
    const float* p = iscore + (long)row * S_;
    int tid = threadIdx.x; // 256
    __shared__ unsigned int hist[256];
    __shared__ unsigned int s_prefix;
    __shared__ int s_rem;
    __shared__ int sgt[257], seq[257];
    if (tid == 0) { s_prefix = 0u; s_rem = ITOPK_; }
    __syncthreads();
    for (int pass = 0; pass < 4; pass++) {
        hist[tid] = 0u;
        __syncthreads();
        int shift = 24 - 8*pass;
        unsigned int pref = s_prefix;
        for (int e = 0; e < 8; e++) {
            int j = tid*8 + e;
            unsigned int u = __float_as_uint(p[j]);
            unsigned int k = (u & 0x80000000u) ? ~u : (u | 0x80000000u);
            bool ok = (pass == 0) || (((k ^ pref) >> (shift + 8)) == 0u);
            if (ok) atomicAdd(&hist[(k >> shift) & 255u], 1u);
        }
        __syncthreads();
        if (tid == 0) {
            int rem = s_rem;
            unsigned int cum = 0; int bin = 0;
            for (int bb = 255; bb >= 0; bb--) {
                if (cum + hist[bb] >= (unsigned)rem) { bin = bb; break; }
                cum += hist[bb];
            }
            s_rem = rem - (int)cum;
            s_prefix = s_prefix | ((unsigned)bin << shift);
        }
        __syncthreads();
    }
    unsigned int kth = s_prefix;
    int cgt = 0, ceq = 0;
    for (int e = 0; e < 8; e++) {
        int j = tid*8 + e;
        unsigned int u = __float_as_uint(p[j]);
        unsigned int k = (u & 0x80000000u) ? ~u : (u | 0x80000000u);
        cgt += (k > kth); ceq += (k == kth);
    }
    sgt[tid] = cgt; seq[tid] = ceq;
    __syncthreads();
    if (tid == 0) {
        int ag = 0, ae = 0;
        for (int i = 0; i < 256; i++) {
            int tg = sgt[i], te = seq[i];
            sgt[i] = ag; seq[i] = ae;
            ag += tg; ae += te;
        }
        sgt[256] = ag;
    }
    __syncthreads();
    int total_gt = sgt[256];
    int pgt = sgt[tid];
    int peq = total_gt + seq[tid];
    int* o = out + (long)row * ITOPK_;
    for (int e = 0; e < 8; e++) {
        int j = tid*8 + e;
        unsigned int u = __float_as_uint(p[j]);
        unsigned int k = (u & 0x80000000u) ? ~u : (u | 0x80000000u);
        if (k > kth) { o[pgt++] = j; }
        else if (k == kth) { if (peq < ITOPK_) o[peq] = j; peq++; }
    }
}

// ---------------- sparse attention (per (b,s), all 16 heads) -------------------
#define ATTN_SMEM ((8192 + 1024 + 8192) * 4 + 512 * 4)
__global__ void attn_kernel(const float* __restrict__ q,
                            const float* __restrict__ qabs,
                            const float* __restrict__ kv,
                            const float* __restrict__ kpe,
                            const int* __restrict__ topk,
                            float* __restrict__ omid) {
    extern __shared__ float smf[];
    float* qas  = smf;
    float* qpes = qas + 8192;
    float* sc   = qpes + 1024;
    int*   tl   = (int*)(sc + 8192);
    int bs = blockIdx.x, b = bs >> 11, s = bs & (S_-1);
    int tid = threadIdx.x;

    for (int i = tid; i < 8192; i += 256) qas[i] = qabs[(long)bs*8192 + i];
    for (int i = tid; i < 1024; i += 256) {
        int h = i >> 6, r = i & 63;
        qpes[i] = q[(long)bs*3072 + h*192 + 128 + r];
    }
    for (int j = tid; j < 512; j += 256) tl[j] = topk[(long)bs*512 + j];
    __syncthreads();

    {
        int j0 = tid, j1 = tid + 256;
        int t0 = tl[j0], t1 = tl[j1];
        bool v0 = (t0 <= s), v1 = (t1 <= s);
        const float4* k0 = (const float4*)(kv + ((long)(b*S_ + (v0 ? t0 : 0)))*512);
        const float4* k1 = (const float4*)(kv + ((long)(b*S_ + (v1 ? t1 : 0)))*512);
        float a0[16], a1[16];
#pragma unroll
        for (int h = 0; h < 16; h++) { a0[h] = 0.f; a1[h] = 0.f; }
        for (int d4 = 0; d4 < 128; d4++) {
            float4 x0 = k0[d4], x1 = k1[d4];
#pragma unroll
            for (int h = 0; h < 16; h++) {
                const float* qh = qas + h*512 + d4*4;
                float q0 = qh[0], q1v = qh[1], q2 = qh[2], q3 = qh[3];
                a0[h] += x0.x*q0 + x0.y*q1v + x0.z*q2 + x0.w*q3;
                a1[h] += x1.x*q0 + x1.y*q1v + x1.z*q2 + x1.w*q3;
            }
        }
        const float4* p0 = (const float4*)(kpe + ((long)(b*S_ + (v0 ? t0 : 0)))*64);
        const float4* p1 = (const float4*)(kpe + ((long)(b*S_ + (v1 ? t1 : 0)))*64);
        for (int d4 = 0; d4 < 16; d4++) {
            float4 x0 = p0[d4], x1 = p1[d4];
#pragma unroll
            for (int h = 0; h < 16; h++) {
                const float* qh = qpes + h*64 + d4*4;
                float q0 = qh[0], q1v = qh[1], q2 = qh[2], q3 = qh[3];
                a0[h] += x0.x*q0 + x0.y*q1v + x0.z*q2 + x0.w*q3;
                a1[h] += x1.x*q0 + x1.y*q1v + x1.z*q2 + x1.w*q3;
            }
        }
        const float scale = rsqrtf(192.0f);
#pragma unroll
        for (int h = 0; h < 16; h++) {
            sc[h*512 + j0] = v0 ? a0[h]*scale : -1e30f;
            sc[h*512 + j1] = v1 ? a1[h]*scale : -1e30f;
        }
    }
    __syncthreads();

    {
        int warp = tid >> 5, lane = tid & 31;
        for (int h = warp*2; h <= warp*2 + 1; h++) {
            float m = -1e30f;
            for (int j = lane; j < 512; j += 32) m = fmaxf(m, sc[h*512 + j]);
#pragma unroll
            for (int o = 16; o > 0; o >>= 1) m = fmaxf(m, __shfl_xor_sync(0xffffffffu, m, o));
            float ss = 0.f;
            for (int j = lane; j < 512; j += 32) {
                float e = expf(sc[h*512 + j] - m);
                sc[h*512 + j] = e;
                ss += e;
            }
#pragma unroll
            for (int o = 16; o > 0; o >>= 1) ss += __shfl_xor_sync(0xffffffffu, ss, o);
            float inv = 1.f / ss;
            for (int j = lane; j < 512; j += 32) sc[h*512 + j] *= inv;
        }
    }
    __syncthreads();

    {
        int c = tid;
        float a0[16], a1[16];
#pragma unroll
        for (int h = 0; h < 16; h++) { a0[h] = 0.f; a1[h] = 0.f; }
#pragma unroll 2
        for (int j = 0; j < 512; j++) {
            int t = tl[j];
            if (t > s) continue;
            const float* kr = kv + ((long)(b*S_ + t))*512;
            float v0 = kr[c], v1 = kr[c + 256];
#pragma unroll
            for (int h = 0; h < 16; h++) {
                float pp = sc[h*512 + j];
                a0[h] += pp*v0; a1[h] += pp*v1;
            }
        }
#pragma unroll
        for (int h = 0; h < 16; h++) {
            omid[(long)bs*8192 + h*512 + c]       = a0[h];
            omid[(long)bs*8192 + h*512 + c + 256] = a1[h];
        }
    }
}

// ---------------- host orchestration ------------------------------------------
extern "C" void kernel_launch(void* const* d_in, const int* in_sizes, int n_in,
                              void* d_out, int out_size) {
    const float* x      = (const float*)d_in[0];
    const float* fcos   = (const float*)d_in[1];
    const float* fsin   = (const float*)d_in[2];
    const float* mask   = (const float*)d_in[3];
    const float* wq_a   = (const float*)d_in[4];
    const float* qnw    = (const float*)d_in[5];
    const float* wq_b   = (const float*)d_in[6];
    const float* wkv_a  = (const float*)d_in[7];
    const float* kvnw   = (const float*)d_in[8];
    const float* wkv_b  = (const float*)d_in[9];
    const float* wo     = (const float*)d_in[10];
    const float* iwqb   = (const float*)d_in[11];
    const float* iwk    = (const float*)d_in[12];
    const float* iknw   = (const float*)d_in[13];
    const float* iknb   = (const float*)d_in[14];
    const float* iwp    = (const float*)d_in[15];
    float* out = (float*)d_out;

    float *qr, *q, *kvfull, *kv, *kpe, *qabs, *qi, *ki, *wts, *iscore, *omid, *o2, *wt;
    int* topkb;
    cudaGetSymbolAddress((void**)&qr,     g_qr);
    cudaGetSymbolAddress((void**)&q,      g_q);
    cudaGetSymbolAddress((void**)&kvfull, g_kvfull);
    cudaGetSymbolAddress((void**)&kv,     g_kv);
    cudaGetSymbolAddress((void**)&kpe,    g_kpe);
    cudaGetSymbolAddress((void**)&qabs,   g_qabs);
    cudaGetSymbolAddress((void**)&qi,     g_qi);
    cudaGetSymbolAddress((void**)&ki,     g_ki);
    cudaGetSymbolAddress((void**)&wts,    g_wts);
    cudaGetSymbolAddress((void**)&iscore, g_iscore);
    cudaGetSymbolAddress((void**)&topkb,  g_topk);
    cudaGetSymbolAddress((void**)&omid,   g_omid);
    cudaGetSymbolAddress((void**)&o2,     g_o2);
    cudaGetSymbolAddress((void**)&wt,     g_wkvbT);

    cudaFuncSetAttribute(attn_kernel, cudaFuncAttributeMaxDynamicSharedMemorySize, ATTN_SMEM);
    cudaFuncSetAttribute(gemm_mma, cudaFuncAttributeMaxDynamicSharedMemorySize, GM_SMEM);

    // qr = rmsnorm(x @ wq_a^T)   [fp32 — feeds indexer/topk, keep bit-identical]
    gemm_bt<<<dim3(12, 64, 1), 256>>>(x, 2048, 0, wq_a, 2048, 0, qr, 768, 0, 4096, 768, 2048);
    rmsnorm_kernel<<<4096, 256>>>(qr, qnw, 768);
    // q = qr @ wq_b^T  [tensor core bf16x3]
    gemm_mma<<<dim3(24, 32, 1), 256, GM_SMEM>>>(qr, 768, 0, wq_b, 768, 0, q, 3072, 0, 4096, 3072, 768);
    rope_q_kernel<<<(BS_*16*32 + 255)/256, 256>>>(q, fcos, fsin);
    // kv path [tensor core]
    gemm_mma<<<dim3(5, 32, 1), 256, GM_SMEM>>>(x, 2048, 0, wkv_a, 2048, 0, kvfull, 576, 0, 4096, 576, 2048);
    kvpost_kernel<<<4096, 256>>>(kvfull, kvnw, fcos, fsin, kv, kpe);
    // q_abs = q_nope @ wkv_b3[h,:128,:] via transposed weights [tensor core]
    transpose_wkvb<<<(16*128*512 + 255)/256, 256>>>(wkv_b, wt);
    gemm_mma<<<dim3(4, 32, 16), 256, GM_SMEM>>>(q, 3072, 192, wt, 128, 65536, qabs, 8192, 512,
                                                4096, 512, 128);
    // indexer [fp32 — determines topk]
    gemm_bt<<<dim3(32, 64, 1), 256>>>(qr, 768, 0, iwqb, 768, 0, qi, 2048, 0, 4096, 2048, 768);
    rope_qi_kernel<<<(BS_*16*32 + 255)/256, 256>>>(qi, fcos, fsin);
    gemm_bt<<<dim3(2, 64, 1), 256>>>(x, 2048, 0, iwk, 2048, 0, ki, 128, 0, 4096, 128, 2048);
    kipost_kernel<<<4096, 128>>>(ki, iknw, iknb, fcos, fsin);
    gemm_bt<<<dim3(1, 64, 1), 256>>>(x, 2048, 0, iwp, 2048, 0, wts, 16, 0, 4096, 16, 2048);
    iscore_kernel<<<dim3(32, 32, 2), 256>>>(qi, ki, wts, mask, iscore);
    topk_kernel<<<4096, 256>>>(iscore, topkb);
    // sparse attention [fp32]
    attn_kernel<<<4096, 256, ATTN_SMEM>>>(q, qabs, kv, kpe, topkb, omid);
    // o2 = omid @ wkv_b3[h,128:,:]^T  [tensor core]
    gemm_mma<<<dim3(1, 32, 16), 256, GM_SMEM>>>(omid, 8192, 512, wkv_b + 128*512, 512, 256*512,
                                                o2, 2048, 128, 4096, 128, 512);
    // out = o2 @ wo^T  [tensor core]
    gemm_mma<<<dim3(16, 32, 1), 256, GM_SMEM>>>(o2, 2048, 0, wo, 2048, 0, out, 2048, 0, 4096, 2048, 2048);
}

// round 4
// speedup vs baseline: 1.4053x; 1.1159x over previous
#include <cuda_runtime.h>
#include <cuda_bf16.h>
#include <math.h>
#include <stdint.h>

// Problem constants
#define B_    2
#define S_    2048
#define DIM_  2048
#define NH_   16
#define QLR_  768
#define KVLR_ 512
#define NOPE_ 128
#define ROPE_ 64
#define VDIM_ 128
#define IH_   16
#define IHD_  128
#define ITOPK_ 512
#define BS_   (B_*S_)   // 4096

// ---------------- scratch (device globals; no allocation allowed) -------------
__device__ float g_qr[BS_*QLR_];
__device__ float g_q[BS_*NH_*(NOPE_+ROPE_)];
__device__ float g_kvfull[BS_*(KVLR_+ROPE_)];
__device__ float g_kv[BS_*KVLR_];
__device__ float g_kpe[BS_*ROPE_];
__device__ float g_qabs[BS_*NH_*KVLR_];
__device__ float g_qi[BS_*IH_*IHD_];
__device__ float g_ki[BS_*IHD_];
__device__ float g_wts[BS_*IH_];
__device__ float g_iscore[B_*S_*S_];
__device__ int   g_topk[BS_*ITOPK_];
__device__ float g_omid[BS_*NH_*KVLR_];
__device__ float g_o2[BS_*NH_*VDIM_];
__device__ float g_wkvbT[16*512*128];            // transposed wkv_b[:, :128, :] -> [h][c][d]
__device__ __nv_bfloat16 g_khi[BS_*576];         // kv||kpe hi split
__device__ __nv_bfloat16 g_klo[BS_*576];         // kv||kpe lo split

// =================== helpers ==================================================
__device__ __forceinline__ uint32_t smem_u32(const void* p) {
    uint32_t a;
    asm("{ .reg .u64 t; cvta.to.shared.u64 t, %1; cvt.u32.u64 %0, t; }" : "=r"(a) : "l"(p));
    return a;
}
__device__ __forceinline__ uint32_t pack_hi(float x, float y) {
    __nv_bfloat162 p;
    p.x = __float2bfloat16_rn(x);
    p.y = __float2bfloat16_rn(y);
    return *(uint32_t*)&p;
}
__device__ __forceinline__ uint32_t pack_lo(float x, float y) {
    __nv_bfloat16 hx = __float2bfloat16_rn(x);
    __nv_bfloat16 hy = __float2bfloat16_rn(y);
    __nv_bfloat162 p;
    p.x = __float2bfloat16_rn(x - __bfloat162float(hx));
    p.y = __float2bfloat16_rn(y - __bfloat162float(hy));
    return *(uint32_t*)&p;
}
__device__ __forceinline__ void mma16816(float* c, const uint32_t* a, const uint32_t* b) {
    asm volatile("mma.sync.aligned.m16n8k16.row.col.f32.bf16.bf16.f32 "
        "{%0,%1,%2,%3}, {%4,%5,%6,%7}, {%8,%9}, {%0,%1,%2,%3};"
        : "+f"(c[0]), "+f"(c[1]), "+f"(c[2]), "+f"(c[3])
        : "r"(a[0]), "r"(a[1]), "r"(a[2]), "r"(a[3]), "r"(b[0]), "r"(b[1]));
}
#define LDSM_X4(r, a) asm volatile("ldmatrix.sync.aligned.m8n8.x4.shared.b16 {%0,%1,%2,%3}, [%4];" \
    : "=r"((r)[0]),"=r"((r)[1]),"=r"((r)[2]),"=r"((r)[3]) : "r"(a))
#define LDSM_X2(r, a) asm volatile("ldmatrix.sync.aligned.m8n8.x2.shared.b16 {%0,%1}, [%2];" \
    : "=r"((r)[0]),"=r"((r)[1]) : "r"(a))
#define LDSM_X2T(r, a) asm volatile("ldmatrix.sync.aligned.m8n8.x2.trans.shared.b16 {%0,%1}, [%2];" \
    : "=r"((r)[0]),"=r"((r)[1]) : "r"(a))

// word-granularity swizzled smem address for gemm_mma tiles (128 rows x 16 words)
__device__ __forceinline__ int sw_addr(int row, int w) {
    return row*16 + (w ^ ((((row)>>1)&3)<<2));
}

// =================== tensor-core GEMM (bf16x3): C[M,N]=A[M,K]@B[N,K]^T ========
#define GM_SMEM 65536

__global__ void __launch_bounds__(256, 1)
gemm_mma(const float* __restrict__ A, int lda, long aZ,
         const float* __restrict__ Bm, int ldb, long bZ,
         float* __restrict__ C, int ldc, long cZ,
         int M, int N, int K) {
    extern __shared__ uint32_t smw[];
    A  += (long)blockIdx.z * aZ;
    Bm += (long)blockIdx.z * bZ;
    C  += (long)blockIdx.z * cZ;
    int m0 = blockIdx.y * 128, n0 = blockIdx.x * 128;
    int tid = threadIdx.x, lane = tid & 31, wid = tid >> 5;
    int wm = wid >> 2, wn = wid & 3;
    int g = lane >> 2, tig = lane & 3;

    float acc[4][4][4];
#pragma unroll
    for (int i = 0; i < 4; i++)
#pragma unroll
        for (int j = 0; j < 4; j++)
#pragma unroll
            for (int r = 0; r < 4; r++) acc[i][j][r] = 0.f;

    int arow = tid >> 1, acol = (tid & 1) * 16;
    int nch = K >> 5;

    float4 ra[4], rb[4];
    {
        const float* ap = A + (long)(m0 + arow)*lda + acol;
        bool aok = (m0 + arow) < M;
#pragma unroll
        for (int i = 0; i < 4; i++)
            ra[i] = aok ? *(const float4*)(ap + i*4) : make_float4(0.f,0.f,0.f,0.f);
        const float* bp = Bm + (long)(n0 + arow)*ldb + acol;
        bool bok = (n0 + arow) < N;
#pragma unroll
        for (int i = 0; i < 4; i++)
            rb[i] = bok ? *(const float4*)(bp + i*4) : make_float4(0.f,0.f,0.f,0.f);
    }

    for (int it = 0; it < nch; it++) {
        int stg = it & 1;
        uint32_t* sAhi = smw + stg*8192;
        uint32_t* sAlo = sAhi + 2048;
        uint32_t* sBhi = sAhi + 4096;
        uint32_t* sBlo = sAhi + 6144;
        {
            uint32_t hw[8], lw[8];
#pragma unroll
            for (int i = 0; i < 4; i++) {
                hw[i*2]   = pack_hi(ra[i].x, ra[i].y);
                hw[i*2+1] = pack_hi(ra[i].z, ra[i].w);
                lw[i*2]   = pack_lo(ra[i].x, ra[i].y);
                lw[i*2+1] = pack_lo(ra[i].z, ra[i].w);
            }
            int g0 = (((tid&1)*2 + 0) ^ ((arow>>1)&3)) * 4;
            int g1 = (((tid&1)*2 + 1) ^ ((arow>>1)&3)) * 4;
            uint32_t* dst = sAhi + arow*16;
            *(uint4*)(dst + g0) = make_uint4(hw[0],hw[1],hw[2],hw[3]);
            *(uint4*)(dst + g1) = make_uint4(hw[4],hw[5],hw[6],hw[7]);
            dst = sAlo + arow*16;
            *(uint4*)(dst + g0) = make_uint4(lw[0],lw[1],lw[2],lw[3]);
            *(uint4*)(dst + g1) = make_uint4(lw[4],lw[5],lw[6],lw[7]);
#pragma unroll
            for (int i = 0; i < 4; i++) {
                hw[i*2]   = pack_hi(rb[i].x, rb[i].y);
                hw[i*2+1] = pack_hi(rb[i].z, rb[i].w);
                lw[i*2]   = pack_lo(rb[i].x, rb[i].y);
                lw[i*2+1] = pack_lo(rb[i].z, rb[i].w);
            }
            dst = sBhi + arow*16;
            *(uint4*)(dst + g0) = make_uint4(hw[0],hw[1],hw[2],hw[3]);
            *(uint4*)(dst + g1) = make_uint4(hw[4],hw[5],hw[6],hw[7]);
            dst = sBlo + arow*16;
            *(uint4*)(dst + g0) = make_uint4(lw[0],lw[1],lw[2],lw[3]);
            *(uint4*)(dst + g1) = make_uint4(lw[4],lw[5],lw[6],lw[7]);
        }
        __syncthreads();
        if (it + 1 < nch) {
            int gk = (it + 1) << 5;
            const float* ap = A + (long)(m0 + arow)*lda + gk + acol;
            bool aok = (m0 + arow) < M;
#pragma unroll
            for (int i = 0; i < 4; i++)
                ra[i] = aok ? *(const float4*)(ap + i*4) : make_float4(0.f,0.f,0.f,0.f);
            const float* bp = Bm + (long)(n0 + arow)*ldb + gk + acol;
            bool bok = (n0 + arow) < N;
#pragma unroll
            for (int i = 0; i < 4; i++)
                rb[i] = bok ? *(const float4*)(bp + i*4) : make_float4(0.f,0.f,0.f,0.f);
        }
#pragma unroll
        for (int ks = 0; ks < 2; ks++) {
            uint32_t bh[4][2], bl[4][2];
#pragma unroll
            for (int nt = 0; nt < 4; nt++) {
                int nrow = wn*32 + nt*8 + g;
                int w0 = ks*8 + tig;
                bh[nt][0] = sBhi[sw_addr(nrow, w0)];
                bh[nt][1] = sBhi[sw_addr(nrow, w0+4)];
                bl[nt][0] = sBlo[sw_addr(nrow, w0)];
                bl[nt][1] = sBlo[sw_addr(nrow, w0+4)];
            }
#pragma unroll
            for (int mt = 0; mt < 4; mt++) {
                int ar = wm*64 + mt*16 + g;
                int w0 = ks*8 + tig;
                uint32_t ah[4], al[4];
                ah[0] = sAhi[sw_addr(ar,   w0)];
                ah[1] = sAhi[sw_addr(ar+8, w0)];
                ah[2] = sAhi[sw_addr(ar,   w0+4)];
                ah[3] = sAhi[sw_addr(ar+8, w0+4)];
                al[0] = sAlo[sw_addr(ar,   w0)];
                al[1] = sAlo[sw_addr(ar+8, w0)];
                al[2] = sAlo[sw_addr(ar,   w0+4)];
                al[3] = sAlo[sw_addr(ar+8, w0+4)];
#pragma unroll
                for (int nt = 0; nt < 4; nt++) {
                    mma16816(acc[mt][nt], ah, bh[nt]);
                    mma16816(acc[mt][nt], ah, bl[nt]);
                    mma16816(acc[mt][nt], al, bh[nt]);
                }
            }
        }
        __syncthreads();
    }
#pragma unroll
    for (int mt = 0; mt < 4; mt++) {
#pragma unroll
        for (int nt = 0; nt < 4; nt++) {
            int r0 = m0 + wm*64 + mt*16 + g;
            int c0 = n0 + wn*32 + nt*8 + tig*2;
            if (c0 < N) {
                if (r0 < M)
                    *(float2*)(C + (long)r0*ldc + c0) = make_float2(acc[mt][nt][0], acc[mt][nt][1]);
                if (r0 + 8 < M)
                    *(float2*)(C + (long)(r0+8)*ldc + c0) = make_float2(acc[mt][nt][2], acc[mt][nt][3]);
            }
        }
    }
}

// transpose wkv_b[:, :128, :] -> wt[h][c][d]
__global__ void transpose_wkvb(const float* __restrict__ w, float* __restrict__ wt) {
    int idx = blockIdx.x * 256 + threadIdx.x;
    if (idx >= 16*128*512) return;
    int c = idx & 511, d = (idx >> 9) & 127, h = idx >> 16;
    wt[h*65536 + c*128 + d] = w[h*131072 + d*512 + c];
}

// ---------------- generic fp32 GEMM: C[M,N] = A[M,K] @ B[N,K]^T ---------------
__global__ void gemm_bt(const float* __restrict__ A, int lda, long aZ,
                        const float* __restrict__ Bm, int ldb, long bZ,
                        float* __restrict__ C, int ldc, long cZ,
                        int M, int N, int K) {
    A  += (long)blockIdx.z * aZ;
    Bm += (long)blockIdx.z * bZ;
    C  += (long)blockIdx.z * cZ;
    int n0 = blockIdx.x * 64, m0 = blockIdx.y * 64;
    __shared__ float As[16][65];
    __shared__ float Bs[16][65];
    int tid = threadIdx.x;
    int tx = tid & 15, ty = tid >> 4;
    int kl = tid & 15, ml = tid >> 4;
    float acc[4][4];
#pragma unroll
    for (int i = 0; i < 4; i++)
#pragma unroll
        for (int j = 0; j < 4; j++) acc[i][j] = 0.f;

    for (int k0 = 0; k0 < K; k0 += 16) {
#pragma unroll
        for (int r = 0; r < 4; r++) {
            int mm = ml + 16*r;
            int gm = m0 + mm, gk = k0 + kl, gn = n0 + mm;
            As[kl][mm] = (gm < M && gk < K) ? A[(long)gm*lda + gk] : 0.f;
            Bs[kl][mm] = (gn < N && gk < K) ? Bm[(long)gn*ldb + gk] : 0.f;
        }
        __syncthreads();
#pragma unroll
        for (int kk = 0; kk < 16; kk++) {
            float a[4], bb[4];
#pragma unroll
            for (int i = 0; i < 4; i++) a[i]  = As[kk][ty + 16*i];
#pragma unroll
            for (int j = 0; j < 4; j++) bb[j] = Bs[kk][tx + 16*j];
#pragma unroll
            for (int i = 0; i < 4; i++)
#pragma unroll
                for (int j = 0; j < 4; j++) acc[i][j] += a[i]*bb[j];
        }
        __syncthreads();
    }
#pragma unroll
    for (int i = 0; i < 4; i++)
#pragma unroll
        for (int j = 0; j < 4; j++) {
            int gm = m0 + ty + 16*i, gn = n0 + tx + 16*j;
            if (gm < M && gn < N) C[(long)gm*ldc + gn] = acc[i][j];
        }
}

// ---------------- elementwise / norm / rope -----------------------------------
__global__ void rmsnorm_kernel(float* __restrict__ x, const float* __restrict__ w, int L) {
    int row = blockIdx.x, tid = threadIdx.x;
    float* pr = x + (long)row * L;
    float ss = 0.f;
    for (int i = tid; i < L; i += 256) { float v = pr[i]; ss += v*v; }
    __shared__ float red[256];
    red[tid] = ss; __syncthreads();
    for (int o = 128; o > 0; o >>= 1) { if (tid < o) red[tid] += red[tid+o]; __syncthreads(); }
    float inv = rsqrtf(red[0] / (float)L + 1e-6f);
    for (int i = tid; i < L; i += 256) pr[i] = w[i] * pr[i] * inv;
}

__global__ void kvpost_kernel(const float* __restrict__ kvfull, const float* __restrict__ w,
                              const float* __restrict__ fcos, const float* __restrict__ fsin,
                              float* __restrict__ kv, float* __restrict__ kpe) {
    int row = blockIdx.x, s = row & (S_-1), tid = threadIdx.x;
    const float* src = kvfull + (long)row * 576;
    float ss = 0.f;
    for (int i = tid; i < 512; i += 256) { float v = src[i]; ss += v*v; }
    __shared__ float red[256];
    red[tid] = ss; __syncthreads();
    for (int o = 128; o > 0; o >>= 1) { if (tid < o) red[tid] += red[tid+o]; __syncthreads(); }
    float inv = rsqrtf(red[0] / 512.f + 1e-6f);
    for (int i = tid; i < 512; i += 256) kv[(long)row*512 + i] = w[i] * src[i] * inv;
    if (tid < 32) {
        float x1 = src[512 + tid], x2 = src[544 + tid];
        float c = fcos[s*32 + tid], sn = fsin[s*32 + tid];
        kpe[(long)row*64 + tid]      = x1*c - x2*sn;
        kpe[(long)row*64 + 32 + tid] = x1*sn + x2*c;
    }
}

// split kv||kpe into bf16 hi/lo global arrays
__global__ void kvsplit_kernel(const float* __restrict__ kv, const float* __restrict__ kpe,
                               __nv_bfloat16* __restrict__ khi, __nv_bfloat16* __restrict__ klo) {
    int idx = blockIdx.x*256 + threadIdx.x;
    if (idx >= BS_*576) return;
    int r = idx / 576, d = idx - r*576;
    float v = (d < 512) ? kv[(long)r*512 + d] : kpe[(long)r*64 + d - 512];
    __nv_bfloat16 hi = __float2bfloat16_rn(v);
    khi[idx] = hi;
    klo[idx] = __float2bfloat16_rn(v - __bfloat162float(hi));
}

__global__ void kipost_kernel(float* __restrict__ ki, const float* __restrict__ w,
                              const float* __restrict__ bvec,
                              const float* __restrict__ fcos, const float* __restrict__ fsin) {
    int row = blockIdx.x, s = row & (S_-1), tid = threadIdx.x; // 128 threads
    float* pr = ki + (long)row * 128;
    float v = pr[tid];
    __shared__ float red[128];
    red[tid] = v; __syncthreads();
    for (int o = 64; o > 0; o >>= 1) { if (tid < o) red[tid] += red[tid+o]; __syncthreads(); }
    float mean = red[0] / 128.f;
    __syncthreads();
    float d = v - mean;
    red[tid] = d*d; __syncthreads();
    for (int o = 64; o > 0; o >>= 1) { if (tid < o) red[tid] += red[tid+o]; __syncthreads(); }
    float var = red[0] / 128.f;
    __syncthreads();
    float y = d * rsqrtf(var + 1e-6f) * w[tid] + bvec[tid];
    __shared__ float yb[128];
    yb[tid] = y; __syncthreads();
    float outv;
    if (tid < 32) {
        float c = fcos[s*32 + tid], sn = fsin[s*32 + tid];
        outv = yb[tid]*c - yb[tid+32]*sn;
    } else if (tid < 64) {
        int i = tid - 32;
        float c = fcos[s*32 + i], sn = fsin[s*32 + i];
        outv = yb[i]*sn + yb[tid]*c;
    } else {
        outv = y;
    }
    pr[tid] = outv;
}

__global__ void rope_q_kernel(float* __restrict__ q, const float* __restrict__ fcos,
                              const float* __restrict__ fsin) {
    int idx = blockIdx.x * blockDim.x + threadIdx.x;
    if (idx >= BS_*16*32) return;
    int i = idx & 31, h = (idx >> 5) & 15, bs = idx >> 9;
    int s = bs & (S_-1);
    long base = (long)bs*3072 + h*192 + 128;
    float x1 = q[base + i], x2 = q[base + 32 + i];
    float c = fcos[s*32 + i], sn = fsin[s*32 + i];
    q[base + i]      = x1*c - x2*sn;
    q[base + 32 + i] = x1*sn + x2*c;
}

__global__ void rope_qi_kernel(float* __restrict__ qi, const float* __restrict__ fcos,
                               const float* __restrict__ fsin) {
    int idx = blockIdx.x * blockDim.x + threadIdx.x;
    if (idx >= BS_*16*32) return;
    int i = idx & 31, h = (idx >> 5) & 15, bs = idx >> 9;
    int s = bs & (S_-1);
    long base = (long)bs*2048 + h*128;
    float x1 = qi[base + i], x2 = qi[base + 32 + i];
    float c = fcos[s*32 + i], sn = fsin[s*32 + i];
    qi[base + i]      = x1*c - x2*sn;
    qi[base + 32 + i] = x1*sn + x2*c;
}

// ---------------- indexer score ------------------------------------------------
__global__ void iscore_kernel(const float* __restrict__ qi, const float* __restrict__ ki,
                              const float* __restrict__ wts, const float* __restrict__ mask,
                              float* __restrict__ iscore) {
    int b = blockIdx.z;
    int s0 = blockIdx.y * 64, t0 = blockIdx.x * 64;
    int tid = threadIdx.x;
    if (t0 > s0 + 63) {
        for (int i = tid; i < 64*64; i += 256) {
            int m = i >> 6, n = i & 63;
            int s = s0 + m, t = t0 + n;
            iscore[((long)b*S_ + s)*S_ + t] = mask[(long)s*S_ + t];
        }
        return;
    }
    int tx = tid & 15, ty = tid >> 4;
    int kl = tid & 15, ml = tid >> 4;
    __shared__ float qs[16][65];
    __shared__ float ks[16][65];
    __shared__ float ws_s[16][64];
    const float IW_SCALE = rsqrtf(2048.0f);
    for (int i = tid; i < 16*64; i += 256) {
        int m = i >> 4, h = i & 15;
        ws_s[h][m] = wts[((long)(b*S_ + s0 + m))*16 + h] * IW_SCALE;
    }
    float acc[4][4];
#pragma unroll
    for (int i = 0; i < 4; i++)
#pragma unroll
        for (int j = 0; j < 4; j++) acc[i][j] = 0.f;
    __syncthreads();

    for (int h = 0; h < 16; h++) {
        float dot[4][4];
#pragma unroll
        for (int i = 0; i < 4; i++)
#pragma unroll
            for (int j = 0; j < 4; j++) dot[i][j] = 0.f;
        for (int d0 = 0; d0 < 128; d0 += 16) {
#pragma unroll
            for (int r = 0; r < 4; r++) {
                int mm = ml + 16*r;
                qs[kl][mm] = qi[((long)(b*S_ + s0 + mm))*2048 + h*128 + d0 + kl];
                ks[kl][mm] = ki[((long)(b*S_ + t0 + mm))*128 + d0 + kl];
            }
            __syncthreads();
#pragma unroll
            for (int kk = 0; kk < 16; kk++) {
                float a[4], bb[4];
#pragma unroll
                for (int i = 0; i < 4; i++) a[i]  = qs[kk][ty + 16*i];
#pragma unroll
                for (int j = 0; j < 4; j++) bb[j] = ks[kk][tx + 16*j];
#pragma unroll
                for (int i = 0; i < 4; i++)
#pragma unroll
                    for (int j = 0; j < 4; j++) dot[i][j] += a[i]*bb[j];
            }
            __syncthreads();
        }
#pragma unroll
        for (int i = 0; i < 4; i++) {
            float w = ws_s[h][ty + 16*i];
#pragma unroll
            for (int j = 0; j < 4; j++) acc[i][j] += fmaxf(dot[i][j], 0.f) * w;
        }
    }
#pragma unroll
    for (int i = 0; i < 4; i++)
#pragma unroll
        for (int j = 0; j < 4; j++) {
            int s = s0 + ty + 16*i, t = t0 + tx + 16*j;
            iscore[((long)b*S_ + s)*S_ + t] = acc[i][j] + mask[(long)s*S_ + t];
        }
}

// ---------------- exact top-512 per row (radix select, deterministic) ---------
__global__ void topk_kernel(const float* __restrict__ iscore, int* __restrict__ out) {
    int row = blockIdx.x;
    const float* p = iscore + (long)row * S_;
    int tid = threadIdx.x; // 256
    __shared__ unsigned int hist[256];
    __shared__ unsigned int s_prefix;
    __shared__ int s_rem;
    __shared__ int sgt[257], seq[257];
    if (tid == 0) { s_prefix = 0u; s_rem = ITOPK_; }
    __syncthreads();
    for (int pass = 0; pass < 4; pass++) {
        hist[tid] = 0u;
        __syncthreads();
        int shift = 24 - 8*pass;
        unsigned int pref = s_prefix;
        for (int e = 0; e < 8; e++) {
            int j = tid*8 + e;
            unsigned int u = __float_as_uint(p[j]);
            unsigned int k = (u & 0x80000000u) ? ~u : (u | 0x80000000u);
            bool ok = (pass == 0) || (((k ^ pref) >> (shift + 8)) == 0u);
            if (ok) atomicAdd(&hist[(k >> shift) & 255u], 1u);
        }
        __syncthreads();
        if (tid == 0) {
            int rem = s_rem;
            unsigned int cum = 0; int bin = 0;
            for (int bb = 255; bb >= 0; bb--) {
                if (cum + hist[bb] >= (unsigned)rem) { bin = bb; break; }
                cum += hist[bb];
            }
            s_rem = rem - (int)cum;
            s_prefix = s_prefix | ((unsigned)bin << shift);
        }
        __syncthreads();
    }
    unsigned int kth = s_prefix;
    int cgt = 0, ceq = 0;
    for (int e = 0; e < 8; e++) {
        int j = tid*8 + e;
        unsigned int u = __float_as_uint(p[j]);
        unsigned int k = (u & 0x80000000u) ? ~u : (u | 0x80000000u);
        cgt += (k > kth); ceq += (k == kth);
    }
    sgt[tid] = cgt; seq[tid] = ceq;
    __syncthreads();
    if (tid == 0) {
        int ag = 0, ae = 0;
        for (int i = 0; i < 256; i++) {
            int tg = sgt[i], te = seq[i];
            sgt[i] = ag; seq[i] = ae;
            ag += tg; ae += te;
        }
        sgt[256] = ag;
    }
    __syncthreads();
    int total_gt = sgt[256];
    int pgt = sgt[tid];
    int peq = total_gt + seq[tid];
    int* o = out + (long)row * ITOPK_;
    for (int e = 0; e < 8; e++) {
        int j = tid*8 + e;
        unsigned int u = __float_as_uint(p[j]);
        unsigned int k = (u & 0x80000000u) ? ~u : (u | 0x80000000u);
        if (k > kth) { o[pgt++] = j; }
        else if (k == kth) { if (peq < ITOPK_) o[peq] = j; peq++; }
    }
}

// ---------------- tensor-core sparse attention ---------------------------------
// One CTA per (b,s). 256 threads, 8 warps. bf16x3 (hi/lo) HMMA for QK and PV.
// smem layout (bytes):
//   [0, 2048)           tl[512] int
//   [2048, 34944)       sc fp32 [16][514]
//   [34944, 72320)      QK: qhi[16][584], qlo (+18688)  /  PV: p_hi[16][520], p_lo (+16640)
//   [72320, 219776)     QK: kt_hi[512][72], kt_lo (+73728) / PV: vt_hi[64][520], vt_lo (+66560)
#define AT_SMEM 219776

__global__ void __launch_bounds__(256, 1)
attn_tc(const float* __restrict__ qabs, const float* __restrict__ qfull,
        const __nv_bfloat16* __restrict__ khi, const __nv_bfloat16* __restrict__ klo,
        const int* __restrict__ topk, float* __restrict__ omid) {
    extern __shared__ char sm[];
    uint32_t sb = smem_u32(sm);
    int* tl = (int*)(sm);
    float* sc = (float*)(sm + 2048);
    __nv_bfloat16* qh = (__nv_bfloat16*)(sm + 34944);
    __nv_bfloat16* ql = (__nv_bfloat16*)(sm + 34944 + 18688);
    int bs = blockIdx.x, b = bs >> 11, s = bs & (S_-1);
    int tid = threadIdx.x, lane = tid & 31, w = tid >> 5;
    const long kb = (long)b * 2048 * 576;

    for (int j = tid; j < 512; j += 256) tl[j] = topk[(long)bs*512 + j];
    const float scale = 0.07216878364870322f;  // 1/sqrt(192)
    for (int i = tid; i < 16*576; i += 256) {
        int h = i / 576, d = i - h*576;
        float v = (d < 512) ? qabs[(long)bs*8192 + h*512 + d]
                            : qfull[(long)bs*3072 + h*192 + 128 + (d - 512)];
        v *= scale;
        __nv_bfloat16 hi = __float2bfloat16_rn(v);
        qh[h*584 + d] = hi;
        ql[h*584 + d] = __float2bfloat16_rn(v - __bfloat162float(hi));
    }
    __syncthreads();

    float acc[8][4];
#pragma unroll
    for (int nt = 0; nt < 8; nt++)
#pragma unroll
        for (int r = 0; r < 4; r++) acc[nt][r] = 0.f;

    // ---- QK: scores[16][512], K dim 576 in 9 chunks of 64
    for (int ch = 0; ch < 9; ch++) {
        int d0 = ch * 64;
        {
            int u = tid & 7, jb = tid >> 3;
#pragma unroll 4
            for (int sw = 0; sw < 16; sw++) {
                int j = sw*32 + jb;
                int t = tl[j];
                const __nv_bfloat16* sh = khi + kb + (long)t*576 + d0;
                const __nv_bfloat16* sl = klo + kb + (long)t*576 + d0;
                uint4 vh = *((const uint4*)sh + u);
                uint4 vl = *((const uint4*)sl + u);
                *(uint4*)(sm + 72320 + (j*72 + u*8)*2) = vh;
                *(uint4*)(sm + 72320 + 73728 + (j*72 + u*8)*2) = vl;
            }
        }
        __syncthreads();
        uint32_t ah[4][4], al[4][4];
        {
            int arow = lane & 15, ac = (lane >> 4) * 8;
#pragma unroll
            for (int ks = 0; ks < 4; ks++) {
                uint32_t ad = sb + 34944 + (arow*584 + d0 + ks*16 + ac)*2;
                LDSM_X4(ah[ks], ad);
                LDSM_X4(al[ks], ad + 18688);
            }
        }
#pragma unroll
        for (int nt = 0; nt < 8; nt++) {
            int n0 = w*64 + nt*8;
            int brow = n0 + (lane & 7);
            int bc = ((lane >> 3) & 1) * 8;
#pragma unroll
            for (int ks = 0; ks < 4; ks++) {
                uint32_t bd = sb + 72320 + (brow*72 + ks*16 + bc)*2;
                uint32_t bh[2], bl[2];
                LDSM_X2(bh, bd);
                LDSM_X2(bl, bd + 73728);
                mma16816(acc[nt], ah[ks], bh);
                mma16816(acc[nt], ah[ks], bl);
                mma16816(acc[nt], al[ks], bh);
            }
        }
        __syncthreads();
    }

    // ---- write scores with causal/topk-validity mask
    {
        int m = lane >> 2, e0 = 2*(lane & 3);
#pragma unroll
        for (int nt = 0; nt < 8; nt++) {
            int n = w*64 + nt*8 + e0;
            bool v0 = tl[n] <= s, v1 = tl[n+1] <= s;
            sc[m*514 + n]         = v0 ? acc[nt][0] : -1e30f;
            sc[m*514 + n + 1]     = v1 ? acc[nt][1] : -1e30f;
            sc[(m+8)*514 + n]     = v0 ? acc[nt][2] : -1e30f;
            sc[(m+8)*514 + n + 1] = v1 ? acc[nt][3] : -1e30f;
        }
    }
    __syncthreads();

    // ---- softmax + P hi/lo conversion (warp w: heads 2w, 2w+1), P reuses q smem
    {
        __nv_bfloat16* ph = (__nv_bfloat16*)(sm + 34944);
        __nv_bfloat16* pl = (__nv_bfloat16*)(sm + 34944 + 16640);
        for (int h = w*2; h <= w*2 + 1; h++) {
            float mx = -1e30f;
            for (int j = lane; j < 512; j += 32) mx = fmaxf(mx, sc[h*514 + j]);
#pragma unroll
            for (int o = 16; o > 0; o >>= 1) mx = fmaxf(mx, __shfl_xor_sync(0xffffffffu, mx, o));
            float ssum = 0.f;
            float ev[16];
#pragma unroll
            for (int jj = 0; jj < 16; jj++) {
                float e = expf(sc[h*514 + lane + jj*32] - mx);
                ev[jj] = e;
                ssum += e;
            }
#pragma unroll
            for (int o = 16; o > 0; o >>= 1) ssum += __shfl_xor_sync(0xffffffffu, ssum, o);
            float inv = 1.f / ssum;
#pragma unroll
            for (int jj = 0; jj < 16; jj++) {
                int j = lane + jj*32;
                float p = ev[jj] * inv;
                __nv_bfloat16 hi = __float2bfloat16_rn(p);
                ph[h*520 + j] = hi;
                pl[h*520 + j] = __float2bfloat16_rn(p - __bfloat162float(hi));
            }
        }
    }
    __syncthreads();

    // ---- PV: O[16][512] = P[16][512] @ V[512][512], keys in 8 chunks of 64
    float oacc[8][4];
#pragma unroll
    for (int nt = 0; nt < 8; nt++)
#pragma unroll
        for (int r = 0; r < 4; r++) oacc[nt][r] = 0.f;

    for (int kc = 0; kc < 8; kc++) {
        {
            int jloc = tid >> 2, qd = tid & 3;
            int t = tl[kc*64 + jloc];
            const __nv_bfloat16* sh = khi + kb + (long)t*576;
            const __nv_bfloat16* sl = klo + kb + (long)t*576;
#pragma unroll 4
            for (int cc = 0; cc < 16; cc++) {
                int c0 = qd*8 + cc*32;
                uint4 vh = *(const uint4*)(sh + c0);
                uint4 vl = *(const uint4*)(sl + c0);
                *(uint4*)(sm + 72320 + (jloc*520 + c0)*2) = vh;
                *(uint4*)(sm + 72320 + 66560 + (jloc*520 + c0)*2) = vl;
            }
        }
        __syncthreads();
        uint32_t ph4[4][4], pl4[4][4];
        {
            int arow = lane & 15, ac = (lane >> 4) * 8;
#pragma unroll
            for (int ks = 0; ks < 4; ks++) {
                uint32_t ad = sb + 34944 + (arow*520 + kc*64 + ks*16 + ac)*2;
                LDSM_X4(ph4[ks], ad);
                LDSM_X4(pl4[ks], ad + 16640);
            }
        }
#pragma unroll
        for (int nt = 0; nt < 8; nt++) {
            int n0 = w*64 + nt*8;
#pragma unroll
            for (int ks = 0; ks < 4; ks++) {
                uint32_t bd = sb + 72320 + ((ks*16 + (lane & 15))*520 + n0)*2;
                uint32_t vh2[2], vl2[2];
                LDSM_X2T(vh2, bd);
                LDSM_X2T(vl2, bd + 66560);
                mma16816(oacc[nt], ph4[ks], vh2);
                mma16816(oacc[nt], ph4[ks], vl2);
                mma16816(oacc[nt], pl4[ks], vh2);
            }
        }
        __syncthreads();
    }

    // ---- epilogue: omid[bs][h][c]
    {
        int m = lane >> 2, e0 = 2*(lane & 3);
#pragma unroll
        for (int nt = 0; nt < 8; nt++) {
            int c = w*64 + nt*8 + e0;
            *(float2*)(omid + (long)bs*8192 + m*512 + c)     = make_float2(oacc[nt][0], oacc[nt][1]);
            *(float2*)(omid + (long)bs*8192 + (m+8)*512 + c) = make_float2(oacc[nt][2], oacc[nt][3]);
        }
    }
}

// ---------------- host orchestration ------------------------------------------
extern "C" void kernel_launch(void* const* d_in, const int* in_sizes, int n_in,
                              void* d_out, int out_size) {
    const float* x      = (const float*)d_in[0];
    const float* fcos   = (const float*)d_in[1];
    const float* fsin   = (const float*)d_in[2];
    const float* mask   = (const float*)d_in[3];
    const float* wq_a   = (const float*)d_in[4];
    const float* qnw    = (const float*)d_in[5];
    const float* wq_b   = (const float*)d_in[6];
    const float* wkv_a  = (const float*)d_in[7];
    const float* kvnw   = (const float*)d_in[8];
    const float* wkv_b  = (const float*)d_in[9];
    const float* wo     = (const float*)d_in[10];
    const float* iwqb   = (const float*)d_in[11];
    const float* iwk    = (const float*)d_in[12];
    const float* iknw   = (const float*)d_in[13];
    const float* iknb   = (const float*)d_in[14];
    const float* iwp    = (const float*)d_in[15];
    float* out = (float*)d_out;

    float *qr, *q, *kvfull, *kv, *kpe, *qabs, *qi, *ki, *wts, *iscore, *omid, *o2, *wt;
    __nv_bfloat16 *khi, *klo;
    int* topkb;
    cudaGetSymbolAddress((void**)&qr,     g_qr);
    cudaGetSymbolAddress((void**)&q,      g_q);
    cudaGetSymbolAddress((void**)&kvfull, g_kvfull);
    cudaGetSymbolAddress((void**)&kv,     g_kv);
    cudaGetSymbolAddress((void**)&kpe,    g_kpe);
    cudaGetSymbolAddress((void**)&qabs,   g_qabs);
    cudaGetSymbolAddress((void**)&qi,     g_qi);
    cudaGetSymbolAddress((void**)&ki,     g_ki);
    cudaGetSymbolAddress((void**)&wts,    g_wts);
    cudaGetSymbolAddress((void**)&iscore, g_iscore);
    cudaGetSymbolAddress((void**)&topkb,  g_topk);
    cudaGetSymbolAddress((void**)&omid,   g_omid);
    cudaGetSymbolAddress((void**)&o2,     g_o2);
    cudaGetSymbolAddress((void**)&wt,     g_wkvbT);
    cudaGetSymbolAddress((void**)&khi,    g_khi);
    cudaGetSymbolAddress((void**)&klo,    g_klo);

    cudaFuncSetAttribute(gemm_mma, cudaFuncAttributeMaxDynamicSharedMemorySize, GM_SMEM);
    cudaFuncSetAttribute(attn_tc,  cudaFuncAttributeMaxDynamicSharedMemorySize, AT_SMEM);

    // qr = rmsnorm(x @ wq_a^T)   [fp32 — feeds indexer/topk, keep bit-identical]
    gemm_bt<<<dim3(12, 64, 1), 256>>>(x, 2048, 0, wq_a, 2048, 0, qr, 768, 0, 4096, 768, 2048);
    rmsnorm_kernel<<<4096, 256>>>(qr, qnw, 768);
    // q = qr @ wq_b^T  [tensor core bf16x3]
    gemm_mma<<<dim3(24, 32, 1), 256, GM_SMEM>>>(qr, 768, 0, wq_b, 768, 0, q, 3072, 0, 4096, 3072, 768);
    rope_q_kernel<<<(BS_*16*32 + 255)/256, 256>>>(q, fcos, fsin);
    // kv path [tensor core]
    gemm_mma<<<dim3(5, 32, 1), 256, GM_SMEM>>>(x, 2048, 0, wkv_a, 2048, 0, kvfull, 576, 0, 4096, 576, 2048);
    kvpost_kernel<<<4096, 256>>>(kvfull, kvnw, fcos, fsin, kv, kpe);
    kvsplit_kernel<<<(BS_*576 + 255)/256, 256>>>(kv, kpe, khi, klo);
    // q_abs = q_nope @ wkv_b3[h,:128,:] via transposed weights [tensor core]
    transpose_wkvb<<<(16*128*512 + 255)/256, 256>>>(wkv_b, wt);
    gemm_mma<<<dim3(4, 32, 16), 256, GM_SMEM>>>(q, 3072, 192, wt, 128, 65536, qabs, 8192, 512,
                                                4096, 512, 128);
    // indexer [fp32 — determines topk]
    gemm_bt<<<dim3(32, 64, 1), 256>>>(qr, 768, 0, iwqb, 768, 0, qi, 2048, 0, 4096, 2048, 768);
    rope_qi_kernel<<<(BS_*16*32 + 255)/256, 256>>>(qi, fcos, fsin);
    gemm_bt<<<dim3(2, 64, 1), 256>>>(x, 2048, 0, iwk, 2048, 0, ki, 128, 0, 4096, 128, 2048);
    kipost_kernel<<<4096, 128>>>(ki, iknw, iknb, fcos, fsin);
    gemm_bt<<<dim3(1, 64, 1), 256>>>(x, 2048, 0, iwp, 2048, 0, wts, 16, 0, 4096, 16, 2048);
    iscore_kernel<<<dim3(32, 32, 2), 256>>>(qi, ki, wts, mask, iscore);
    topk_kernel<<<4096, 256>>>(iscore, topkb);
    // sparse attention [tensor core bf16x3]
    attn_tc<<<4096, 256, AT_SMEM>>>(qabs, q, khi, klo, topkb, omid);
    // o2 = omid @ wkv_b3[h,128:,:]^T  [tensor core]
    gemm_mma<<<dim3(1, 32, 16), 256, GM_SMEM>>>(omid, 8192, 512, wkv_b + 128*512, 512, 256*512,
                                                o2, 2048, 128, 4096, 128, 512);
    // out = o2 @ wo^T  [tensor core]
    gemm_mma<<<dim3(16, 32, 1), 256, GM_SMEM>>>(o2, 2048, 0, wo, 2048, 0, out, 2048, 0, 4096, 2048, 2048);
}

// round 5
// speedup vs baseline: 1.6351x; 1.1636x over previous
#include <cuda_runtime.h>
#include <cuda_bf16.h>
#include <math.h>
#include <stdint.h>

// Problem constants
#define B_    2
#define S_    2048
#define DIM_  2048
#define NH_   16
#define QLR_  768
#define KVLR_ 512
#define NOPE_ 128
#define ROPE_ 64
#define VDIM_ 128
#define IH_   16
#define IHD_  128
#define ITOPK_ 512
#define BS_   (B_*S_)   // 4096

// ---------------- scratch (device globals; no allocation allowed) -------------
__device__ float g_qr[BS_*QLR_];
__device__ float g_q[BS_*NH_*(NOPE_+ROPE_)];
__device__ float g_kvfull[BS_*(KVLR_+ROPE_)];
__device__ float g_kv[BS_*KVLR_];
__device__ float g_kpe[BS_*ROPE_];
__device__ float g_qabs[BS_*NH_*KVLR_];
__device__ float g_qi[BS_*IH_*IHD_];
__device__ float g_ki[BS_*IHD_];
__device__ float g_wts[BS_*IH_];
__device__ float g_iscore[B_*S_*S_];
__device__ int   g_topk[BS_*ITOPK_];
__device__ float g_omid[BS_*NH_*KVLR_];
__device__ float g_o2[BS_*NH_*VDIM_];
__device__ float g_wkvbT[16*512*128];            // transposed wkv_b[:, :128, :] -> [h][c][d]
__device__ __nv_bfloat16 g_khi[BS_*576];         // kv||kpe hi split
__device__ __nv_bfloat16 g_klo[BS_*576];         // kv||kpe lo split

// =================== helpers ==================================================
__device__ __forceinline__ uint32_t smem_u32(const void* p) {
    uint32_t a;
    asm("{ .reg .u64 t; cvta.to.shared.u64 t, %1; cvt.u32.u64 %0, t; }" : "=r"(a) : "l"(p));
    return a;
}
__device__ __forceinline__ uint32_t pack_hi(float x, float y) {
    __nv_bfloat162 p;
    p.x = __float2bfloat16_rn(x);
    p.y = __float2bfloat16_rn(y);
    return *(uint32_t*)&p;
}
__device__ __forceinline__ uint32_t pack_lo(float x, float y) {
    __nv_bfloat16 hx = __float2bfloat16_rn(x);
    __nv_bfloat16 hy = __float2bfloat16_rn(y);
    __nv_bfloat162 p;
    p.x = __float2bfloat16_rn(x - __bfloat162float(hx));
    p.y = __float2bfloat16_rn(y - __bfloat162float(hy));
    return *(uint32_t*)&p;
}
__device__ __forceinline__ void mma16816(float* c, const uint32_t* a, const uint32_t* b) {
    asm volatile("mma.sync.aligned.m16n8k16.row.col.f32.bf16.bf16.f32 "
        "{%0,%1,%2,%3}, {%4,%5,%6,%7}, {%8,%9}, {%0,%1,%2,%3};"
        : "+f"(c[0]), "+f"(c[1]), "+f"(c[2]), "+f"(c[3])
        : "r"(a[0]), "r"(a[1]), "r"(a[2]), "r"(a[3]), "r"(b[0]), "r"(b[1]));
}
#define LDSM_X4(r, a) asm volatile("ldmatrix.sync.aligned.m8n8.x4.shared.b16 {%0,%1,%2,%3}, [%4];" \
    : "=r"((r)[0]),"=r"((r)[1]),"=r"((r)[2]),"=r"((r)[3]) : "r"(a))
#define LDSM_X2(r, a) asm volatile("ldmatrix.sync.aligned.m8n8.x2.shared.b16 {%0,%1}, [%2];" \
    : "=r"((r)[0]),"=r"((r)[1]) : "r"(a))
#define LDSM_X2T(r, a) asm volatile("ldmatrix.sync.aligned.m8n8.x2.trans.shared.b16 {%0,%1}, [%2];" \
    : "=r"((r)[0]),"=r"((r)[1]) : "r"(a))
#define CP_ASYNC16(dst, src) asm volatile("cp.async.cg.shared.global [%0], [%1], 16;" :: "r"(dst), "l"(src))
#define CP_COMMIT() asm volatile("cp.async.commit_group;" ::: "memory")
#define CP_WAIT(n)  asm volatile("cp.async.wait_group %0;" :: "n"(n) : "memory")

// word-granularity swizzled smem address for gemm_mma tiles (128 rows x 16 words)
__device__ __forceinline__ int sw_addr(int row, int w) {
    return row*16 + (w ^ ((((row)>>1)&3)<<2));
}

// =================== tensor-core GEMM (bf16x3): C[M,N]=A[M,K]@B[N,K]^T ========
#define GM_SMEM 65536

__global__ void __launch_bounds__(256, 1)
gemm_mma(const float* __restrict__ A, int lda, long aZ,
         const float* __restrict__ Bm, int ldb, long bZ,
         float* __restrict__ C, int ldc, long cZ,
         int M, int N, int K) {
    extern __shared__ uint32_t smw[];
    A  += (long)blockIdx.z * aZ;
    Bm += (long)blockIdx.z * bZ;
    C  += (long)blockIdx.z * cZ;
    int m0 = blockIdx.y * 128, n0 = blockIdx.x * 128;
    int tid = threadIdx.x, lane = tid & 31, wid = tid >> 5;
    int wm = wid >> 2, wn = wid & 3;
    int g = lane >> 2, tig = lane & 3;

    float acc[4][4][4];
#pragma unroll
    for (int i = 0; i < 4; i++)
#pragma unroll
        for (int j = 0; j < 4; j++)
#pragma unroll
            for (int r = 0; r < 4; r++) acc[i][j][r] = 0.f;

    int arow = tid >> 1, acol = (tid & 1) * 16;
    int nch = K >> 5;

    float4 ra[4], rb[4];
    {
        const float* ap = A + (long)(m0 + arow)*lda + acol;
        bool aok = (m0 + arow) < M;
#pragma unroll
        for (int i = 0; i < 4; i++)
            ra[i] = aok ? *(const float4*)(ap + i*4) : make_float4(0.f,0.f,0.f,0.f);
        const float* bp = Bm + (long)(n0 + arow)*ldb + acol;
        bool bok = (n0 + arow) < N;
#pragma unroll
        for (int i = 0; i < 4; i++)
            rb[i] = bok ? *(const float4*)(bp + i*4) : make_float4(0.f,0.f,0.f,0.f);
    }

    for (int it = 0; it < nch; it++) {
        int stg = it & 1;
        uint32_t* sAhi = smw + stg*8192;
        uint32_t* sAlo = sAhi + 2048;
        uint32_t* sBhi = sAhi + 4096;
        uint32_t* sBlo = sAhi + 6144;
        {
            uint32_t hw[8], lw[8];
#pragma unroll
            for (int i = 0; i < 4; i++) {
                hw[i*2]   = pack_hi(ra[i].x, ra[i].y);
                hw[i*2+1] = pack_hi(ra[i].z, ra[i].w);
                lw[i*2]   = pack_lo(ra[i].x, ra[i].y);
                lw[i*2+1] = pack_lo(ra[i].z, ra[i].w);
            }
            int g0 = (((tid&1)*2 + 0) ^ ((arow>>1)&3)) * 4;
            int g1 = (((tid&1)*2 + 1) ^ ((arow>>1)&3)) * 4;
            uint32_t* dst = sAhi + arow*16;
            *(uint4*)(dst + g0) = make_uint4(hw[0],hw[1],hw[2],hw[3]);
            *(uint4*)(dst + g1) = make_uint4(hw[4],hw[5],hw[6],hw[7]);
            dst = sAlo + arow*16;
            *(uint4*)(dst + g0) = make_uint4(lw[0],lw[1],lw[2],lw[3]);
            *(uint4*)(dst + g1) = make_uint4(lw[4],lw[5],lw[6],lw[7]);
#pragma unroll
            for (int i = 0; i < 4; i++) {
                hw[i*2]   = pack_hi(rb[i].x, rb[i].y);
                hw[i*2+1] = pack_hi(rb[i].z, rb[i].w);
                lw[i*2]   = pack_lo(rb[i].x, rb[i].y);
                lw[i*2+1] = pack_lo(rb[i].z, rb[i].w);
            }
            dst = sBhi + arow*16;
            *(uint4*)(dst + g0) = make_uint4(hw[0],hw[1],hw[2],hw[3]);
            *(uint4*)(dst + g1) = make_uint4(hw[4],hw[5],hw[6],hw[7]);
            dst = sBlo + arow*16;
            *(uint4*)(dst + g0) = make_uint4(lw[0],lw[1],lw[2],lw[3]);
            *(uint4*)(dst + g1) = make_uint4(lw[4],lw[5],lw[6],lw[7]);
        }
        __syncthreads();
        if (it + 1 < nch) {
            int gk = (it + 1) << 5;
            const float* ap = A + (long)(m0 + arow)*lda + gk + acol;
            bool aok = (m0 + arow) < M;
#pragma unroll
            for (int i = 0; i < 4; i++)
                ra[i] = aok ? *(const float4*)(ap + i*4) : make_float4(0.f,0.f,0.f,0.f);
            const float* bp = Bm + (long)(n0 + arow)*ldb + gk + acol;
            bool bok = (n0 + arow) < N;
#pragma unroll
            for (int i = 0; i < 4; i++)
                rb[i] = bok ? *(const float4*)(bp + i*4) : make_float4(0.f,0.f,0.f,0.f);
        }
#pragma unroll
        for (int ks = 0; ks < 2; ks++) {
            uint32_t bh[4][2], bl[4][2];
#pragma unroll
            for (int nt = 0; nt < 4; nt++) {
                int nrow = wn*32 + nt*8 + g;
                int w0 = ks*8 + tig;
                bh[nt][0] = sBhi[sw_addr(nrow, w0)];
                bh[nt][1] = sBhi[sw_addr(nrow, w0+4)];
                bl[nt][0] = sBlo[sw_addr(nrow, w0)];
                bl[nt][1] = sBlo[sw_addr(nrow, w0+4)];
            }
#pragma unroll
            for (int mt = 0; mt < 4; mt++) {
                int ar = wm*64 + mt*16 + g;
                int w0 = ks*8 + tig;
                uint32_t ah[4], al[4];
                ah[0] = sAhi[sw_addr(ar,   w0)];
                ah[1] = sAhi[sw_addr(ar+8, w0)];
                ah[2] = sAhi[sw_addr(ar,   w0+4)];
                ah[3] = sAhi[sw_addr(ar+8, w0+4)];
                al[0] = sAlo[sw_addr(ar,   w0)];
                al[1] = sAlo[sw_addr(ar+8, w0)];
                al[2] = sAlo[sw_addr(ar,   w0+4)];
                al[3] = sAlo[sw_addr(ar+8, w0+4)];
#pragma unroll
                for (int nt = 0; nt < 4; nt++) {
                    mma16816(acc[mt][nt], ah, bh[nt]);
                    mma16816(acc[mt][nt], ah, bl[nt]);
                    mma16816(acc[mt][nt], al, bh[nt]);
                }
            }
        }
        __syncthreads();
    }
#pragma unroll
    for (int mt = 0; mt < 4; mt++) {
#pragma unroll
        for (int nt = 0; nt < 4; nt++) {
            int r0 = m0 + wm*64 + mt*16 + g;
            int c0 = n0 + wn*32 + nt*8 + tig*2;
            if (c0 < N) {
                if (r0 < M)
                    *(float2*)(C + (long)r0*ldc + c0) = make_float2(acc[mt][nt][0], acc[mt][nt][1]);
                if (r0 + 8 < M)
                    *(float2*)(C + (long)(r0+8)*ldc + c0) = make_float2(acc[mt][nt][2], acc[mt][nt][3]);
            }
        }
    }
}

// transpose wkv_b[:, :128, :] -> wt[h][c][d]
__global__ void transpose_wkvb(const float* __restrict__ w, float* __restrict__ wt) {
    int idx = blockIdx.x * 256 + threadIdx.x;
    if (idx >= 16*128*512) return;
    int c = idx & 511, d = (idx >> 9) & 127, h = idx >> 16;
    wt[h*65536 + c*128 + d] = w[h*131072 + d*512 + c];
}

// ---------------- generic fp32 GEMM: C[M,N] = A[M,K] @ B[N,K]^T ---------------
__global__ void gemm_bt(const float* __restrict__ A, int lda, long aZ,
                        const float* __restrict__ Bm, int ldb, long bZ,
                        float* __restrict__ C, int ldc, long cZ,
                        int M, int N, int K) {
    A  += (long)blockIdx.z * aZ;
    Bm += (long)blockIdx.z * bZ;
    C  += (long)blockIdx.z * cZ;
    int n0 = blockIdx.x * 64, m0 = blockIdx.y * 64;
    __shared__ float As[16][65];
    __shared__ float Bs[16][65];
    int tid = threadIdx.x;
    int tx = tid & 15, ty = tid >> 4;
    int kl = tid & 15, ml = tid >> 4;
    float acc[4][4];
#pragma unroll
    for (int i = 0; i < 4; i++)
#pragma unroll
        for (int j = 0; j < 4; j++) acc[i][j] = 0.f;

    for (int k0 = 0; k0 < K; k0 += 16) {
#pragma unroll
        for (int r = 0; r < 4; r++) {
            int mm = ml + 16*r;
            int gm = m0 + mm, gk = k0 + kl, gn = n0 + mm;
            As[kl][mm] = (gm < M && gk < K) ? A[(long)gm*lda + gk] : 0.f;
            Bs[kl][mm] = (gn < N && gk < K) ? Bm[(long)gn*ldb + gk] : 0.f;
        }
        __syncthreads();
#pragma unroll
        for (int kk = 0; kk < 16; kk++) {
            float a[4], bb[4];
#pragma unroll
            for (int i = 0; i < 4; i++) a[i]  = As[kk][ty + 16*i];
#pragma unroll
            for (int j = 0; j < 4; j++) bb[j] = Bs[kk][tx + 16*j];
#pragma unroll
            for (int i = 0; i < 4; i++)
#pragma unroll
                for (int j = 0; j < 4; j++) acc[i][j] += a[i]*bb[j];
        }
        __syncthreads();
    }
#pragma unroll
    for (int i = 0; i < 4; i++)
#pragma unroll
        for (int j = 0; j < 4; j++) {
            int gm = m0 + ty + 16*i, gn = n0 + tx + 16*j;
            if (gm < M && gn < N) C[(long)gm*ldc + gn] = acc[i][j];
        }
}

// ---------------- elementwise / norm / rope -----------------------------------
__global__ void rmsnorm_kernel(float* __restrict__ x, const float* __restrict__ w, int L) {
    int row = blockIdx.x, tid = threadIdx.x;
    float* pr = x + (long)row * L;
    float ss = 0.f;
    for (int i = tid; i < L; i += 256) { float v = pr[i]; ss += v*v; }
    __shared__ float red[256];
    red[tid] = ss; __syncthreads();
    for (int o = 128; o > 0; o >>= 1) { if (tid < o) red[tid] += red[tid+o]; __syncthreads(); }
    float inv = rsqrtf(red[0] / (float)L + 1e-6f);
    for (int i = tid; i < L; i += 256) pr[i] = w[i] * pr[i] * inv;
}

__global__ void kvpost_kernel(const float* __restrict__ kvfull, const float* __restrict__ w,
                              const float* __restrict__ fcos, const float* __restrict__ fsin,
                              float* __restrict__ kv, float* __restrict__ kpe) {
    int row = blockIdx.x, s = row & (S_-1), tid = threadIdx.x;
    const float* src = kvfull + (long)row * 576;
    float ss = 0.f;
    for (int i = tid; i < 512; i += 256) { float v = src[i]; ss += v*v; }
    __shared__ float red[256];
    red[tid] = ss; __syncthreads();
    for (int o = 128; o > 0; o >>= 1) { if (tid < o) red[tid] += red[tid+o]; __syncthreads(); }
    float inv = rsqrtf(red[0] / 512.f + 1e-6f);
    for (int i = tid; i < 512; i += 256) kv[(long)row*512 + i] = w[i] * src[i] * inv;
    if (tid < 32) {
        float x1 = src[512 + tid], x2 = src[544 + tid];
        float c = fcos[s*32 + tid], sn = fsin[s*32 + tid];
        kpe[(long)row*64 + tid]      = x1*c - x2*sn;
        kpe[(long)row*64 + 32 + tid] = x1*sn + x2*c;
    }
}

// split kv||kpe into bf16 hi/lo global arrays
__global__ void kvsplit_kernel(const float* __restrict__ kv, const float* __restrict__ kpe,
                               __nv_bfloat16* __restrict__ khi, __nv_bfloat16* __restrict__ klo) {
    int idx = blockIdx.x*256 + threadIdx.x;
    if (idx >= BS_*576) return;
    int r = idx / 576, d = idx - r*576;
    float v = (d < 512) ? kv[(long)r*512 + d] : kpe[(long)r*64 + d - 512];
    __nv_bfloat16 hi = __float2bfloat16_rn(v);
    khi[idx] = hi;
    klo[idx] = __float2bfloat16_rn(v - __bfloat162float(hi));
}

__global__ void kipost_kernel(float* __restrict__ ki, const float* __restrict__ w,
                              const float* __restrict__ bvec,
                              const float* __restrict__ fcos, const float* __restrict__ fsin) {
    int row = blockIdx.x, s = row & (S_-1), tid = threadIdx.x; // 128 threads
    float* pr = ki + (long)row * 128;
    float v = pr[tid];
    __shared__ float red[128];
    red[tid] = v; __syncthreads();
    for (int o = 64; o > 0; o >>= 1) { if (tid < o) red[tid] += red[tid+o]; __syncthreads(); }
    float mean = red[0] / 128.f;
    __syncthreads();
    float d = v - mean;
    red[tid] = d*d; __syncthreads();
    for (int o = 64; o > 0; o >>= 1) { if (tid < o) red[tid] += red[tid+o]; __syncthreads(); }
    float var = red[0] / 128.f;
    __syncthreads();
    float y = d * rsqrtf(var + 1e-6f) * w[tid] + bvec[tid];
    __shared__ float yb[128];
    yb[tid] = y; __syncthreads();
    float outv;
    if (tid < 32) {
        float c = fcos[s*32 + tid], sn = fsin[s*32 + tid];
        outv = yb[tid]*c - yb[tid+32]*sn;
    } else if (tid < 64) {
        int i = tid - 32;
        float c = fcos[s*32 + i], sn = fsin[s*32 + i];
        outv = yb[i]*sn + yb[tid]*c;
    } else {
        outv = y;
    }
    pr[tid] = outv;
}

__global__ void rope_q_kernel(float* __restrict__ q, const float* __restrict__ fcos,
                              const float* __restrict__ fsin) {
    int idx = blockIdx.x * blockDim.x + threadIdx.x;
    if (idx >= BS_*16*32) return;
    int i = idx & 31, h = (idx >> 5) & 15, bs = idx >> 9;
    int s = bs & (S_-1);
    long base = (long)bs*3072 + h*192 + 128;
    float x1 = q[base + i], x2 = q[base + 32 + i];
    float c = fcos[s*32 + i], sn = fsin[s*32 + i];
    q[base + i]      = x1*c - x2*sn;
    q[base + 32 + i] = x1*sn + x2*c;
}

__global__ void rope_qi_kernel(float* __restrict__ qi, const float* __restrict__ fcos,
                               const float* __restrict__ fsin) {
    int idx = blockIdx.x * blockDim.x + threadIdx.x;
    if (idx >= BS_*16*32) return;
    int i = idx & 31, h = (idx >> 5) & 15, bs = idx >> 9;
    int s = bs & (S_-1);
    long base = (long)bs*2048 + h*128;
    float x1 = qi[base + i], x2 = qi[base + 32 + i];
    float c = fcos[s*32 + i], sn = fsin[s*32 + i];
    qi[base + i]      = x1*c - x2*sn;
    qi[base + 32 + i] = x1*sn + x2*c;
}

// ---------------- indexer score ------------------------------------------------
__global__ void iscore_kernel(const float* __restrict__ qi, const float* __restrict__ ki,
                              const float* __restrict__ wts, const float* __restrict__ mask,
                              float* __restrict__ iscore) {
    int b = blockIdx.z;
    int s0 = blockIdx.y * 64, t0 = blockIdx.x * 64;
    int tid = threadIdx.x;
    if (t0 > s0 + 63) {
        for (int i = tid; i < 64*64; i += 256) {
            int m = i >> 6, n = i & 63;
            int s = s0 + m, t = t0 + n;
            iscore[((long)b*S_ + s)*S_ + t] = mask[(long)s*S_ + t];
        }
        return;
    }
    int tx = tid & 15, ty = tid >> 4;
    int kl = tid & 15, ml = tid >> 4;
    __shared__ float qs[16][65];
    __shared__ float ks[16][65];
    __shared__ float ws_s[16][64];
    const float IW_SCALE = rsqrtf(2048.0f);
    for (int i = tid; i < 16*64; i += 256) {
        int m = i >> 4, h = i & 15;
        ws_s[h][m] = wts[((long)(b*S_ + s0 + m))*16 + h] * IW_SCALE;
    }
    float acc[4][4];
#pragma unroll
    for (int i = 0; i < 4; i++)
#pragma unroll
        for (int j = 0; j < 4; j++) acc[i][j] = 0.f;
    __syncthreads();

    for (int h = 0; h < 16; h++) {
        float dot[4][4];
#pragma unroll
        for (int i = 0; i < 4; i++)
#pragma unroll
            for (int j = 0; j < 4; j++) dot[i][j] = 0.f;
        for (int d0 = 0; d0 < 128; d0 += 16) {
#pragma unroll
            for (int r = 0; r < 4; r++) {
                int mm = ml + 16*r;
                qs[kl][mm] = qi[((long)(b*S_ + s0 + mm))*2048 + h*128 + d0 + kl];
                ks[kl][mm] = ki[((long)(b*S_ + t0 + mm))*128 + d0 + kl];
            }
            __syncthreads();
#pragma unroll
            for (int kk = 0; kk < 16; kk++) {
                float a[4], bb[4];
#pragma unroll
                for (int i = 0; i < 4; i++) a[i]  = qs[kk][ty + 16*i];
#pragma unroll
                for (int j = 0; j < 4; j++) bb[j] = ks[kk][tx + 16*j];
#pragma unroll
                for (int i = 0; i < 4; i++)
#pragma unroll
                    for (int j = 0; j < 4; j++) dot[i][j] += a[i]*bb[j];
            }
            __syncthreads();
        }
#pragma unroll
        for (int i = 0; i < 4; i++) {
            float w = ws_s[h][ty + 16*i];
#pragma unroll
            for (int j = 0; j < 4; j++) acc[i][j] += fmaxf(dot[i][j], 0.f) * w;
        }
    }
#pragma unroll
    for (int i = 0; i < 4; i++)
#pragma unroll
        for (int j = 0; j < 4; j++) {
            int s = s0 + ty + 16*i, t = t0 + tx + 16*j;
            iscore[((long)b*S_ + s)*S_ + t] = acc[i][j] + mask[(long)s*S_ + t];
        }
}

// ---------------- exact top-512 per row (radix select, deterministic) ---------
__global__ void topk_kernel(const float* __restrict__ iscore, int* __restrict__ out) {
    int row = blockIdx.x;
    const float* p = iscore + (long)row * S_;
    int tid = threadIdx.x; // 256
    __shared__ unsigned int hist[256];
    __shared__ unsigned int s_prefix;
    __shared__ int s_rem;
    __shared__ int sgt[257], seq[257];
    if (tid == 0) { s_prefix = 0u; s_rem = ITOPK_; }
    __syncthreads();
    for (int pass = 0; pass < 4; pass++) {
        hist[tid] = 0u;
        __syncthreads();
        int shift = 24 - 8*pass;
        unsigned int pref = s_prefix;
        for (int e = 0; e < 8; e++) {
            int j = tid*8 + e;
            unsigned int u = __float_as_uint(p[j]);
            unsigned int k = (u & 0x80000000u) ? ~u : (u | 0x80000000u);
            bool ok = (pass == 0) || (((k ^ pref) >> (shift + 8)) == 0u);
            if (ok) atomicAdd(&hist[(k >> shift) & 255u], 1u);
        }
        __syncthreads();
        if (tid == 0) {
            int rem = s_rem;
            unsigned int cum = 0; int bin = 0;
            for (int bb = 255; bb >= 0; bb--) {
                if (cum + hist[bb] >= (unsigned)rem) { bin = bb; break; }
                cum += hist[bb];
            }
            s_rem = rem - (int)cum;
            s_prefix = s_prefix | ((unsigned)bin << shift);
        }
        __syncthreads();
    }
    unsigned int kth = s_prefix;
    int cgt = 0, ceq = 0;
    for (int e = 0; e < 8; e++) {
        int j = tid*8 + e;
        unsigned int u = __float_as_uint(p[j]);
        unsigned int k = (u & 0x80000000u) ? ~u : (u | 0x80000000u);
        cgt += (k > kth); ceq += (k == kth);
    }
    sgt[tid] = cgt; seq[tid] = ceq;
    __syncthreads();
    if (tid == 0) {
        int ag = 0, ae = 0;
        for (int i = 0; i < 256; i++) {
            int tg = sgt[i], te = seq[i];
            sgt[i] = ag; seq[i] = ae;
            ag += tg; ae += te;
        }
        sgt[256] = ag;
    }
    __syncthreads();
    int total_gt = sgt[256];
    int pgt = sgt[tid];
    int peq = total_gt + seq[tid];
    int* o = out + (long)row * ITOPK_;
    for (int e = 0; e < 8; e++) {
        int j = tid*8 + e;
        unsigned int u = __float_as_uint(p[j]);
        unsigned int k = (u & 0x80000000u) ? ~u : (u | 0x80000000u);
        if (k > kth) { o[pgt++] = j; }
        else if (k == kth) { if (peq < ITOPK_) o[peq] = j; peq++; }
    }
}

// ---------------- fused flash-style tensor-core sparse attention ---------------
// One CTA per (b,s), 256 threads / 8 warps. Online softmax over 16 chunks of 32
// topk tokens; each token's full 576-dim kv||kpe hi/lo row gathered ONCE via
// cp.async (double-buffered), used for QK (ldsm) and PV (ldsm.trans).
// smem (bytes):
//   0      tl[512]                    2048
//   2048   m_s[16], l_s[16], al_s[16]
//   2304   sc[2][16][34] f32          4352
//   8192   qh[16][584] bf16           18688
//   26880  ql[16][584]                18688
//   45568  ph[16][40]                 1280
//   46848  pl[16][40]                 1280
//   48128  buf{0,1}: hi[32][584] + lo[32][584]  (74752 each)
#define AT_SMEM 197632
#define AT_BUF0 48128
#define AT_BUFSZ 74752
#define AT_LO 37376

__device__ __forceinline__ void at_gather(const __nv_bfloat16* __restrict__ khi,
                                          const __nv_bfloat16* __restrict__ klo,
                                          long kb, const int* tl, int c,
                                          uint32_t bufaddr, int tid) {
    int jloc = tid >> 3, sg0 = tid & 7;
    int t = tl[c*32 + jloc];
    const char* sh = (const char*)(khi + kb + (long)t*576);
    const char* sl = (const char*)(klo + kb + (long)t*576);
    uint32_t dh = bufaddr + jloc*1168;
#pragma unroll
    for (int u = 0; u < 9; u++) {
        int off = (sg0 + u*8) * 16;
        CP_ASYNC16(dh + off, sh + off);
        CP_ASYNC16(dh + AT_LO + off, sl + off);
    }
    CP_COMMIT();
}

__global__ void __launch_bounds__(256, 1)
attn_tc(const float* __restrict__ qabs, const float* __restrict__ qfull,
        const __nv_bfloat16* __restrict__ khi, const __nv_bfloat16* __restrict__ klo,
        const int* __restrict__ topk, float* __restrict__ omid) {
    extern __shared__ char sm[];
    uint32_t sb = smem_u32(sm);
    int* tl = (int*)sm;
    float* m_s  = (float*)(sm + 2048);
    float* l_s  = (float*)(sm + 2112);
    float* al_s = (float*)(sm + 2176);
    float* sc   = (float*)(sm + 2304);       // [2][16][34]
    __nv_bfloat16* qh = (__nv_bfloat16*)(sm + 8192);
    __nv_bfloat16* ql = (__nv_bfloat16*)(sm + 26880);
    __nv_bfloat16* ph = (__nv_bfloat16*)(sm + 45568);
    __nv_bfloat16* pl = (__nv_bfloat16*)(sm + 46848);
    int bs = blockIdx.x, b = bs >> 11, s = bs & (S_-1);
    int tid = threadIdx.x, lane = tid & 31, w = tid >> 5;
    const long kb = (long)b * 2048 * 576;

    for (int j = tid; j < 512; j += 256) tl[j] = topk[(long)bs*512 + j];
    if (tid < 16) { m_s[tid] = -1e30f; l_s[tid] = 0.f; }
    const float scale = 0.07216878364870322f;  // 1/sqrt(192)
    __syncthreads();   // tl ready (gather + q-load both need it? q-load doesn't, but keep order)
    for (int i = tid; i < 16*576; i += 256) {
        int h = i / 576, d = i - h*576;
        float v = (d < 512) ? qabs[(long)bs*8192 + h*512 + d]
                            : qfull[(long)bs*3072 + h*192 + 128 + (d - 512)];
        v *= scale;
        __nv_bfloat16 hi = __float2bfloat16_rn(v);
        qh[h*584 + d] = hi;
        ql[h*584 + d] = __float2bfloat16_rn(v - __bfloat162float(hi));
    }
    // prologue gather of chunk 0
    at_gather(khi, klo, kb, tl, 0, sb + AT_BUF0, tid);
    __syncthreads();   // q tiles ready for all warps

    float oacc[8][4];
#pragma unroll
    for (int nt = 0; nt < 8; nt++)
#pragma unroll
        for (int r = 0; r < 4; r++) oacc[nt][r] = 0.f;

    int kh = w >> 2, nt4 = w & 3;
    int arow = lane & 15, ac = (lane >> 4) * 8;
    int brow = nt4*8 + (lane & 7), bc = ((lane >> 3) & 1) * 8;

    for (int c = 0; c < 16; c++) {
        uint32_t buf = sb + AT_BUF0 + (c & 1)*AT_BUFSZ;
        if (c < 15) {
            at_gather(khi, klo, kb, tl, c+1, sb + AT_BUF0 + ((c+1)&1)*AT_BUFSZ, tid);
            CP_WAIT(1);
        } else {
            CP_WAIT(0);
        }
        __syncthreads();   // buf[c&1] fully gathered

        // ---- QK partial: warp w -> k-half kh, token n-tile nt4
        float qk[4] = {0.f, 0.f, 0.f, 0.f};
#pragma unroll
        for (int ks = 0; ks < 18; ks++) {
            int d = kh*288 + ks*16;
            uint32_t ah[4], alr[4], bh[2], bl[2];
            uint32_t ad = sb + 8192 + (arow*584 + d + ac)*2;
            LDSM_X4(ah, ad);
            LDSM_X4(alr, ad + 18688);
            uint32_t bd = buf + (brow*584 + d + bc)*2;
            LDSM_X2(bh, bd);
            LDSM_X2(bl, bd + AT_LO);
            mma16816(qk, ah, bh);
            mma16816(qk, ah, bl);
            mma16816(qk, alr, bh);
        }
        {
            int m_ = lane >> 2, e0 = 2*(lane & 3);
            float* scr = sc + kh*544;
            scr[m_*34 + nt4*8 + e0]       = qk[0];
            scr[m_*34 + nt4*8 + e0 + 1]   = qk[1];
            scr[(m_+8)*34 + nt4*8 + e0]   = qk[2];
            scr[(m_+8)*34 + nt4*8 + e0+1] = qk[3];
        }
        __syncthreads();

        // ---- online softmax: warp w handles heads 2w, 2w+1; lane = local key
        {
            int t = tl[c*32 + lane];
            bool valid = (t <= s);
#pragma unroll
            for (int hi2 = 0; hi2 < 2; hi2++) {
                int hh = w*2 + hi2;
                float v = sc[hh*34 + lane] + sc[544 + hh*34 + lane];
                float val = valid ? v : -1e30f;
                float mc = val;
#pragma unroll
                for (int o = 16; o > 0; o >>= 1) mc = fmaxf(mc, __shfl_xor_sync(0xffffffffu, mc, o));
                float m_old = m_s[hh];
                float m_new = fmaxf(m_old, mc);
                float a = expf(m_old - m_new);
                float p = valid ? expf(val - m_new) : 0.f;
                float psum = p;
#pragma unroll
                for (int o = 16; o > 0; o >>= 1) psum += __shfl_xor_sync(0xffffffffu, psum, o);
                if (lane == 0) { m_s[hh] = m_new; l_s[hh] = l_s[hh]*a + psum; al_s[hh] = a; }
                __nv_bfloat16 phi = __float2bfloat16_rn(p);
                ph[hh*40 + lane] = phi;
                pl[hh*40 + lane] = __float2bfloat16_rn(p - __bfloat162float(phi));
            }
        }
        __syncthreads();   // alpha + p ready

        // ---- rescale O and PV accumulate (warp w owns cols w*64..w*64+63)
        {
            float a0 = al_s[lane >> 2], a1 = al_s[(lane >> 2) + 8];
#pragma unroll
            for (int nt = 0; nt < 8; nt++) {
                oacc[nt][0] *= a0; oacc[nt][1] *= a0;
                oacc[nt][2] *= a1; oacc[nt][3] *= a1;
            }
            uint32_t ph4[2][4], pl4[2][4];
#pragma unroll
            for (int ks = 0; ks < 2; ks++) {
                uint32_t ad = sb + 45568 + (arow*40 + ks*16 + ac)*2;
                LDSM_X4(ph4[ks], ad);
                LDSM_X4(pl4[ks], ad + 1280);
            }
#pragma unroll
            for (int nt = 0; nt < 8; nt++) {
                int n0 = w*64 + nt*8;
#pragma unroll
                for (int ks = 0; ks < 2; ks++) {
                    uint32_t bd = buf + ((ks*16 + (lane & 15))*584 + n0)*2;
                    uint32_t vh[2], vl[2];
                    LDSM_X2T(vh, bd);
                    LDSM_X2T(vl, bd + AT_LO);
                    mma16816(oacc[nt], ph4[ks], vh);
                    mma16816(oacc[nt], ph4[ks], vl);
                    mma16816(oacc[nt], pl4[ks], vh);
                }
            }
        }
        __syncthreads();   // done reading buf[c&1]; next iter may overwrite it
    }

    // ---- epilogue: normalize by l and store
    {
        int m_ = lane >> 2, e0 = 2*(lane & 3);
        float li0 = 1.f / l_s[m_];
        float li1 = 1.f / l_s[m_ + 8];
#pragma unroll
        for (int nt = 0; nt < 8; nt++) {
            int c0 = w*64 + nt*8 + e0;
            *(float2*)(omid + (long)bs*8192 + m_*512 + c0)     = make_float2(oacc[nt][0]*li0, oacc[nt][1]*li0);
            *(float2*)(omid + (long)bs*8192 + (m_+8)*512 + c0) = make_float2(oacc[nt][2]*li1, oacc[nt][3]*li1);
        }
    }
}

// ---------------- host orchestration ------------------------------------------
extern "C" void kernel_launch(void* const* d_in, const int* in_sizes, int n_in,
                              void* d_out, int out_size) {
    const float* x      = (const float*)d_in[0];
    const float* fcos   = (const float*)d_in[1];
    const float* fsin   = (const float*)d_in[2];
    const float* mask   = (const float*)d_in[3];
    const float* wq_a   = (const float*)d_in[4];
    const float* qnw    = (const float*)d_in[5];
    const float* wq_b   = (const float*)d_in[6];
    const float* wkv_a  = (const float*)d_in[7];
    const float* kvnw   = (const float*)d_in[8];
    const float* wkv_b  = (const float*)d_in[9];
    const float* wo     = (const float*)d_in[10];
    const float* iwqb   = (const float*)d_in[11];
    const float* iwk    = (const float*)d_in[12];
    const float* iknw   = (const float*)d_in[13];
    const float* iknb   = (const float*)d_in[14];
    const float* iwp    = (const float*)d_in[15];
    float* out = (float*)d_out;

    float *qr, *q, *kvfull, *kv, *kpe, *qabs, *qi, *ki, *wts, *iscore, *omid, *o2, *wt;
    __nv_bfloat16 *khi, *klo;
    int* topkb;
    cudaGetSymbolAddress((void**)&qr,     g_qr);
    cudaGetSymbolAddress((void**)&q,      g_q);
    cudaGetSymbolAddress((void**)&kvfull, g_kvfull);
    cudaGetSymbolAddress((void**)&kv,     g_kv);
    cudaGetSymbolAddress((void**)&kpe,    g_kpe);
    cudaGetSymbolAddress((void**)&qabs,   g_qabs);
    cudaGetSymbolAddress((void**)&qi,     g_qi);
    cudaGetSymbolAddress((void**)&ki,     g_ki);
    cudaGetSymbolAddress((void**)&wts,    g_wts);
    cudaGetSymbolAddress((void**)&iscore, g_iscore);
    cudaGetSymbolAddress((void**)&topkb,  g_topk);
    cudaGetSymbolAddress((void**)&omid,   g_omid);
    cudaGetSymbolAddress((void**)&o2,     g_o2);
    cudaGetSymbolAddress((void**)&wt,     g_wkvbT);
    cudaGetSymbolAddress((void**)&khi,    g_khi);
    cudaGetSymbolAddress((void**)&klo,    g_klo);

    cudaFuncSetAttribute(gemm_mma, cudaFuncAttributeMaxDynamicSharedMemorySize, GM_SMEM);
    cudaFuncSetAttribute(attn_tc,  cudaFuncAttributeMaxDynamicSharedMemorySize, AT_SMEM);

    // qr = rmsnorm(x @ wq_a^T)   [fp32 — feeds indexer/topk, keep bit-identical]
    gemm_bt<<<dim3(12, 64, 1), 256>>>(x, 2048, 0, wq_a, 2048, 0, qr, 768, 0, 4096, 768, 2048);
    rmsnorm_kernel<<<4096, 256>>>(qr, qnw, 768);
    // q = qr @ wq_b^T  [tensor core bf16x3]
    gemm_mma<<<dim3(24, 32, 1), 256, GM_SMEM>>>(qr, 768, 0, wq_b, 768, 0, q, 3072, 0, 4096, 3072, 768);
    rope_q_kernel<<<(BS_*16*32 + 255)/256, 256>>>(q, fcos, fsin);
    // kv path [tensor core]
    gemm_mma<<<dim3(5, 32, 1), 256, GM_SMEM>>>(x, 2048, 0, wkv_a, 2048, 0, kvfull, 576, 0, 4096, 576, 2048);
    kvpost_kernel<<<4096, 256>>>(kvfull, kvnw, fcos, fsin, kv, kpe);
    kvsplit_kernel<<<(BS_*576 + 255)/256, 256>>>(kv, kpe, khi, klo);
    // q_abs = q_nope @ wkv_b3[h,:128,:] via transposed weights [tensor core]
    transpose_wkvb<<<(16*128*512 + 255)/256, 256>>>(wkv_b, wt);
    gemm_mma<<<dim3(4, 32, 16), 256, GM_SMEM>>>(q, 3072, 192, wt, 128, 65536, qabs, 8192, 512,
                                                4096, 512, 128);
    // indexer [fp32 — determines topk]
    gemm_bt<<<dim3(32, 64, 1), 256>>>(qr, 768, 0, iwqb, 768, 0, qi, 2048, 0, 4096, 2048, 768);
    rope_qi_kernel<<<(BS_*16*32 + 255)/256, 256>>>(qi, fcos, fsin);
    gemm_bt<<<dim3(2, 64, 1), 256>>>(x, 2048, 0, iwk, 2048, 0, ki, 128, 0, 4096, 128, 2048);
    kipost_kernel<<<4096, 128>>>(ki, iknw, iknb, fcos, fsin);
    gemm_bt<<<dim3(1, 64, 1), 256>>>(x, 2048, 0, iwp, 2048, 0, wts, 16, 0, 4096, 16, 2048);
    iscore_kernel<<<dim3(32, 32, 2), 256>>>(qi, ki, wts, mask, iscore);
    topk_kernel<<<4096, 256>>>(iscore, topkb);
    // fused sparse attention [tensor core bf16x3, single gather, cp.async dbuf]
    attn_tc<<<4096, 256, AT_SMEM>>>(qabs, q, khi, klo, topkb, omid);
    // o2 = omid @ wkv_b3[h,128:,:]^T  [tensor core]
    gemm_mma<<<dim3(1, 32, 16), 256, GM_SMEM>>>(omid, 8192, 512, wkv_b + 128*512, 512, 256*512,
                                                o2, 2048, 128, 4096, 128, 512);
    // out = o2 @ wo^T  [tensor core]
    gemm_mma<<<dim3(16, 32, 1), 256, GM_SMEM>>>(o2, 2048, 0, wo, 2048, 0, out, 2048, 0, 4096, 2048, 2048);
}

// round 6
// speedup vs baseline: 1.7216x; 1.0529x over previous
#include <cuda_runtime.h>
#include <cuda_bf16.h>
#include <math.h>
#include <stdint.h>

// Problem constants
#define B_    2
#define S_    2048
#define DIM_  2048
#define NH_   16
#define QLR_  768
#define KVLR_ 512
#define NOPE_ 128
#define ROPE_ 64
#define VDIM_ 128
#define IH_   16
#define IHD_  128
#define ITOPK_ 512
#define BS_   (B_*S_)   // 4096

// ---------------- scratch (device globals; no allocation allowed) -------------
__device__ float g_qr[BS_*QLR_];
__device__ float g_q[BS_*NH_*(NOPE_+ROPE_)];
__device__ float g_kvfull[BS_*(KVLR_+ROPE_)];
__device__ float g_kv[BS_*KVLR_];
__device__ float g_kpe[BS_*ROPE_];
__device__ float g_qabs[BS_*NH_*KVLR_];
__device__ float g_qi[BS_*IH_*IHD_];
__device__ float g_ki[BS_*IHD_];
__device__ float g_wts[BS_*IH_];
__device__ float g_iscore[B_*S_*S_];
__device__ int   g_topk[BS_*ITOPK_];
__device__ float g_omid[BS_*NH_*KVLR_];
__device__ float g_o2[BS_*NH_*VDIM_];
__device__ float g_wkvbT[16*512*128];            // transposed wkv_b[:, :128, :] -> [h][c][d]
__device__ __nv_bfloat16 g_khi[BS_*576];         // kv||kpe hi split
__device__ __nv_bfloat16 g_klo[BS_*576];         // kv||kpe lo split

// =================== helpers ==================================================
__device__ __forceinline__ uint32_t smem_u32(const void* p) {
    uint32_t a;
    asm("{ .reg .u64 t; cvta.to.shared.u64 t, %1; cvt.u32.u64 %0, t; }" : "=r"(a) : "l"(p));
    return a;
}
__device__ __forceinline__ uint32_t pack_hi(float x, float y) {
    __nv_bfloat162 p;
    p.x = __float2bfloat16_rn(x);
    p.y = __float2bfloat16_rn(y);
    return *(uint32_t*)&p;
}
__device__ __forceinline__ uint32_t pack_lo(float x, float y) {
    __nv_bfloat16 hx = __float2bfloat16_rn(x);
    __nv_bfloat16 hy = __float2bfloat16_rn(y);
    __nv_bfloat162 p;
    p.x = __float2bfloat16_rn(x - __bfloat162float(hx));
    p.y = __float2bfloat16_rn(y - __bfloat162float(hy));
    return *(uint32_t*)&p;
}
__device__ __forceinline__ void mma16816(float* c, const uint32_t* a, const uint32_t* b) {
    asm volatile("mma.sync.aligned.m16n8k16.row.col.f32.bf16.bf16.f32 "
        "{%0,%1,%2,%3}, {%4,%5,%6,%7}, {%8,%9}, {%0,%1,%2,%3};"
        : "+f"(c[0]), "+f"(c[1]), "+f"(c[2]), "+f"(c[3])
        : "r"(a[0]), "r"(a[1]), "r"(a[2]), "r"(a[3]), "r"(b[0]), "r"(b[1]));
}
#define LDSM_X4(r, a) asm volatile("ldmatrix.sync.aligned.m8n8.x4.shared.b16 {%0,%1,%2,%3}, [%4];" \
    : "=r"((r)[0]),"=r"((r)[1]),"=r"((r)[2]),"=r"((r)[3]) : "r"(a))
#define LDSM_X2(r, a) asm volatile("ldmatrix.sync.aligned.m8n8.x2.shared.b16 {%0,%1}, [%2];" \
    : "=r"((r)[0]),"=r"((r)[1]) : "r"(a))
#define LDSM_X2T(r, a) asm volatile("ldmatrix.sync.aligned.m8n8.x2.trans.shared.b16 {%0,%1}, [%2];" \
    : "=r"((r)[0]),"=r"((r)[1]) : "r"(a))
#define CP_ASYNC16(dst, src) asm volatile("cp.async.cg.shared.global [%0], [%1], 16;" :: "r"(dst), "l"(src))
#define CP_COMMIT() asm volatile("cp.async.commit_group;" ::: "memory")
#define CP_WAIT(n)  asm volatile("cp.async.wait_group %0;" :: "n"(n) : "memory")

// word-granularity swizzled smem address for gemm_mma tiles (128 rows x 16 words)
__device__ __forceinline__ int sw_addr(int row, int w) {
    return row*16 + (w ^ ((((row)>>1)&3)<<2));
}

// =================== tensor-core GEMM (bf16x3): C[M,N]=A[M,K]@B[N,K]^T ========
#define GM_SMEM 65536

__global__ void __launch_bounds__(256, 1)
gemm_mma(const float* __restrict__ A, int lda, long aZ,
         const float* __restrict__ Bm, int ldb, long bZ,
         float* __restrict__ C, int ldc, long cZ,
         int M, int N, int K) {
    extern __shared__ uint32_t smw[];
    A  += (long)blockIdx.z * aZ;
    Bm += (long)blockIdx.z * bZ;
    C  += (long)blockIdx.z * cZ;
    int m0 = blockIdx.y * 128, n0 = blockIdx.x * 128;
    int tid = threadIdx.x, lane = tid & 31, wid = tid >> 5;
    int wm = wid >> 2, wn = wid & 3;
    int g = lane >> 2, tig = lane & 3;

    float acc[4][4][4];
#pragma unroll
    for (int i = 0; i < 4; i++)
#pragma unroll
        for (int j = 0; j < 4; j++)
#pragma unroll
            for (int r = 0; r < 4; r++) acc[i][j][r] = 0.f;

    int arow = tid >> 1, acol = (tid & 1) * 16;
    int nch = K >> 5;

    float4 ra[4], rb[4];
    {
        const float* ap = A + (long)(m0 + arow)*lda + acol;
        bool aok = (m0 + arow) < M;
#pragma unroll
        for (int i = 0; i < 4; i++)
            ra[i] = aok ? *(const float4*)(ap + i*4) : make_float4(0.f,0.f,0.f,0.f);
        const float* bp = Bm + (long)(n0 + arow)*ldb + acol;
        bool bok = (n0 + arow) < N;
#pragma unroll
        for (int i = 0; i < 4; i++)
            rb[i] = bok ? *(const float4*)(bp + i*4) : make_float4(0.f,0.f,0.f,0.f);
    }

    for (int it = 0; it < nch; it++) {
        int stg = it & 1;
        uint32_t* sAhi = smw + stg*8192;
        uint32_t* sAlo = sAhi + 2048;
        uint32_t* sBhi = sAhi + 4096;
        uint32_t* sBlo = sAhi + 6144;
        {
            uint32_t hw[8], lw[8];
#pragma unroll
            for (int i = 0; i < 4; i++) {
                hw[i*2]   = pack_hi(ra[i].x, ra[i].y);
                hw[i*2+1] = pack_hi(ra[i].z, ra[i].w);
                lw[i*2]   = pack_lo(ra[i].x, ra[i].y);
                lw[i*2+1] = pack_lo(ra[i].z, ra[i].w);
            }
            int g0 = (((tid&1)*2 + 0) ^ ((arow>>1)&3)) * 4;
            int g1 = (((tid&1)*2 + 1) ^ ((arow>>1)&3)) * 4;
            uint32_t* dst = sAhi + arow*16;
            *(uint4*)(dst + g0) = make_uint4(hw[0],hw[1],hw[2],hw[3]);
            *(uint4*)(dst + g1) = make_uint4(hw[4],hw[5],hw[6],hw[7]);
            dst = sAlo + arow*16;
            *(uint4*)(dst + g0) = make_uint4(lw[0],lw[1],lw[2],lw[3]);
            *(uint4*)(dst + g1) = make_uint4(lw[4],lw[5],lw[6],lw[7]);
#pragma unroll
            for (int i = 0; i < 4; i++) {
                hw[i*2]   = pack_hi(rb[i].x, rb[i].y);
                hw[i*2+1] = pack_hi(rb[i].z, rb[i].w);
                lw[i*2]   = pack_lo(rb[i].x, rb[i].y);
                lw[i*2+1] = pack_lo(rb[i].z, rb[i].w);
            }
            dst = sBhi + arow*16;
            *(uint4*)(dst + g0) = make_uint4(hw[0],hw[1],hw[2],hw[3]);
            *(uint4*)(dst + g1) = make_uint4(hw[4],hw[5],hw[6],hw[7]);
            dst = sBlo + arow*16;
            *(uint4*)(dst + g0) = make_uint4(lw[0],lw[1],lw[2],lw[3]);
            *(uint4*)(dst + g1) = make_uint4(lw[4],lw[5],lw[6],lw[7]);
        }
        __syncthreads();
        if (it + 1 < nch) {
            int gk = (it + 1) << 5;
            const float* ap = A + (long)(m0 + arow)*lda + gk + acol;
            bool aok = (m0 + arow) < M;
#pragma unroll
            for (int i = 0; i < 4; i++)
                ra[i] = aok ? *(const float4*)(ap + i*4) : make_float4(0.f,0.f,0.f,0.f);
            const float* bp = Bm + (long)(n0 + arow)*ldb + gk + acol;
            bool bok = (n0 + arow) < N;
#pragma unroll
            for (int i = 0; i < 4; i++)
                rb[i] = bok ? *(const float4*)(bp + i*4) : make_float4(0.f,0.f,0.f,0.f);
        }
#pragma unroll
        for (int ks = 0; ks < 2; ks++) {
            uint32_t bh[4][2], bl[4][2];
#pragma unroll
            for (int nt = 0; nt < 4; nt++) {
                int nrow = wn*32 + nt*8 + g;
                int w0 = ks*8 + tig;
                bh[nt][0] = sBhi[sw_addr(nrow, w0)];
                bh[nt][1] = sBhi[sw_addr(nrow, w0+4)];
                bl[nt][0] = sBlo[sw_addr(nrow, w0)];
                bl[nt][1] = sBlo[sw_addr(nrow, w0+4)];
            }
#pragma unroll
            for (int mt = 0; mt < 4; mt++) {
                int ar = wm*64 + mt*16 + g;
                int w0 = ks*8 + tig;
                uint32_t ah[4], al[4];
                ah[0] = sAhi[sw_addr(ar,   w0)];
                ah[1] = sAhi[sw_addr(ar+8, w0)];
                ah[2] = sAhi[sw_addr(ar,   w0+4)];
                ah[3] = sAhi[sw_addr(ar+8, w0+4)];
                al[0] = sAlo[sw_addr(ar,   w0)];
                al[1] = sAlo[sw_addr(ar+8, w0)];
                al[2] = sAlo[sw_addr(ar,   w0+4)];
                al[3] = sAlo[sw_addr(ar+8, w0+4)];
#pragma unroll
                for (int nt = 0; nt < 4; nt++) {
                    mma16816(acc[mt][nt], ah, bh[nt]);
                    mma16816(acc[mt][nt], ah, bl[nt]);
                    mma16816(acc[mt][nt], al, bh[nt]);
                }
            }
        }
        __syncthreads();
    }
#pragma unroll
    for (int mt = 0; mt < 4; mt++) {
#pragma unroll
        for (int nt = 0; nt < 4; nt++) {
            int r0 = m0 + wm*64 + mt*16 + g;
            int c0 = n0 + wn*32 + nt*8 + tig*2;
            if (c0 < N) {
                if (r0 < M)
                    *(float2*)(C + (long)r0*ldc + c0) = make_float2(acc[mt][nt][0], acc[mt][nt][1]);
                if (r0 + 8 < M)
                    *(float2*)(C + (long)(r0+8)*ldc + c0) = make_float2(acc[mt][nt][2], acc[mt][nt][3]);
            }
        }
    }
}

// transpose wkv_b[:, :128, :] -> wt[h][c][d]
__global__ void transpose_wkvb(const float* __restrict__ w, float* __restrict__ wt) {
    int idx = blockIdx.x * 256 + threadIdx.x;
    if (idx >= 16*128*512) return;
    int c = idx & 511, d = (idx >> 9) & 127, h = idx >> 16;
    wt[h*65536 + c*128 + d] = w[h*131072 + d*512 + c];
}

// ---------------- generic fp32 GEMM: C[M,N] = A[M,K] @ B[N,K]^T ---------------
__global__ void gemm_bt(const float* __restrict__ A, int lda, long aZ,
                        const float* __restrict__ Bm, int ldb, long bZ,
                        float* __restrict__ C, int ldc, long cZ,
                        int M, int N, int K) {
    A  += (long)blockIdx.z * aZ;
    Bm += (long)blockIdx.z * bZ;
    C  += (long)blockIdx.z * cZ;
    int n0 = blockIdx.x * 64, m0 = blockIdx.y * 64;
    __shared__ float As[16][65];
    __shared__ float Bs[16][65];
    int tid = threadIdx.x;
    int tx = tid & 15, ty = tid >> 4;
    int kl = tid & 15, ml = tid >> 4;
    float acc[4][4];
#pragma unroll
    for (int i = 0; i < 4; i++)
#pragma unroll
        for (int j = 0; j < 4; j++) acc[i][j] = 0.f;

    for (int k0 = 0; k0 < K; k0 += 16) {
#pragma unroll
        for (int r = 0; r < 4; r++) {
            int mm = ml + 16*r;
            int gm = m0 + mm, gk = k0 + kl, gn = n0 + mm;
            As[kl][mm] = (gm < M && gk < K) ? A[(long)gm*lda + gk] : 0.f;
            Bs[kl][mm] = (gn < N && gk < K) ? Bm[(long)gn*ldb + gk] : 0.f;
        }
        __syncthreads();
#pragma unroll
        for (int kk = 0; kk < 16; kk++) {
            float a[4], bb[4];
#pragma unroll
            for (int i = 0; i < 4; i++) a[i]  = As[kk][ty + 16*i];
#pragma unroll
            for (int j = 0; j < 4; j++) bb[j] = Bs[kk][tx + 16*j];
#pragma unroll
            for (int i = 0; i < 4; i++)
#pragma unroll
                for (int j = 0; j < 4; j++) acc[i][j] += a[i]*bb[j];
        }
        __syncthreads();
    }
#pragma unroll
    for (int i = 0; i < 4; i++)
#pragma unroll
        for (int j = 0; j < 4; j++) {
            int gm = m0 + ty + 16*i, gn = n0 + tx + 16*j;
            if (gm < M && gn < N) C[(long)gm*ldc + gn] = acc[i][j];
        }
}

// ---------------- elementwise / norm / rope -----------------------------------
__global__ void rmsnorm_kernel(float* __restrict__ x, const float* __restrict__ w, int L) {
    int row = blockIdx.x, tid = threadIdx.x;
    float* pr = x + (long)row * L;
    float ss = 0.f;
    for (int i = tid; i < L; i += 256) { float v = pr[i]; ss += v*v; }
    __shared__ float red[256];
    red[tid] = ss; __syncthreads();
    for (int o = 128; o > 0; o >>= 1) { if (tid < o) red[tid] += red[tid+o]; __syncthreads(); }
    float inv = rsqrtf(red[0] / (float)L + 1e-6f);
    for (int i = tid; i < L; i += 256) pr[i] = w[i] * pr[i] * inv;
}

__global__ void kvpost_kernel(const float* __restrict__ kvfull, const float* __restrict__ w,
                              const float* __restrict__ fcos, const float* __restrict__ fsin,
                              float* __restrict__ kv, float* __restrict__ kpe) {
    int row = blockIdx.x, s = row & (S_-1), tid = threadIdx.x;
    const float* src = kvfull + (long)row * 576;
    float ss = 0.f;
    for (int i = tid; i < 512; i += 256) { float v = src[i]; ss += v*v; }
    __shared__ float red[256];
    red[tid] = ss; __syncthreads();
    for (int o = 128; o > 0; o >>= 1) { if (tid < o) red[tid] += red[tid+o]; __syncthreads(); }
    float inv = rsqrtf(red[0] / 512.f + 1e-6f);
    for (int i = tid; i < 512; i += 256) kv[(long)row*512 + i] = w[i] * src[i] * inv;
    if (tid < 32) {
        float x1 = src[512 + tid], x2 = src[544 + tid];
        float c = fcos[s*32 + tid], sn = fsin[s*32 + tid];
        kpe[(long)row*64 + tid]      = x1*c - x2*sn;
        kpe[(long)row*64 + 32 + tid] = x1*sn + x2*c;
    }
}

// split kv||kpe into bf16 hi/lo global arrays
__global__ void kvsplit_kernel(const float* __restrict__ kv, const float* __restrict__ kpe,
                               __nv_bfloat16* __restrict__ khi, __nv_bfloat16* __restrict__ klo) {
    int idx = blockIdx.x*256 + threadIdx.x;
    if (idx >= BS_*576) return;
    int r = idx / 576, d = idx - r*576;
    float v = (d < 512) ? kv[(long)r*512 + d] : kpe[(long)r*64 + d - 512];
    __nv_bfloat16 hi = __float2bfloat16_rn(v);
    khi[idx] = hi;
    klo[idx] = __float2bfloat16_rn(v - __bfloat162float(hi));
}

__global__ void kipost_kernel(float* __restrict__ ki, const float* __restrict__ w,
                              const float* __restrict__ bvec,
                              const float* __restrict__ fcos, const float* __restrict__ fsin) {
    int row = blockIdx.x, s = row & (S_-1), tid = threadIdx.x; // 128 threads
    float* pr = ki + (long)row * 128;
    float v = pr[tid];
    __shared__ float red[128];
    red[tid] = v; __syncthreads();
    for (int o = 64; o > 0; o >>= 1) { if (tid < o) red[tid] += red[tid+o]; __syncthreads(); }
    float mean = red[0] / 128.f;
    __syncthreads();
    float d = v - mean;
    red[tid] = d*d; __syncthreads();
    for (int o = 64; o > 0; o >>= 1) { if (tid < o) red[tid] += red[tid+o]; __syncthreads(); }
    float var = red[0] / 128.f;
    __syncthreads();
    float y = d * rsqrtf(var + 1e-6f) * w[tid] + bvec[tid];
    __shared__ float yb[128];
    yb[tid] = y; __syncthreads();
    float outv;
    if (tid < 32) {
        float c = fcos[s*32 + tid], sn = fsin[s*32 + tid];
        outv = yb[tid]*c - yb[tid+32]*sn;
    } else if (tid < 64) {
        int i = tid - 32;
        float c = fcos[s*32 + i], sn = fsin[s*32 + i];
        outv = yb[i]*sn + yb[tid]*c;
    } else {
        outv = y;
    }
    pr[tid] = outv;
}

__global__ void rope_q_kernel(float* __restrict__ q, const float* __restrict__ fcos,
                              const float* __restrict__ fsin) {
    int idx = blockIdx.x * blockDim.x + threadIdx.x;
    if (idx >= BS_*16*32) return;
    int i = idx & 31, h = (idx >> 5) & 15, bs = idx >> 9;
    int s = bs & (S_-1);
    long base = (long)bs*3072 + h*192 + 128;
    float x1 = q[base + i], x2 = q[base + 32 + i];
    float c = fcos[s*32 + i], sn = fsin[s*32 + i];
    q[base + i]      = x1*c - x2*sn;
    q[base + 32 + i] = x1*sn + x2*c;
}

__global__ void rope_qi_kernel(float* __restrict__ qi, const float* __restrict__ fcos,
                               const float* __restrict__ fsin) {
    int idx = blockIdx.x * blockDim.x + threadIdx.x;
    if (idx >= BS_*16*32) return;
    int i = idx & 31, h = (idx >> 5) & 15, bs = idx >> 9;
    int s = bs & (S_-1);
    long base = (long)bs*2048 + h*128;
    float x1 = qi[base + i], x2 = qi[base + 32 + i];
    float c = fcos[s*32 + i], sn = fsin[s*32 + i];
    qi[base + i]      = x1*c - x2*sn;
    qi[base + 32 + i] = x1*sn + x2*c;
}

// ---------------- indexer score ------------------------------------------------
__global__ void iscore_kernel(const float* __restrict__ qi, const float* __restrict__ ki,
                              const float* __restrict__ wts, const float* __restrict__ mask,
                              float* __restrict__ iscore) {
    int b = blockIdx.z;
    int s0 = blockIdx.y * 64, t0 = blockIdx.x * 64;
    int tid = threadIdx.x;
    if (t0 > s0 + 63) {
        for (int i = tid; i < 64*64; i += 256) {
            int m = i >> 6, n = i & 63;
            int s = s0 + m, t = t0 + n;
            iscore[((long)b*S_ + s)*S_ + t] = mask[(long)s*S_ + t];
        }
        return;
    }
    int tx = tid & 15, ty = tid >> 4;
    int kl = tid & 15, ml = tid >> 4;
    __shared__ float qs[16][65];
    __shared__ float ks[16][65];
    __shared__ float ws_s[16][64];
    const float IW_SCALE = rsqrtf(2048.0f);
    for (int i = tid; i < 16*64; i += 256) {
        int m = i >> 4, h = i & 15;
        ws_s[h][m] = wts[((long)(b*S_ + s0 + m))*16 + h] * IW_SCALE;
    }
    float acc[4][4];
#pragma unroll
    for (int i = 0; i < 4; i++)
#pragma unroll
        for (int j = 0; j < 4; j++) acc[i][j] = 0.f;
    __syncthreads();

    for (int h = 0; h < 16; h++) {
        float dot[4][4];
#pragma unroll
        for (int i = 0; i < 4; i++)
#pragma unroll
            for (int j = 0; j < 4; j++) dot[i][j] = 0.f;
        for (int d0 = 0; d0 < 128; d0 += 16) {
#pragma unroll
            for (int r = 0; r < 4; r++) {
                int mm = ml + 16*r;
                qs[kl][mm] = qi[((long)(b*S_ + s0 + mm))*2048 + h*128 + d0 + kl];
                ks[kl][mm] = ki[((long)(b*S_ + t0 + mm))*128 + d0 + kl];
            }
            __syncthreads();
#pragma unroll
            for (int kk = 0; kk < 16; kk++) {
                float a[4], bb[4];
#pragma unroll
                for (int i = 0; i < 4; i++) a[i]  = qs[kk][ty + 16*i];
#pragma unroll
                for (int j = 0; j < 4; j++) bb[j] = ks[kk][tx + 16*j];
#pragma unroll
                for (int i = 0; i < 4; i++)
#pragma unroll
                    for (int j = 0; j < 4; j++) dot[i][j] += a[i]*bb[j];
            }
            __syncthreads();
        }
#pragma unroll
        for (int i = 0; i < 4; i++) {
            float w = ws_s[h][ty + 16*i];
#pragma unroll
            for (int j = 0; j < 4; j++) acc[i][j] += fmaxf(dot[i][j], 0.f) * w;
        }
    }
#pragma unroll
    for (int i = 0; i < 4; i++)
#pragma unroll
        for (int j = 0; j < 4; j++) {
            int s = s0 + ty + 16*i, t = t0 + tx + 16*j;
            iscore[((long)b*S_ + s)*S_ + t] = acc[i][j] + mask[(long)s*S_ + t];
        }
}

// ---------------- exact top-512 per row (radix select, deterministic) ---------
__global__ void topk_kernel(const float* __restrict__ iscore, int* __restrict__ out) {
    int row = blockIdx.x;
    const float* p = iscore + (long)row * S_;
    int tid = threadIdx.x; // 256
    __shared__ unsigned int hist[256];
    __shared__ unsigned int s_prefix;
    __shared__ int s_rem;
    __shared__ int sgt[257], seq[257];
    if (tid == 0) { s_prefix = 0u; s_rem = ITOPK_; }
    __syncthreads();
    for (int pass = 0; pass < 4; pass++) {
        hist[tid] = 0u;
        __syncthreads();
        int shift = 24 - 8*pass;
        unsigned int pref = s_prefix;
        for (int e = 0; e < 8; e++) {
            int j = tid*8 + e;
            unsigned int u = __float_as_uint(p[j]);
            unsigned int k = (u & 0x80000000u) ? ~u : (u | 0x80000000u);
            bool ok = (pass == 0) || (((k ^ pref) >> (shift + 8)) == 0u);
            if (ok) atomicAdd(&hist[(k >> shift) & 255u], 1u);
        }
        __syncthreads();
        if (tid == 0) {
            int rem = s_rem;
            unsigned int cum = 0; int bin = 0;
            for (int bb = 255; bb >= 0; bb--) {
                if (cum + hist[bb] >= (unsigned)rem) { bin = bb; break; }
                cum += hist[bb];
            }
            s_rem = rem - (int)cum;
            s_prefix = s_prefix | ((unsigned)bin << shift);
        }
        __syncthreads();
    }
    unsigned int kth = s_prefix;
    int cgt = 0, ceq = 0;
    for (int e = 0; e < 8; e++) {
        int j = tid*8 + e;
        unsigned int u = __float_as_uint(p[j]);
        unsigned int k = (u & 0x80000000u) ? ~u : (u | 0x80000000u);
        cgt += (k > kth); ceq += (k == kth);
    }
    sgt[tid] = cgt; seq[tid] = ceq;
    __syncthreads();
    if (tid == 0) {
        int ag = 0, ae = 0;
        for (int i = 0; i < 256; i++) {
            int tg = sgt[i], te = seq[i];
            sgt[i] = ag; seq[i] = ae;
            ag += tg; ae += te;
        }
        sgt[256] = ag;
    }
    __syncthreads();
    int total_gt = sgt[256];
    int pgt = sgt[tid];
    int peq = total_gt + seq[tid];
    int* o = out + (long)row * ITOPK_;
    for (int e = 0; e < 8; e++) {
        int j = tid*8 + e;
        unsigned int u = __float_as_uint(p[j]);
        unsigned int k = (u & 0x80000000u) ? ~u : (u | 0x80000000u);
        if (k > kth) { o[pgt++] = j; }
        else if (k == kth) { if (peq < ITOPK_) o[peq] = j; peq++; }
    }
}

// ---------------- fused flash-style tensor-core sparse attention ---------------
#define AT_SMEM 197632
#define AT_BUF0 48128
#define AT_BUFSZ 74752
#define AT_LO 37376

__device__ __forceinline__ void at_gather(const __nv_bfloat16* __restrict__ khi,
                                          const __nv_bfloat16* __restrict__ klo,
                                          long kb, const int* tl, int c,
                                          uint32_t bufaddr, int tid) {
    int jloc = tid >> 3, sg0 = tid & 7;
    int t = tl[c*32 + jloc];
    const char* sh = (const char*)(khi + kb + (long)t*576);
    const char* sl = (const char*)(klo + kb + (long)t*576);
    uint32_t dh = bufaddr + jloc*1168;
#pragma unroll
    for (int u = 0; u < 9; u++) {
        int off = (sg0 + u*8) * 16;
        CP_ASYNC16(dh + off, sh + off);
        CP_ASYNC16(dh + AT_LO + off, sl + off);
    }
    CP_COMMIT();
}

__global__ void __launch_bounds__(256, 1)
attn_tc(const float* __restrict__ qabs, const float* __restrict__ qfull,
        const __nv_bfloat16* __restrict__ khi, const __nv_bfloat16* __restrict__ klo,
        const int* __restrict__ topk, float* __restrict__ omid) {
    extern __shared__ char sm[];
    uint32_t sb = smem_u32(sm);
    int* tl = (int*)sm;
    float* m_s  = (float*)(sm + 2048);
    float* l_s  = (float*)(sm + 2112);
    float* al_s = (float*)(sm + 2176);
    float* sc   = (float*)(sm + 2304);       // [2][16][34]
    __nv_bfloat16* qh = (__nv_bfloat16*)(sm + 8192);
    __nv_bfloat16* ql = (__nv_bfloat16*)(sm + 26880);
    __nv_bfloat16* ph = (__nv_bfloat16*)(sm + 45568);
    __nv_bfloat16* pl = (__nv_bfloat16*)(sm + 46848);
    int bs = blockIdx.x, b = bs >> 11, s = bs & (S_-1);
    int tid = threadIdx.x, lane = tid & 31, w = tid >> 5;
    const long kb = (long)b * 2048 * 576;

    for (int j = tid; j < 512; j += 256) tl[j] = topk[(long)bs*512 + j];
    if (tid < 16) { m_s[tid] = -1e30f; l_s[tid] = 0.f; }
    const float scale = 0.07216878364870322f;  // 1/sqrt(192)
    __syncthreads();
    for (int i = tid; i < 16*576; i += 256) {
        int h = i / 576, d = i - h*576;
        float v = (d < 512) ? qabs[(long)bs*8192 + h*512 + d]
                            : qfull[(long)bs*3072 + h*192 + 128 + (d - 512)];
        v *= scale;
        __nv_bfloat16 hi = __float2bfloat16_rn(v);
        qh[h*584 + d] = hi;
        ql[h*584 + d] = __float2bfloat16_rn(v - __bfloat162float(hi));
    }
    at_gather(khi, klo, kb, tl, 0, sb + AT_BUF0, tid);
    __syncthreads();

    float oacc[8][4];
#pragma unroll
    for (int nt = 0; nt < 8; nt++)
#pragma unroll
        for (int r = 0; r < 4; r++) oacc[nt][r] = 0.f;

    int kh = w >> 2, nt4 = w & 3;
    int arow = lane & 15, ac = (lane >> 4) * 8;
    int brow = nt4*8 + (lane & 7), bc = ((lane >> 3) & 1) * 8;

    for (int c = 0; c < 16; c++) {
        uint32_t buf = sb + AT_BUF0 + (c & 1)*AT_BUFSZ;
        if (c < 15) {
            at_gather(khi, klo, kb, tl, c+1, sb + AT_BUF0 + ((c+1)&1)*AT_BUFSZ, tid);
            CP_WAIT(1);
        } else {
            CP_WAIT(0);
        }
        __syncthreads();

        float qk[4] = {0.f, 0.f, 0.f, 0.f};
#pragma unroll
        for (int ks = 0; ks < 18; ks++) {
            int d = kh*288 + ks*16;
            uint32_t ah[4], alr[4], bh[2], bl[2];
            uint32_t ad = sb + 8192 + (arow*584 + d + ac)*2;
            LDSM_X4(ah, ad);
            LDSM_X4(alr, ad + 18688);
            uint32_t bd = buf + (brow*584 + d + bc)*2;
            LDSM_X2(bh, bd);
            LDSM_X2(bl, bd + AT_LO);
            mma16816(qk, ah, bh);
            mma16816(qk, ah, bl);
            mma16816(qk, alr, bh);
        }
        {
            int m_ = lane >> 2, e0 = 2*(lane & 3);
            float* scr = sc + kh*544;
            scr[m_*34 + nt4*8 + e0]       = qk[0];
            scr[m_*34 + nt4*8 + e0 + 1]   = qk[1];
            scr[(m_+8)*34 + nt4*8 + e0]   = qk[2];
            scr[(m_+8)*34 + nt4*8 + e0+1] = qk[3];
        }
        __syncthreads();

        {
            int t = tl[c*32 + lane];
            bool valid = (t <= s);
#pragma unroll
            for (int hi2 = 0; hi2 < 2; hi2++) {
                int hh = w*2 + hi2;
                float v = sc[hh*34 + lane] + sc[544 + hh*34 + lane];
                float val = valid ? v : -1e30f;
                float mc = val;
#pragma unroll
                for (int o = 16; o > 0; o >>= 1) mc = fmaxf(mc, __shfl_xor_sync(0xffffffffu, mc, o));
                float m_old = m_s[hh];
                float m_new = fmaxf(m_old, mc);
                float a = expf(m_old - m_new);
                float p = valid ? expf(val - m_new) : 0.f;
                float psum = p;
#pragma unroll
                for (int o = 16; o > 0; o >>= 1) psum += __shfl_xor_sync(0xffffffffu, psum, o);
                if (lane == 0) { m_s[hh] = m_new; l_s[hh] = l_s[hh]*a + psum; al_s[hh] = a; }
                __nv_bfloat16 phi = __float2bfloat16_rn(p);
                ph[hh*40 + lane] = phi;
                pl[hh*40 + lane] = __float2bfloat16_rn(p - __bfloat162float(phi));
            }
        }
        __syncthreads();

        {
            float a0 = al_s[lane >> 2], a1 = al_s[(lane >> 2) + 8];
#pragma unroll
            for (int nt = 0; nt < 8; nt++) {
                oacc[nt][0] *= a0; oacc[nt][1] *= a0;
                oacc[nt][2] *= a1; oacc[nt][3] *= a1;
            }
            uint32_t ph4[2][4], pl4[2][4];
#pragma unroll
            for (int ks = 0; ks < 2; ks++) {
                uint32_t ad = sb + 45568 + (arow*40 + ks*16 + ac)*2;
                LDSM_X4(ph4[ks], ad);
                LDSM_X4(pl4[ks], ad + 1280);
            }
#pragma unroll
            for (int nt = 0; nt < 8; nt++) {
                int n0 = w*64 + nt*8;
#pragma unroll
                for (int ks = 0; ks < 2; ks++) {
                    uint32_t bd = buf + ((ks*16 + (lane & 15))*584 + n0)*2;
                    uint32_t vh[2], vl[2];
                    LDSM_X2T(vh, bd);
                    LDSM_X2T(vl, bd + AT_LO);
                    mma16816(oacc[nt], ph4[ks], vh);
                    mma16816(oacc[nt], ph4[ks], vl);
                    mma16816(oacc[nt], pl4[ks], vh);
                }
            }
        }
        __syncthreads();
    }

    {
        int m_ = lane >> 2, e0 = 2*(lane & 3);
        float li0 = 1.f / l_s[m_];
        float li1 = 1.f / l_s[m_ + 8];
#pragma unroll
        for (int nt = 0; nt < 8; nt++) {
            int c0 = w*64 + nt*8 + e0;
            *(float2*)(omid + (long)bs*8192 + m_*512 + c0)     = make_float2(oacc[nt][0]*li0, oacc[nt][1]*li0);
            *(float2*)(omid + (long)bs*8192 + (m_+8)*512 + c0) = make_float2(oacc[nt][2]*li1, oacc[nt][3]*li1);
        }
    }
}

// ---------------- host orchestration (3-stream fork/join DAG) ------------------
extern "C" void kernel_launch(void* const* d_in, const int* in_sizes, int n_in,
                              void* d_out, int out_size) {
    const float* x      = (const float*)d_in[0];
    const float* fcos   = (const float*)d_in[1];
    const float* fsin   = (const float*)d_in[2];
    const float* mask   = (const float*)d_in[3];
    const float* wq_a   = (const float*)d_in[4];
    const float* qnw    = (const float*)d_in[5];
    const float* wq_b   = (const float*)d_in[6];
    const float* wkv_a  = (const float*)d_in[7];
    const float* kvnw   = (const float*)d_in[8];
    const float* wkv_b  = (const float*)d_in[9];
    const float* wo     = (const float*)d_in[10];
    const float* iwqb   = (const float*)d_in[11];
    const float* iwk    = (const float*)d_in[12];
    const float* iknw   = (const float*)d_in[13];
    const float* iknb   = (const float*)d_in[14];
    const float* iwp    = (const float*)d_in[15];
    float* out = (float*)d_out;

    float *qr, *q, *kvfull, *kv, *kpe, *qabs, *qi, *ki, *wts, *iscore, *omid, *o2, *wt;
    __nv_bfloat16 *khi, *klo;
    int* topkb;
    cudaGetSymbolAddress((void**)&qr,     g_qr);
    cudaGetSymbolAddress((void**)&q,      g_q);
    cudaGetSymbolAddress((void**)&kvfull, g_kvfull);
    cudaGetSymbolAddress((void**)&kv,     g_kv);
    cudaGetSymbolAddress((void**)&kpe,    g_kpe);
    cudaGetSymbolAddress((void**)&qabs,   g_qabs);
    cudaGetSymbolAddress((void**)&qi,     g_qi);
    cudaGetSymbolAddress((void**)&ki,     g_ki);
    cudaGetSymbolAddress((void**)&wts,    g_wts);
    cudaGetSymbolAddress((void**)&iscore, g_iscore);
    cudaGetSymbolAddress((void**)&topkb,  g_topk);
    cudaGetSymbolAddress((void**)&omid,   g_omid);
    cudaGetSymbolAddress((void**)&o2,     g_o2);
    cudaGetSymbolAddress((void**)&wt,     g_wkvbT);
    cudaGetSymbolAddress((void**)&khi,    g_khi);
    cudaGetSymbolAddress((void**)&klo,    g_klo);

    cudaFuncSetAttribute(gemm_mma, cudaFuncAttributeMaxDynamicSharedMemorySize, GM_SMEM);
    cudaFuncSetAttribute(attn_tc,  cudaFuncAttributeMaxDynamicSharedMemorySize, AT_SMEM);

    // lazily-created side streams + events (created OUTSIDE capture: first call
    // is the correctness run; the capture call reuses them). Work per call is
    // identical — creation is infra, not work.
    static cudaStream_t s1 = 0, s2 = 0;
    static cudaEvent_t eF = 0, eQR = 0, eWT = 0, eJ1 = 0;
    if (s1 == 0) {
        cudaStreamCreateWithFlags(&s1, cudaStreamNonBlocking);
        cudaStreamCreateWithFlags(&s2, cudaStreamNonBlocking);
        cudaEventCreateWithFlags(&eF,  cudaEventDisableTiming);
        cudaEventCreateWithFlags(&eQR, cudaEventDisableTiming);
        cudaEventCreateWithFlags(&eWT, cudaEventDisableTiming);
        cudaEventCreateWithFlags(&eJ1, cudaEventDisableTiming);
    }
    cudaStream_t s0 = 0;  // legacy default (capture origin)

    // fork
    cudaEventRecord(eF, s0);
    cudaStreamWaitEvent(s1, eF, 0);
    cudaStreamWaitEvent(s2, eF, 0);

    // ---- s0: qr chain -> q chain -> attention -> output
    gemm_bt<<<dim3(12, 64, 1), 256, 0, s0>>>(x, 2048, 0, wq_a, 2048, 0, qr, 768, 0, 4096, 768, 2048);
    rmsnorm_kernel<<<4096, 256, 0, s0>>>(qr, qnw, 768);
    cudaEventRecord(eQR, s0);

    // ---- s2: kv path + weight transpose (independent of qr)
    gemm_mma<<<dim3(5, 32, 1), 256, GM_SMEM, s2>>>(x, 2048, 0, wkv_a, 2048, 0, kvfull, 576, 0, 4096, 576, 2048);
    kvpost_kernel<<<4096, 256, 0, s2>>>(kvfull, kvnw, fcos, fsin, kv, kpe);
    kvsplit_kernel<<<(BS_*576 + 255)/256, 256, 0, s2>>>(kv, kpe, khi, klo);
    transpose_wkvb<<<(16*128*512 + 255)/256, 256, 0, s2>>>(wkv_b, wt);
    cudaEventRecord(eWT, s2);

    // ---- s1: indexer path (ki/wts first, then qi after qr)
    gemm_bt<<<dim3(2, 64, 1), 256, 0, s1>>>(x, 2048, 0, iwk, 2048, 0, ki, 128, 0, 4096, 128, 2048);
    kipost_kernel<<<4096, 128, 0, s1>>>(ki, iknw, iknb, fcos, fsin);
    gemm_bt<<<dim3(1, 64, 1), 256, 0, s1>>>(x, 2048, 0, iwp, 2048, 0, wts, 16, 0, 4096, 16, 2048);
    cudaStreamWaitEvent(s1, eQR, 0);
    gemm_bt<<<dim3(32, 64, 1), 256, 0, s1>>>(qr, 768, 0, iwqb, 768, 0, qi, 2048, 0, 4096, 2048, 768);
    rope_qi_kernel<<<(BS_*16*32 + 255)/256, 256, 0, s1>>>(qi, fcos, fsin);
    iscore_kernel<<<dim3(32, 32, 2), 256, 0, s1>>>(qi, ki, wts, mask, iscore);
    topk_kernel<<<4096, 256, 0, s1>>>(iscore, topkb);
    cudaEventRecord(eJ1, s1);

    // ---- s0 continues: q = qr @ wq_b^T, rope, q_abs
    gemm_mma<<<dim3(24, 32, 1), 256, GM_SMEM, s0>>>(qr, 768, 0, wq_b, 768, 0, q, 3072, 0, 4096, 3072, 768);
    rope_q_kernel<<<(BS_*16*32 + 255)/256, 256, 0, s0>>>(q, fcos, fsin);
    cudaStreamWaitEvent(s0, eWT, 0);   // joins s2 (wt + khi/klo ready)
    gemm_mma<<<dim3(4, 32, 16), 256, GM_SMEM, s0>>>(q, 3072, 192, wt, 128, 65536, qabs, 8192, 512,
                                                    4096, 512, 128);
    cudaStreamWaitEvent(s0, eJ1, 0);   // joins s1 (topk ready)
    attn_tc<<<4096, 256, AT_SMEM, s0>>>(qabs, q, khi, klo, topkb, omid);
    gemm_mma<<<dim3(1, 32, 16), 256, GM_SMEM, s0>>>(omid, 8192, 512, wkv_b + 128*512, 512, 256*512,
                                                    o2, 2048, 128, 4096, 128, 512);
    gemm_mma<<<dim3(16, 32, 1), 256, GM_SMEM, s0>>>(o2, 2048, 0, wo, 2048, 0, out, 2048, 0, 4096, 2048, 2048);
}

// round 7
// speedup vs baseline: 1.8816x; 1.0929x over previous
#include <cuda_runtime.h>
#include <cuda_bf16.h>
#include <math.h>
#include <stdint.h>

// Problem constants
#define B_    2
#define S_    2048
#define DIM_  2048
#define NH_   16
#define QLR_  768
#define KVLR_ 512
#define NOPE_ 128
#define ROPE_ 64
#define VDIM_ 128
#define IH_   16
#define IHD_  128
#define ITOPK_ 512
#define BS_   (B_*S_)   // 4096

// ---------------- scratch (device globals; no allocation allowed) -------------
__device__ float g_qr[BS_*QLR_];
__device__ float g_q[BS_*NH_*(NOPE_+ROPE_)];
__device__ float g_kvfull[BS_*(KVLR_+ROPE_)];
__device__ float g_kv[BS_*KVLR_];
__device__ float g_kpe[BS_*ROPE_];
__device__ float g_qabs[BS_*NH_*KVLR_];
__device__ float g_qi[BS_*IH_*IHD_];
__device__ float g_ki[BS_*IHD_];
__device__ float g_wts[BS_*IH_];
__device__ float g_iscore[B_*S_*S_];
__device__ int   g_topk[BS_*ITOPK_];
__device__ float g_omid[BS_*NH_*KVLR_];
__device__ float g_o2[BS_*NH_*VDIM_];
__device__ float g_wkvbT[16*512*128];            // transposed wkv_b[:, :128, :] -> [h][c][d]
__device__ __nv_bfloat16 g_khi[BS_*576];         // kv||kpe hi split
__device__ __nv_bfloat16 g_klo[BS_*576];         // kv||kpe lo split

// =================== helpers ==================================================
__device__ __forceinline__ uint32_t smem_u32(const void* p) {
    uint32_t a;
    asm("{ .reg .u64 t; cvta.to.shared.u64 t, %1; cvt.u32.u64 %0, t; }" : "=r"(a) : "l"(p));
    return a;
}
__device__ __forceinline__ uint32_t pack_hi(float x, float y) {
    __nv_bfloat162 p;
    p.x = __float2bfloat16_rn(x);
    p.y = __float2bfloat16_rn(y);
    return *(uint32_t*)&p;
}
__device__ __forceinline__ uint32_t pack_lo(float x, float y) {
    __nv_bfloat16 hx = __float2bfloat16_rn(x);
    __nv_bfloat16 hy = __float2bfloat16_rn(y);
    __nv_bfloat162 p;
    p.x = __float2bfloat16_rn(x - __bfloat162float(hx));
    p.y = __float2bfloat16_rn(y - __bfloat162float(hy));
    return *(uint32_t*)&p;
}
__device__ __forceinline__ void mma16816(float* c, const uint32_t* a, const uint32_t* b) {
    asm volatile("mma.sync.aligned.m16n8k16.row.col.f32.bf16.bf16.f32 "
        "{%0,%1,%2,%3}, {%4,%5,%6,%7}, {%8,%9}, {%0,%1,%2,%3};"
        : "+f"(c[0]), "+f"(c[1]), "+f"(c[2]), "+f"(c[3])
        : "r"(a[0]), "r"(a[1]), "r"(a[2]), "r"(a[3]), "r"(b[0]), "r"(b[1]));
}
#define LDSM_X4(r, a) asm volatile("ldmatrix.sync.aligned.m8n8.x4.shared.b16 {%0,%1,%2,%3}, [%4];" \
    : "=r"((r)[0]),"=r"((r)[1]),"=r"((r)[2]),"=r"((r)[3]) : "r"(a))
#define LDSM_X2(r, a) asm volatile("ldmatrix.sync.aligned.m8n8.x2.shared.b16 {%0,%1}, [%2];" \
    : "=r"((r)[0]),"=r"((r)[1]) : "r"(a))
#define LDSM_X2T(r, a) asm volatile("ldmatrix.sync.aligned.m8n8.x2.trans.shared.b16 {%0,%1}, [%2];" \
    : "=r"((r)[0]),"=r"((r)[1]) : "r"(a))
#define CP_ASYNC16(dst, src) asm volatile("cp.async.cg.shared.global [%0], [%1], 16;" :: "r"(dst), "l"(src))
#define CP_COMMIT() asm volatile("cp.async.commit_group;" ::: "memory")
#define CP_WAIT(n)  asm volatile("cp.async.wait_group %0;" :: "n"(n) : "memory")

// word-granularity swizzled smem address for gemm_mma tiles (128 rows x 16 words)
__device__ __forceinline__ int sw_addr(int row, int w) {
    return row*16 + (w ^ ((((row)>>1)&3)<<2));
}

// =================== tensor-core GEMM (bf16x3): C[M,N]=A[M,K]@B[N,K]^T ========
#define GM_SMEM 65536

__global__ void __launch_bounds__(256, 1)
gemm_mma(const float* __restrict__ A, int lda, long aZ,
         const float* __restrict__ Bm, int ldb, long bZ,
         float* __restrict__ C, int ldc, long cZ,
         int M, int N, int K) {
    extern __shared__ uint32_t smw[];
    A  += (long)blockIdx.z * aZ;
    Bm += (long)blockIdx.z * bZ;
    C  += (long)blockIdx.z * cZ;
    int m0 = blockIdx.y * 128, n0 = blockIdx.x * 128;
    int tid = threadIdx.x, lane = tid & 31, wid = tid >> 5;
    int wm = wid >> 2, wn = wid & 3;
    int g = lane >> 2, tig = lane & 3;

    float acc[4][4][4];
#pragma unroll
    for (int i = 0; i < 4; i++)
#pragma unroll
        for (int j = 0; j < 4; j++)
#pragma unroll
            for (int r = 0; r < 4; r++) acc[i][j][r] = 0.f;

    int arow = tid >> 1, acol = (tid & 1) * 16;
    int nch = K >> 5;

    float4 ra[4], rb[4];
    {
        const float* ap = A + (long)(m0 + arow)*lda + acol;
        bool aok = (m0 + arow) < M;
#pragma unroll
        for (int i = 0; i < 4; i++)
            ra[i] = aok ? *(const float4*)(ap + i*4) : make_float4(0.f,0.f,0.f,0.f);
        const float* bp = Bm + (long)(n0 + arow)*ldb + acol;
        bool bok = (n0 + arow) < N;
#pragma unroll
        for (int i = 0; i < 4; i++)
            rb[i] = bok ? *(const float4*)(bp + i*4) : make_float4(0.f,0.f,0.f,0.f);
    }

    for (int it = 0; it < nch; it++) {
        int stg = it & 1;
        uint32_t* sAhi = smw + stg*8192;
        uint32_t* sAlo = sAhi + 2048;
        uint32_t* sBhi = sAhi + 4096;
        uint32_t* sBlo = sAhi + 6144;
        {
            uint32_t hw[8], lw[8];
#pragma unroll
            for (int i = 0; i < 4; i++) {
                hw[i*2]   = pack_hi(ra[i].x, ra[i].y);
                hw[i*2+1] = pack_hi(ra[i].z, ra[i].w);
                lw[i*2]   = pack_lo(ra[i].x, ra[i].y);
                lw[i*2+1] = pack_lo(ra[i].z, ra[i].w);
            }
            int g0 = (((tid&1)*2 + 0) ^ ((arow>>1)&3)) * 4;
            int g1 = (((tid&1)*2 + 1) ^ ((arow>>1)&3)) * 4;
            uint32_t* dst = sAhi + arow*16;
            *(uint4*)(dst + g0) = make_uint4(hw[0],hw[1],hw[2],hw[3]);
            *(uint4*)(dst + g1) = make_uint4(hw[4],hw[5],hw[6],hw[7]);
            dst = sAlo + arow*16;
            *(uint4*)(dst + g0) = make_uint4(lw[0],lw[1],lw[2],lw[3]);
            *(uint4*)(dst + g1) = make_uint4(lw[4],lw[5],lw[6],lw[7]);
#pragma unroll
            for (int i = 0; i < 4; i++) {
                hw[i*2]   = pack_hi(rb[i].x, rb[i].y);
                hw[i*2+1] = pack_hi(rb[i].z, rb[i].w);
                lw[i*2]   = pack_lo(rb[i].x, rb[i].y);
                lw[i*2+1] = pack_lo(rb[i].z, rb[i].w);
            }
            dst = sBhi + arow*16;
            *(uint4*)(dst + g0) = make_uint4(hw[0],hw[1],hw[2],hw[3]);
            *(uint4*)(dst + g1) = make_uint4(hw[4],hw[5],hw[6],hw[7]);
            dst = sBlo + arow*16;
            *(uint4*)(dst + g0) = make_uint4(lw[0],lw[1],lw[2],lw[3]);
            *(uint4*)(dst + g1) = make_uint4(lw[4],lw[5],lw[6],lw[7]);
        }
        __syncthreads();
        if (it + 1 < nch) {
            int gk = (it + 1) << 5;
            const float* ap = A + (long)(m0 + arow)*lda + gk + acol;
            bool aok = (m0 + arow) < M;
#pragma unroll
            for (int i = 0; i < 4; i++)
                ra[i] = aok ? *(const float4*)(ap + i*4) : make_float4(0.f,0.f,0.f,0.f);
            const float* bp = Bm + (long)(n0 + arow)*ldb + gk + acol;
            bool bok = (n0 + arow) < N;
#pragma unroll
            for (int i = 0; i < 4; i++)
                rb[i] = bok ? *(const float4*)(bp + i*4) : make_float4(0.f,0.f,0.f,0.f);
        }
#pragma unroll
        for (int ks = 0; ks < 2; ks++) {
            uint32_t bh[4][2], bl[4][2];
#pragma unroll
            for (int nt = 0; nt < 4; nt++) {
                int nrow = wn*32 + nt*8 + g;
                int w0 = ks*8 + tig;
                bh[nt][0] = sBhi[sw_addr(nrow, w0)];
                bh[nt][1] = sBhi[sw_addr(nrow, w0+4)];
                bl[nt][0] = sBlo[sw_addr(nrow, w0)];
                bl[nt][1] = sBlo[sw_addr(nrow, w0+4)];
            }
#pragma unroll
            for (int mt = 0; mt < 4; mt++) {
                int ar = wm*64 + mt*16 + g;
                int w0 = ks*8 + tig;
                uint32_t ah[4], al[4];
                ah[0] = sAhi[sw_addr(ar,   w0)];
                ah[1] = sAhi[sw_addr(ar+8, w0)];
                ah[2] = sAhi[sw_addr(ar,   w0+4)];
                ah[3] = sAhi[sw_addr(ar+8, w0+4)];
                al[0] = sAlo[sw_addr(ar,   w0)];
                al[1] = sAlo[sw_addr(ar+8, w0)];
                al[2] = sAlo[sw_addr(ar,   w0+4)];
                al[3] = sAlo[sw_addr(ar+8, w0+4)];
#pragma unroll
                for (int nt = 0; nt < 4; nt++) {
                    mma16816(acc[mt][nt], ah, bh[nt]);
                    mma16816(acc[mt][nt], ah, bl[nt]);
                    mma16816(acc[mt][nt], al, bh[nt]);
                }
            }
        }
        __syncthreads();
    }
#pragma unroll
    for (int mt = 0; mt < 4; mt++) {
#pragma unroll
        for (int nt = 0; nt < 4; nt++) {
            int r0 = m0 + wm*64 + mt*16 + g;
            int c0 = n0 + wn*32 + nt*8 + tig*2;
            if (c0 < N) {
                if (r0 < M)
                    *(float2*)(C + (long)r0*ldc + c0) = make_float2(acc[mt][nt][0], acc[mt][nt][1]);
                if (r0 + 8 < M)
                    *(float2*)(C + (long)(r0+8)*ldc + c0) = make_float2(acc[mt][nt][2], acc[mt][nt][3]);
            }
        }
    }
}

// transpose wkv_b[:, :128, :] -> wt[h][c][d]
__global__ void transpose_wkvb(const float* __restrict__ w, float* __restrict__ wt) {
    int idx = blockIdx.x * 256 + threadIdx.x;
    if (idx >= 16*128*512) return;
    int c = idx & 511, d = (idx >> 9) & 127, h = idx >> 16;
    wt[h*65536 + c*128 + d] = w[h*131072 + d*512 + c];
}

// ---------------- fp32 GEMM (bit-exact k-order): C[M,N] = A[M,K] @ B[N,K]^T ---
// 128(M) x 64(N) tile, 256 threads, 8x4 micro-tile — FMA-bound.
__global__ void __launch_bounds__(256)
gemm_bt(const float* __restrict__ A, int lda, long aZ,
        const float* __restrict__ Bm, int ldb, long bZ,
        float* __restrict__ C, int ldc, long cZ,
        int M, int N, int K) {
    A  += (long)blockIdx.z * aZ;
    Bm += (long)blockIdx.z * bZ;
    C  += (long)blockIdx.z * cZ;
    int n0 = blockIdx.x * 64, m0 = blockIdx.y * 128;
    __shared__ float As[16][129];
    __shared__ float Bs[16][65];
    int tid = threadIdx.x;
    int tx = tid & 15, ty = tid >> 4;
    int kl = tid & 15, ml = tid >> 4;
    float acc[8][4];
#pragma unroll
    for (int i = 0; i < 8; i++)
#pragma unroll
        for (int j = 0; j < 4; j++) acc[i][j] = 0.f;

    for (int k0 = 0; k0 < K; k0 += 16) {
#pragma unroll
        for (int r = 0; r < 8; r++) {
            int mm = ml + 16*r;
            int gm = m0 + mm, gk = k0 + kl;
            As[kl][mm] = (gm < M && gk < K) ? A[(long)gm*lda + gk] : 0.f;
        }
#pragma unroll
        for (int r = 0; r < 4; r++) {
            int mm = ml + 16*r;
            int gn = n0 + mm, gk = k0 + kl;
            Bs[kl][mm] = (gn < N && gk < K) ? Bm[(long)gn*ldb + gk] : 0.f;
        }
        __syncthreads();
#pragma unroll
        for (int kk = 0; kk < 16; kk++) {
            float a[8], bb[4];
#pragma unroll
            for (int i = 0; i < 8; i++) a[i]  = As[kk][ty + 16*i];
#pragma unroll
            for (int j = 0; j < 4; j++) bb[j] = Bs[kk][tx + 16*j];
#pragma unroll
            for (int i = 0; i < 8; i++)
#pragma unroll
                for (int j = 0; j < 4; j++) acc[i][j] += a[i]*bb[j];
        }
        __syncthreads();
    }
#pragma unroll
    for (int i = 0; i < 8; i++)
#pragma unroll
        for (int j = 0; j < 4; j++) {
            int gm = m0 + ty + 16*i, gn = n0 + tx + 16*j;
            if (gm < M && gn < N) C[(long)gm*ldc + gn] = acc[i][j];
        }
}

// ---------------- elementwise / norm / rope -----------------------------------
__global__ void rmsnorm_kernel(float* __restrict__ x, const float* __restrict__ w, int L) {
    int row = blockIdx.x, tid = threadIdx.x;
    float* pr = x + (long)row * L;
    float ss = 0.f;
    for (int i = tid; i < L; i += 256) { float v = pr[i]; ss += v*v; }
    __shared__ float red[256];
    red[tid] = ss; __syncthreads();
    for (int o = 128; o > 0; o >>= 1) { if (tid < o) red[tid] += red[tid+o]; __syncthreads(); }
    float inv = rsqrtf(red[0] / (float)L + 1e-6f);
    for (int i = tid; i < L; i += 256) pr[i] = w[i] * pr[i] * inv;
}

__global__ void kvpost_kernel(const float* __restrict__ kvfull, const float* __restrict__ w,
                              const float* __restrict__ fcos, const float* __restrict__ fsin,
                              float* __restrict__ kv, float* __restrict__ kpe) {
    int row = blockIdx.x, s = row & (S_-1), tid = threadIdx.x;
    const float* src = kvfull + (long)row * 576;
    float ss = 0.f;
    for (int i = tid; i < 512; i += 256) { float v = src[i]; ss += v*v; }
    __shared__ float red[256];
    red[tid] = ss; __syncthreads();
    for (int o = 128; o > 0; o >>= 1) { if (tid < o) red[tid] += red[tid+o]; __syncthreads(); }
    float inv = rsqrtf(red[0] / 512.f + 1e-6f);
    for (int i = tid; i < 512; i += 256) kv[(long)row*512 + i] = w[i] * src[i] * inv;
    if (tid < 32) {
        float x1 = src[512 + tid], x2 = src[544 + tid];
        float c = fcos[s*32 + tid], sn = fsin[s*32 + tid];
        kpe[(long)row*64 + tid]      = x1*c - x2*sn;
        kpe[(long)row*64 + 32 + tid] = x1*sn + x2*c;
    }
}

// split kv||kpe into bf16 hi/lo global arrays
__global__ void kvsplit_kernel(const float* __restrict__ kv, const float* __restrict__ kpe,
                               __nv_bfloat16* __restrict__ khi, __nv_bfloat16* __restrict__ klo) {
    int idx = blockIdx.x*256 + threadIdx.x;
    if (idx >= BS_*576) return;
    int r = idx / 576, d = idx - r*576;
    float v = (d < 512) ? kv[(long)r*512 + d] : kpe[(long)r*64 + d - 512];
    __nv_bfloat16 hi = __float2bfloat16_rn(v);
    khi[idx] = hi;
    klo[idx] = __float2bfloat16_rn(v - __bfloat162float(hi));
}

__global__ void kipost_kernel(float* __restrict__ ki, const float* __restrict__ w,
                              const float* __restrict__ bvec,
                              const float* __restrict__ fcos, const float* __restrict__ fsin) {
    int row = blockIdx.x, s = row & (S_-1), tid = threadIdx.x; // 128 threads
    float* pr = ki + (long)row * 128;
    float v = pr[tid];
    __shared__ float red[128];
    red[tid] = v; __syncthreads();
    for (int o = 64; o > 0; o >>= 1) { if (tid < o) red[tid] += red[tid+o]; __syncthreads(); }
    float mean = red[0] / 128.f;
    __syncthreads();
    float d = v - mean;
    red[tid] = d*d; __syncthreads();
    for (int o = 64; o > 0; o >>= 1) { if (tid < o) red[tid] += red[tid+o]; __syncthreads(); }
    float var = red[0] / 128.f;
    __syncthreads();
    float y = d * rsqrtf(var + 1e-6f) * w[tid] + bvec[tid];
    __shared__ float yb[128];
    yb[tid] = y; __syncthreads();
    float outv;
    if (tid < 32) {
        float c = fcos[s*32 + tid], sn = fsin[s*32 + tid];
        outv = yb[tid]*c - yb[tid+32]*sn;
    } else if (tid < 64) {
        int i = tid - 32;
        float c = fcos[s*32 + i], sn = fsin[s*32 + i];
        outv = yb[i]*sn + yb[tid]*c;
    } else {
        outv = y;
    }
    pr[tid] = outv;
}

__global__ void rope_q_kernel(float* __restrict__ q, const float* __restrict__ fcos,
                              const float* __restrict__ fsin) {
    int idx = blockIdx.x * blockDim.x + threadIdx.x;
    if (idx >= BS_*16*32) return;
    int i = idx & 31, h = (idx >> 5) & 15, bs = idx >> 9;
    int s = bs & (S_-1);
    long base = (long)bs*3072 + h*192 + 128;
    float x1 = q[base + i], x2 = q[base + 32 + i];
    float c = fcos[s*32 + i], sn = fsin[s*32 + i];
    q[base + i]      = x1*c - x2*sn;
    q[base + 32 + i] = x1*sn + x2*c;
}

__global__ void rope_qi_kernel(float* __restrict__ qi, const float* __restrict__ fcos,
                               const float* __restrict__ fsin) {
    int idx = blockIdx.x * blockDim.x + threadIdx.x;
    if (idx >= BS_*16*32) return;
    int i = idx & 31, h = (idx >> 5) & 15, bs = idx >> 9;
    int s = bs & (S_-1);
    long base = (long)bs*2048 + h*128;
    float x1 = qi[base + i], x2 = qi[base + 32 + i];
    float c = fcos[s*32 + i], sn = fsin[s*32 + i];
    qi[base + i]      = x1*c - x2*sn;
    qi[base + 32 + i] = x1*sn + x2*c;
}

// ---------------- indexer score (128s x 64t tile, bit-exact order) -------------
__global__ void __launch_bounds__(256)
iscore_kernel(const float* __restrict__ qi, const float* __restrict__ ki,
              const float* __restrict__ wts, const float* __restrict__ mask,
              float* __restrict__ iscore) {
    int b = blockIdx.z;
    int s0 = blockIdx.y * 128, t0 = blockIdx.x * 64;
    int tid = threadIdx.x;
    if (t0 > s0 + 127) {
        for (int i = tid; i < 128*64; i += 256) {
            int m = i >> 6, n = i & 63;
            int s = s0 + m, t = t0 + n;
            iscore[((long)b*S_ + s)*S_ + t] = mask[(long)s*S_ + t];
        }
        return;
    }
    int tx = tid & 15, ty = tid >> 4;
    int kl = tid & 15, ml = tid >> 4;
    __shared__ float qs[16][129];
    __shared__ float ks[16][65];
    __shared__ float ws_s[16][128];
    const float IW_SCALE = rsqrtf(2048.0f);
    for (int i = tid; i < 16*128; i += 256) {
        int m = i >> 4, h = i & 15;
        ws_s[h][m] = wts[((long)(b*S_ + s0 + m))*16 + h] * IW_SCALE;
    }
    float acc[8][4];
#pragma unroll
    for (int i = 0; i < 8; i++)
#pragma unroll
        for (int j = 0; j < 4; j++) acc[i][j] = 0.f;
    __syncthreads();

    for (int h = 0; h < 16; h++) {
        float dot[8][4];
#pragma unroll
        for (int i = 0; i < 8; i++)
#pragma unroll
            for (int j = 0; j < 4; j++) dot[i][j] = 0.f;
        for (int d0 = 0; d0 < 128; d0 += 16) {
#pragma unroll
            for (int r = 0; r < 8; r++) {
                int mm = ml + 16*r;
                qs[kl][mm] = qi[((long)(b*S_ + s0 + mm))*2048 + h*128 + d0 + kl];
            }
#pragma unroll
            for (int r = 0; r < 4; r++) {
                int mm = ml + 16*r;
                ks[kl][mm] = ki[((long)(b*S_ + t0 + mm))*128 + d0 + kl];
            }
            __syncthreads();
#pragma unroll
            for (int kk = 0; kk < 16; kk++) {
                float a[8], bb[4];
#pragma unroll
                for (int i = 0; i < 8; i++) a[i]  = qs[kk][ty + 16*i];
#pragma unroll
                for (int j = 0; j < 4; j++) bb[j] = ks[kk][tx + 16*j];
#pragma unroll
                for (int i = 0; i < 8; i++)
#pragma unroll
                    for (int j = 0; j < 4; j++) dot[i][j] += a[i]*bb[j];
            }
            __syncthreads();
        }
#pragma unroll
        for (int i = 0; i < 8; i++) {
            float w = ws_s[h][ty + 16*i];
#pragma unroll
            for (int j = 0; j < 4; j++) acc[i][j] += fmaxf(dot[i][j], 0.f) * w;
        }
    }
#pragma unroll
    for (int i = 0; i < 8; i++)
#pragma unroll
        for (int j = 0; j < 4; j++) {
            int s = s0 + ty + 16*i, t = t0 + tx + 16*j;
            iscore[((long)b*S_ + s)*S_ + t] = acc[i][j] + mask[(long)s*S_ + t];
        }
}

// ---------------- exact top-512 per row (radix select, deterministic) ---------
__global__ void topk_kernel(const float* __restrict__ iscore, int* __restrict__ out) {
    int row = blockIdx.x;
    const float* p = iscore + (long)row * S_;
    int tid = threadIdx.x; // 256
    __shared__ unsigned int hist[256];
    __shared__ unsigned int s_prefix;
    __shared__ int s_rem;
    __shared__ int sgt[257], seq[257];
    if (tid == 0) { s_prefix = 0u; s_rem = ITOPK_; }
    __syncthreads();
    for (int pass = 0; pass < 4; pass++) {
        hist[tid] = 0u;
        __syncthreads();
        int shift = 24 - 8*pass;
        unsigned int pref = s_prefix;
        for (int e = 0; e < 8; e++) {
            int j = tid*8 + e;
            unsigned int u = __float_as_uint(p[j]);
            unsigned int k = (u & 0x80000000u) ? ~u : (u | 0x80000000u);
            bool ok = (pass == 0) || (((k ^ pref) >> (shift + 8)) == 0u);
            if (ok) atomicAdd(&hist[(k >> shift) & 255u], 1u);
        }
        __syncthreads();
        if (tid == 0) {
            int rem = s_rem;
            unsigned int cum = 0; int bin = 0;
            for (int bb = 255; bb >= 0; bb--) {
                if (cum + hist[bb] >= (unsigned)rem) { bin = bb; break; }
                cum += hist[bb];
            }
            s_rem = rem - (int)cum;
            s_prefix = s_prefix | ((unsigned)bin << shift);
        }
        __syncthreads();
    }
    unsigned int kth = s_prefix;
    int cgt = 0, ceq = 0;
    for (int e = 0; e < 8; e++) {
        int j = tid*8 + e;
        unsigned int u = __float_as_uint(p[j]);
        unsigned int k = (u & 0x80000000u) ? ~u : (u | 0x80000000u);
        cgt += (k > kth); ceq += (k == kth);
    }
    sgt[tid] = cgt; seq[tid] = ceq;
    __syncthreads();
    if (tid == 0) {
        int ag = 0, ae = 0;
        for (int i = 0; i < 256; i++) {
            int tg = sgt[i], te = seq[i];
            sgt[i] = ag; seq[i] = ae;
            ag += tg; ae += te;
        }
        sgt[256] = ag;
    }
    __syncthreads();
    int total_gt = sgt[256];
    int pgt = sgt[tid];
    int peq = total_gt + seq[tid];
    int* o = out + (long)row * ITOPK_;
    for (int e = 0; e < 8; e++) {
        int j = tid*8 + e;
        unsigned int u = __float_as_uint(p[j]);
        unsigned int k = (u & 0x80000000u) ? ~u : (u | 0x80000000u);
        if (k > kth) { o[pgt++] = j; }
        else if (k == kth) { if (peq < ITOPK_) o[peq] = j; peq++; }
    }
}

// ---------------- fused flash-style tensor-core sparse attention ---------------
// 512 threads / 16 warps. Online softmax over 16 chunks of 32 topk tokens.
// QK: k-dim split 4 ways across warps (9 ksteps each), partials reduced in smem.
// PV: each warp owns 32 output cols. Single gather per token, cp.async dbuf.
// smem layout (bytes):
//   0      tl[512]                 2048
//   2048   m_s/l_s/al_s[16]        256
//   2304   sc[4][16][34] f32       8704   -> 11008
//   11008  qh[16][584] bf16        18688  -> 29696
//   29696  ql[16][584]             18688  -> 48384
//   48384  ph[16][40]              1280   -> 49664
//   49664  pl[16][40]              1280   -> 50944
//   50944  buf{0,1}: hi[32][584]+lo[32][584] (74752 each) -> 200448
#define AT_SMEM 200448
#define AT_BUF0 50944
#define AT_BUFSZ 74752
#define AT_LO 37376

__device__ __forceinline__ void at_gather(const __nv_bfloat16* __restrict__ khi,
                                          const __nv_bfloat16* __restrict__ klo,
                                          long kb, const int* tl, int c,
                                          uint32_t bufaddr, int tid) {
    int jloc = tid >> 4, sg0 = tid & 15;   // 32 rows x 16 threads
    int t = tl[c*32 + jloc];
    const char* sh = (const char*)(khi + kb + (long)t*576);
    const char* sl = (const char*)(klo + kb + (long)t*576);
    uint32_t dh = bufaddr + jloc*1168;
#pragma unroll
    for (int u = 0; u < 9; u++) {
        int ch = sg0 + u*16;               // 0..143: 72 hi chunks then 72 lo
        if (ch < 72) CP_ASYNC16(dh + ch*16, sh + ch*16);
        else         CP_ASYNC16(dh + AT_LO + (ch-72)*16, sl + (ch-72)*16);
    }
    CP_COMMIT();
}

__global__ void __launch_bounds__(512, 1)
attn_tc(const float* __restrict__ qabs, const float* __restrict__ qfull,
        const __nv_bfloat16* __restrict__ khi, const __nv_bfloat16* __restrict__ klo,
        const int* __restrict__ topk, float* __restrict__ omid) {
    extern __shared__ char sm[];
    uint32_t sb = smem_u32(sm);
    int* tl = (int*)sm;
    float* m_s  = (float*)(sm + 2048);
    float* l_s  = (float*)(sm + 2112);
    float* al_s = (float*)(sm + 2176);
    float* sc   = (float*)(sm + 2304);       // [4][16][34]
    __nv_bfloat16* qh = (__nv_bfloat16*)(sm + 11008);
    __nv_bfloat16* ph = (__nv_bfloat16*)(sm + 48384);
    __nv_bfloat16* pl = (__nv_bfloat16*)(sm + 49664);
    int bs = blockIdx.x, b = bs >> 11, s = bs & (S_-1);
    int tid = threadIdx.x, lane = tid & 31, w = tid >> 5;
    const long kb = (long)b * 2048 * 576;

    for (int j = tid; j < 512; j += 512) tl[j] = topk[(long)bs*512 + j];
    if (tid < 16) { m_s[tid] = -1e30f; l_s[tid] = 0.f; }
    const float scale = 0.07216878364870322f;  // 1/sqrt(192)
    __syncthreads();
    for (int i = tid; i < 16*576; i += 512) {
        int h = i / 576, d = i - h*576;
        float v = (d < 512) ? qabs[(long)bs*8192 + h*512 + d]
                            : qfull[(long)bs*3072 + h*192 + 128 + (d - 512)];
        v *= scale;
        __nv_bfloat16 hi = __float2bfloat16_rn(v);
        qh[h*584 + d] = hi;
        qh[9344 + h*584 + d] = __float2bfloat16_rn(v - __bfloat162float(hi));  // ql region
    }
    at_gather(khi, klo, kb, tl, 0, sb + AT_BUF0, tid);
    __syncthreads();

    float oacc[4][4];
#pragma unroll
    for (int nt = 0; nt < 4; nt++)
#pragma unroll
        for (int r = 0; r < 4; r++) oacc[nt][r] = 0.f;

    int kh4 = w >> 2, nt4 = w & 3;
    int arow = lane & 15, ac = (lane >> 4) * 8;
    int brow = nt4*8 + (lane & 7), bc = ((lane >> 3) & 1) * 8;

    for (int c = 0; c < 16; c++) {
        uint32_t buf = sb + AT_BUF0 + (c & 1)*AT_BUFSZ;
        if (c < 15) {
            at_gather(khi, klo, kb, tl, c+1, sb + AT_BUF0 + ((c+1)&1)*AT_BUFSZ, tid);
            CP_WAIT(1);
        } else {
            CP_WAIT(0);
        }
        __syncthreads();

        // ---- QK partial: warp -> k-quarter kh4 (144 dims), token n-tile nt4
        float qk[4] = {0.f, 0.f, 0.f, 0.f};
#pragma unroll
        for (int ks = 0; ks < 9; ks++) {
            int d = kh4*144 + ks*16;
            uint32_t ah[4], alr[4], bh[2], bl[2];
            uint32_t ad = sb + 11008 + (arow*584 + d + ac)*2;
            LDSM_X4(ah, ad);
            LDSM_X4(alr, ad + 18688);
            uint32_t bd = buf + (brow*584 + d + bc)*2;
            LDSM_X2(bh, bd);
            LDSM_X2(bl, bd + AT_LO);
            mma16816(qk, ah, bh);
            mma16816(qk, ah, bl);
            mma16816(qk, alr, bh);
        }
        {
            int m_ = lane >> 2, e0 = 2*(lane & 3);
            float* scr = sc + kh4*544;
            scr[m_*34 + nt4*8 + e0]       = qk[0];
            scr[m_*34 + nt4*8 + e0 + 1]   = qk[1];
            scr[(m_+8)*34 + nt4*8 + e0]   = qk[2];
            scr[(m_+8)*34 + nt4*8 + e0+1] = qk[3];
        }
        __syncthreads();

        // ---- online softmax: warp w handles head w; lane = local key
        {
            int t = tl[c*32 + lane];
            bool valid = (t <= s);
            int hh = w;
            float v = sc[hh*34 + lane] + sc[544 + hh*34 + lane]
                    + sc[1088 + hh*34 + lane] + sc[1632 + hh*34 + lane];
            float val = valid ? v : -1e30f;
            float mc = val;
#pragma unroll
            for (int o = 16; o > 0; o >>= 1) mc = fmaxf(mc, __shfl_xor_sync(0xffffffffu, mc, o));
            float m_old = m_s[hh];
            float m_new = fmaxf(m_old, mc);
            float a = expf(m_old - m_new);
            float p = valid ? expf(val - m_new) : 0.f;
            float psum = p;
#pragma unroll
            for (int o = 16; o > 0; o >>= 1) psum += __shfl_xor_sync(0xffffffffu, psum, o);
            if (lane == 0) { m_s[hh] = m_new; l_s[hh] = l_s[hh]*a + psum; al_s[hh] = a; }
            __nv_bfloat16 phi = __float2bfloat16_rn(p);
            ph[hh*40 + lane] = phi;
            pl[hh*40 + lane] = __float2bfloat16_rn(p - __bfloat162float(phi));
        }
        __syncthreads();

        // ---- rescale O and PV accumulate (warp w owns cols w*32..w*32+31)
        {
            float a0 = al_s[lane >> 2], a1 = al_s[(lane >> 2) + 8];
#pragma unroll
            for (int nt = 0; nt < 4; nt++) {
                oacc[nt][0] *= a0; oacc[nt][1] *= a0;
                oacc[nt][2] *= a1; oacc[nt][3] *= a1;
            }
            uint32_t ph4[2][4], pl4[2][4];
#pragma unroll
            for (int ks = 0; ks < 2; ks++) {
                uint32_t ad = sb + 48384 + (arow*40 + ks*16 + ac)*2;
                LDSM_X4(ph4[ks], ad);
                LDSM_X4(pl4[ks], ad + 1280);
            }
#pragma unroll
            for (int nt = 0; nt < 4; nt++) {
                int n0 = w*32 + nt*8;
#pragma unroll
                for (int ks = 0; ks < 2; ks++) {
                    uint32_t bd = buf + ((ks*16 + (lane & 15))*584 + n0)*2;
                    uint32_t vh[2], vl[2];
                    LDSM_X2T(vh, bd);
                    LDSM_X2T(vl, bd + AT_LO);
                    mma16816(oacc[nt], ph4[ks], vh);
                    mma16816(oacc[nt], ph4[ks], vl);
                    mma16816(oacc[nt], pl4[ks], vh);
                }
            }
        }
        __syncthreads();
    }

    {
        int m_ = lane >> 2, e0 = 2*(lane & 3);
        float li0 = 1.f / l_s[m_];
        float li1 = 1.f / l_s[m_ + 8];
#pragma unroll
        for (int nt = 0; nt < 4; nt++) {
            int c0 = w*32 + nt*8 + e0;
            *(float2*)(omid + (long)bs*8192 + m_*512 + c0)     = make_float2(oacc[nt][0]*li0, oacc[nt][1]*li0);
            *(float2*)(omid + (long)bs*8192 + (m_+8)*512 + c0) = make_float2(oacc[nt][2]*li1, oacc[nt][3]*li1);
        }
    }
}

// ---------------- host orchestration (3-stream fork/join DAG) ------------------
extern "C" void kernel_launch(void* const* d_in, const int* in_sizes, int n_in,
                              void* d_out, int out_size) {
    const float* x      = (const float*)d_in[0];
    const float* fcos   = (const float*)d_in[1];
    const float* fsin   = (const float*)d_in[2];
    const float* mask   = (const float*)d_in[3];
    const float* wq_a   = (const float*)d_in[4];
    const float* qnw    = (const float*)d_in[5];
    const float* wq_b   = (const float*)d_in[6];
    const float* wkv_a  = (const float*)d_in[7];
    const float* kvnw   = (const float*)d_in[8];
    const float* wkv_b  = (const float*)d_in[9];
    const float* wo     = (const float*)d_in[10];
    const float* iwqb   = (const float*)d_in[11];
    const float* iwk    = (const float*)d_in[12];
    const float* iknw   = (const float*)d_in[13];
    const float* iknb   = (const float*)d_in[14];
    const float* iwp    = (const float*)d_in[15];
    float* out = (float*)d_out;

    float *qr, *q, *kvfull, *kv, *kpe, *qabs, *qi, *ki, *wts, *iscore, *omid, *o2, *wt;
    __nv_bfloat16 *khi, *klo;
    int* topkb;
    cudaGetSymbolAddress((void**)&qr,     g_qr);
    cudaGetSymbolAddress((void**)&q,      g_q);
    cudaGetSymbolAddress((void**)&kvfull, g_kvfull);
    cudaGetSymbolAddress((void**)&kv,     g_kv);
    cudaGetSymbolAddress((void**)&kpe,    g_kpe);
    cudaGetSymbolAddress((void**)&qabs,   g_qabs);
    cudaGetSymbolAddress((void**)&qi,     g_qi);
    cudaGetSymbolAddress((void**)&ki,     g_ki);
    cudaGetSymbolAddress((void**)&wts,    g_wts);
    cudaGetSymbolAddress((void**)&iscore, g_iscore);
    cudaGetSymbolAddress((void**)&topkb,  g_topk);
    cudaGetSymbolAddress((void**)&omid,   g_omid);
    cudaGetSymbolAddress((void**)&o2,     g_o2);
    cudaGetSymbolAddress((void**)&wt,     g_wkvbT);
    cudaGetSymbolAddress((void**)&khi,    g_khi);
    cudaGetSymbolAddress((void**)&klo,    g_klo);

    cudaFuncSetAttribute(gemm_mma, cudaFuncAttributeMaxDynamicSharedMemorySize, GM_SMEM);
    cudaFuncSetAttribute(attn_tc,  cudaFuncAttributeMaxDynamicSharedMemorySize, AT_SMEM);

    static cudaStream_t s1 = 0, s2 = 0;
    static cudaEvent_t eF = 0, eQR = 0, eWT = 0, eJ1 = 0;
    if (s1 == 0) {
        cudaStreamCreateWithFlags(&s1, cudaStreamNonBlocking);
        cudaStreamCreateWithFlags(&s2, cudaStreamNonBlocking);
        cudaEventCreateWithFlags(&eF,  cudaEventDisableTiming);
        cudaEventCreateWithFlags(&eQR, cudaEventDisableTiming);
        cudaEventCreateWithFlags(&eWT, cudaEventDisableTiming);
        cudaEventCreateWithFlags(&eJ1, cudaEventDisableTiming);
    }
    cudaStream_t s0 = 0;

    cudaEventRecord(eF, s0);
    cudaStreamWaitEvent(s1, eF, 0);
    cudaStreamWaitEvent(s2, eF, 0);

    // ---- s0: qr chain -> q chain -> attention -> output
    gemm_bt<<<dim3(12, 32, 1), 256, 0, s0>>>(x, 2048, 0, wq_a, 2048, 0, qr, 768, 0, 4096, 768, 2048);
    rmsnorm_kernel<<<4096, 256, 0, s0>>>(qr, qnw, 768);
    cudaEventRecord(eQR, s0);

    // ---- s2: kv path + weight transpose
    gemm_mma<<<dim3(5, 32, 1), 256, GM_SMEM, s2>>>(x, 2048, 0, wkv_a, 2048, 0, kvfull, 576, 0, 4096, 576, 2048);
    kvpost_kernel<<<4096, 256, 0, s2>>>(kvfull, kvnw, fcos, fsin, kv, kpe);
    kvsplit_kernel<<<(BS_*576 + 255)/256, 256, 0, s2>>>(kv, kpe, khi, klo);
    transpose_wkvb<<<(16*128*512 + 255)/256, 256, 0, s2>>>(wkv_b, wt);
    cudaEventRecord(eWT, s2);

    // ---- s1: indexer path
    gemm_bt<<<dim3(2, 32, 1), 256, 0, s1>>>(x, 2048, 0, iwk, 2048, 0, ki, 128, 0, 4096, 128, 2048);
    kipost_kernel<<<4096, 128, 0, s1>>>(ki, iknw, iknb, fcos, fsin);
    gemm_bt<<<dim3(1, 32, 1), 256, 0, s1>>>(x, 2048, 0, iwp, 2048, 0, wts, 16, 0, 4096, 16, 2048);
    cudaStreamWaitEvent(s1, eQR, 0);
    gemm_bt<<<dim3(32, 32, 1), 256, 0, s1>>>(qr, 768, 0, iwqb, 768, 0, qi, 2048, 0, 4096, 2048, 768);
    rope_qi_kernel<<<(BS_*16*32 + 255)/256, 256, 0, s1>>>(qi, fcos, fsin);
    iscore_kernel<<<dim3(32, 16, 2), 256, 0, s1>>>(qi, ki, wts, mask, iscore);
    topk_kernel<<<4096, 256, 0, s1>>>(iscore, topkb);
    cudaEventRecord(eJ1, s1);

    // ---- s0 continues
    gemm_mma<<<dim3(24, 32, 1), 256, GM_SMEM, s0>>>(qr, 768, 0, wq_b, 768, 0, q, 3072, 0, 4096, 3072, 768);
    rope_q_kernel<<<(BS_*16*32 + 255)/256, 256, 0, s0>>>(q, fcos, fsin);
    cudaStreamWaitEvent(s0, eWT, 0);
    gemm_mma<<<dim3(4, 32, 16), 256, GM_SMEM, s0>>>(q, 3072, 192, wt, 128, 65536, qabs, 8192, 512,
                                                    4096, 512, 128);
    cudaStreamWaitEvent(s0, eJ1, 0);
    attn_tc<<<4096, 512, AT_SMEM, s0>>>(qabs, q, khi, klo, topkb, omid);
    gemm_mma<<<dim3(1, 32, 16), 256, GM_SMEM, s0>>>(omid, 8192, 512, wkv_b + 128*512, 512, 256*512,
                                                    o2, 2048, 128, 4096, 128, 512);
    gemm_mma<<<dim3(16, 32, 1), 256, GM_SMEM, s0>>>(o2, 2048, 0, wo, 2048, 0, out, 2048, 0, 4096, 2048, 2048);
}

// round 8
// speedup vs baseline: 1.9473x; 1.0349x over previous
#include <cuda_runtime.h>
#include <cuda_bf16.h>
#include <math.h>
#include <stdint.h>

// Problem constants
#define B_    2
#define S_    2048
#define DIM_  2048
#define NH_   16
#define QLR_  768
#define KVLR_ 512
#define NOPE_ 128
#define ROPE_ 64
#define VDIM_ 128
#define IH_   16
#define IHD_  128
#define ITOPK_ 512
#define BS_   (B_*S_)   // 4096

// ---------------- scratch (device globals; no allocation allowed) -------------
__device__ float g_qr[BS_*QLR_];
__device__ float g_q[BS_*NH_*(NOPE_+ROPE_)];
__device__ float g_kvfull[BS_*(KVLR_+ROPE_)];
__device__ float g_kv[BS_*KVLR_];
__device__ float g_kpe[BS_*ROPE_];
__device__ float g_qabs[BS_*NH_*KVLR_];
__device__ float g_qi[BS_*IH_*IHD_];
__device__ float g_ki[BS_*IHD_];
__device__ float g_wts[BS_*IH_];
__device__ float g_iscore[B_*S_*S_];
__device__ int   g_topk[BS_*ITOPK_];
__device__ float g_omid[BS_*NH_*KVLR_];
__device__ float g_o2[BS_*NH_*VDIM_];
__device__ float g_wkvbT[16*512*128];            // transposed wkv_b[:, :128, :] -> [h][c][d]
__device__ __nv_bfloat16 g_khi[BS_*576];         // kv||kpe hi split
__device__ __nv_bfloat16 g_klo[BS_*576];         // kv||kpe lo split

// =================== helpers ==================================================
__device__ __forceinline__ uint32_t smem_u32(const void* p) {
    uint32_t a;
    asm("{ .reg .u64 t; cvta.to.shared.u64 t, %1; cvt.u32.u64 %0, t; }" : "=r"(a) : "l"(p));
    return a;
}
__device__ __forceinline__ uint32_t pack_hi(float x, float y) {
    __nv_bfloat162 p;
    p.x = __float2bfloat16_rn(x);
    p.y = __float2bfloat16_rn(y);
    return *(uint32_t*)&p;
}
__device__ __forceinline__ uint32_t pack_lo(float x, float y) {
    __nv_bfloat16 hx = __float2bfloat16_rn(x);
    __nv_bfloat16 hy = __float2bfloat16_rn(y);
    __nv_bfloat162 p;
    p.x = __float2bfloat16_rn(x - __bfloat162float(hx));
    p.y = __float2bfloat16_rn(y - __bfloat162float(hy));
    return *(uint32_t*)&p;
}
__device__ __forceinline__ void mma16816(float* c, const uint32_t* a, const uint32_t* b) {
    asm volatile("mma.sync.aligned.m16n8k16.row.col.f32.bf16.bf16.f32 "
        "{%0,%1,%2,%3}, {%4,%5,%6,%7}, {%8,%9}, {%0,%1,%2,%3};"
        : "+f"(c[0]), "+f"(c[1]), "+f"(c[2]), "+f"(c[3])
        : "r"(a[0]), "r"(a[1]), "r"(a[2]), "r"(a[3]), "r"(b[0]), "r"(b[1]));
}
#define LDSM_X4(r, a) asm volatile("ldmatrix.sync.aligned.m8n8.x4.shared.b16 {%0,%1,%2,%3}, [%4];" \
    : "=r"((r)[0]),"=r"((r)[1]),"=r"((r)[2]),"=r"((r)[3]) : "r"(a))
#define LDSM_X2(r, a) asm volatile("ldmatrix.sync.aligned.m8n8.x2.shared.b16 {%0,%1}, [%2];" \
    : "=r"((r)[0]),"=r"((r)[1]) : "r"(a))
#define LDSM_X2T(r, a) asm volatile("ldmatrix.sync.aligned.m8n8.x2.trans.shared.b16 {%0,%1}, [%2];" \
    : "=r"((r)[0]),"=r"((r)[1]) : "r"(a))
#define CP_ASYNC16(dst, src) asm volatile("cp.async.cg.shared.global [%0], [%1], 16;" :: "r"(dst), "l"(src))
#define CP_COMMIT() asm volatile("cp.async.commit_group;" ::: "memory")
#define CP_WAIT(n)  asm volatile("cp.async.wait_group %0;" :: "n"(n) : "memory")

// word-granularity swizzled smem address for gemm_mma tiles (128 rows x 16 words)
__device__ __forceinline__ int sw_addr(int row, int w) {
    return row*16 + (w ^ ((((row)>>1)&3)<<2));
}

// =================== tensor-core GEMM (bf16x3): C[M,N]=A[M,K]@B[N,K]^T ========
#define GM_SMEM 65536

__global__ void __launch_bounds__(256, 1)
gemm_mma(const float* __restrict__ A, int lda, long aZ,
         const float* __restrict__ Bm, int ldb, long bZ,
         float* __restrict__ C, int ldc, long cZ,
         int M, int N, int K) {
    extern __shared__ uint32_t smw[];
    A  += (long)blockIdx.z * aZ;
    Bm += (long)blockIdx.z * bZ;
    C  += (long)blockIdx.z * cZ;
    int m0 = blockIdx.y * 128, n0 = blockIdx.x * 128;
    int tid = threadIdx.x, lane = tid & 31, wid = tid >> 5;
    int wm = wid >> 2, wn = wid & 3;
    int g = lane >> 2, tig = lane & 3;

    float acc[4][4][4];
#pragma unroll
    for (int i = 0; i < 4; i++)
#pragma unroll
        for (int j = 0; j < 4; j++)
#pragma unroll
            for (int r = 0; r < 4; r++) acc[i][j][r] = 0.f;

    int arow = tid >> 1, acol = (tid & 1) * 16;
    int nch = K >> 5;

    float4 ra[4], rb[4];
    {
        const float* ap = A + (long)(m0 + arow)*lda + acol;
        bool aok = (m0 + arow) < M;
#pragma unroll
        for (int i = 0; i < 4; i++)
            ra[i] = aok ? *(const float4*)(ap + i*4) : make_float4(0.f,0.f,0.f,0.f);
        const float* bp = Bm + (long)(n0 + arow)*ldb + acol;
        bool bok = (n0 + arow) < N;
#pragma unroll
        for (int i = 0; i < 4; i++)
            rb[i] = bok ? *(const float4*)(bp + i*4) : make_float4(0.f,0.f,0.f,0.f);
    }

    for (int it = 0; it < nch; it++) {
        int stg = it & 1;
        uint32_t* sAhi = smw + stg*8192;
        uint32_t* sAlo = sAhi + 2048;
        uint32_t* sBhi = sAhi + 4096;
        uint32_t* sBlo = sAhi + 6144;
        {
            uint32_t hw[8], lw[8];
#pragma unroll
            for (int i = 0; i < 4; i++) {
                hw[i*2]   = pack_hi(ra[i].x, ra[i].y);
                hw[i*2+1] = pack_hi(ra[i].z, ra[i].w);
                lw[i*2]   = pack_lo(ra[i].x, ra[i].y);
                lw[i*2+1] = pack_lo(ra[i].z, ra[i].w);
            }
            int g0 = (((tid&1)*2 + 0) ^ ((arow>>1)&3)) * 4;
            int g1 = (((tid&1)*2 + 1) ^ ((arow>>1)&3)) * 4;
            uint32_t* dst = sAhi + arow*16;
            *(uint4*)(dst + g0) = make_uint4(hw[0],hw[1],hw[2],hw[3]);
            *(uint4*)(dst + g1) = make_uint4(hw[4],hw[5],hw[6],hw[7]);
            dst = sAlo + arow*16;
            *(uint4*)(dst + g0) = make_uint4(lw[0],lw[1],lw[2],lw[3]);
            *(uint4*)(dst + g1) = make_uint4(lw[4],lw[5],lw[6],lw[7]);
#pragma unroll
            for (int i = 0; i < 4; i++) {
                hw[i*2]   = pack_hi(rb[i].x, rb[i].y);
                hw[i*2+1] = pack_hi(rb[i].z, rb[i].w);
                lw[i*2]   = pack_lo(rb[i].x, rb[i].y);
                lw[i*2+1] = pack_lo(rb[i].z, rb[i].w);
            }
            dst = sBhi + arow*16;
            *(uint4*)(dst + g0) = make_uint4(hw[0],hw[1],hw[2],hw[3]);
            *(uint4*)(dst + g1) = make_uint4(hw[4],hw[5],hw[6],hw[7]);
            dst = sBlo + arow*16;
            *(uint4*)(dst + g0) = make_uint4(lw[0],lw[1],lw[2],lw[3]);
            *(uint4*)(dst + g1) = make_uint4(lw[4],lw[5],lw[6],lw[7]);
        }
        __syncthreads();
        if (it + 1 < nch) {
            int gk = (it + 1) << 5;
            const float* ap = A + (long)(m0 + arow)*lda + gk + acol;
            bool aok = (m0 + arow) < M;
#pragma unroll
            for (int i = 0; i < 4; i++)
                ra[i] = aok ? *(const float4*)(ap + i*4) : make_float4(0.f,0.f,0.f,0.f);
            const float* bp = Bm + (long)(n0 + arow)*ldb + gk + acol;
            bool bok = (n0 + arow) < N;
#pragma unroll
            for (int i = 0; i < 4; i++)
                rb[i] = bok ? *(const float4*)(bp + i*4) : make_float4(0.f,0.f,0.f,0.f);
        }
#pragma unroll
        for (int ks = 0; ks < 2; ks++) {
            uint32_t bh[4][2], bl[4][2];
#pragma unroll
            for (int nt = 0; nt < 4; nt++) {
                int nrow = wn*32 + nt*8 + g;
                int w0 = ks*8 + tig;
                bh[nt][0] = sBhi[sw_addr(nrow, w0)];
                bh[nt][1] = sBhi[sw_addr(nrow, w0+4)];
                bl[nt][0] = sBlo[sw_addr(nrow, w0)];
                bl[nt][1] = sBlo[sw_addr(nrow, w0+4)];
            }
#pragma unroll
            for (int mt = 0; mt < 4; mt++) {
                int ar = wm*64 + mt*16 + g;
                int w0 = ks*8 + tig;
                uint32_t ah[4], al[4];
                ah[0] = sAhi[sw_addr(ar,   w0)];
                ah[1] = sAhi[sw_addr(ar+8, w0)];
                ah[2] = sAhi[sw_addr(ar,   w0+4)];
                ah[3] = sAhi[sw_addr(ar+8, w0+4)];
                al[0] = sAlo[sw_addr(ar,   w0)];
                al[1] = sAlo[sw_addr(ar+8, w0)];
                al[2] = sAlo[sw_addr(ar,   w0+4)];
                al[3] = sAlo[sw_addr(ar+8, w0+4)];
#pragma unroll
                for (int nt = 0; nt < 4; nt++) {
                    mma16816(acc[mt][nt], ah, bh[nt]);
                    mma16816(acc[mt][nt], ah, bl[nt]);
                    mma16816(acc[mt][nt], al, bh[nt]);
                }
            }
        }
        __syncthreads();
    }
#pragma unroll
    for (int mt = 0; mt < 4; mt++) {
#pragma unroll
        for (int nt = 0; nt < 4; nt++) {
            int r0 = m0 + wm*64 + mt*16 + g;
            int c0 = n0 + wn*32 + nt*8 + tig*2;
            if (c0 < N) {
                if (r0 < M)
                    *(float2*)(C + (long)r0*ldc + c0) = make_float2(acc[mt][nt][0], acc[mt][nt][1]);
                if (r0 + 8 < M)
                    *(float2*)(C + (long)(r0+8)*ldc + c0) = make_float2(acc[mt][nt][2], acc[mt][nt][3]);
            }
        }
    }
}

// transpose wkv_b[:, :128, :] -> wt[h][c][d]
__global__ void transpose_wkvb(const float* __restrict__ w, float* __restrict__ wt) {
    int idx = blockIdx.x * 256 + threadIdx.x;
    if (idx >= 16*128*512) return;
    int c = idx & 511, d = (idx >> 9) & 127, h = idx >> 16;
    wt[h*65536 + c*128 + d] = w[h*131072 + d*512 + c];
}

// ---------------- fp32 GEMM (bit-exact k-order): C[M,N] = A[M,K] @ B[N,K]^T ---
// 128(M) x 128(N) tile, 256 threads, 8x8 micro-tile — FMA-bound (4:1).
__global__ void __launch_bounds__(256)
gemm_bt(const float* __restrict__ A, int lda, long aZ,
        const float* __restrict__ Bm, int ldb, long bZ,
        float* __restrict__ C, int ldc, long cZ,
        int M, int N, int K) {
    A  += (long)blockIdx.z * aZ;
    Bm += (long)blockIdx.z * bZ;
    C  += (long)blockIdx.z * cZ;
    int n0 = blockIdx.x * 128, m0 = blockIdx.y * 128;
    __shared__ float As[16][129];
    __shared__ float Bs[16][129];
    int tid = threadIdx.x;
    int tx = tid & 15, ty = tid >> 4;
    int kl = tid & 15, ml = tid >> 4;
    float acc[8][8];
#pragma unroll
    for (int i = 0; i < 8; i++)
#pragma unroll
        for (int j = 0; j < 8; j++) acc[i][j] = 0.f;

    for (int k0 = 0; k0 < K; k0 += 16) {
#pragma unroll
        for (int r = 0; r < 8; r++) {
            int mm = ml + 16*r;
            int gm = m0 + mm, gk = k0 + kl;
            As[kl][mm] = (gm < M && gk < K) ? A[(long)gm*lda + gk] : 0.f;
            int gn = n0 + mm;
            Bs[kl][mm] = (gn < N && gk < K) ? Bm[(long)gn*ldb + gk] : 0.f;
        }
        __syncthreads();
#pragma unroll
        for (int kk = 0; kk < 16; kk++) {
            float a[8], bb[8];
#pragma unroll
            for (int i = 0; i < 8; i++) a[i]  = As[kk][ty + 16*i];
#pragma unroll
            for (int j = 0; j < 8; j++) bb[j] = Bs[kk][tx + 16*j];
#pragma unroll
            for (int i = 0; i < 8; i++)
#pragma unroll
                for (int j = 0; j < 8; j++) acc[i][j] += a[i]*bb[j];
        }
        __syncthreads();
    }
#pragma unroll
    for (int i = 0; i < 8; i++)
#pragma unroll
        for (int j = 0; j < 8; j++) {
            int gm = m0 + ty + 16*i, gn = n0 + tx + 16*j;
            if (gm < M && gn < N) C[(long)gm*ldc + gn] = acc[i][j];
        }
}

// ---------------- elementwise / norm / rope -----------------------------------
__global__ void rmsnorm_kernel(float* __restrict__ x, const float* __restrict__ w, int L) {
    int row = blockIdx.x, tid = threadIdx.x;
    float* pr = x + (long)row * L;
    float ss = 0.f;
    for (int i = tid; i < L; i += 256) { float v = pr[i]; ss += v*v; }
    __shared__ float red[256];
    red[tid] = ss; __syncthreads();
    for (int o = 128; o > 0; o >>= 1) { if (tid < o) red[tid] += red[tid+o]; __syncthreads(); }
    float inv = rsqrtf(red[0] / (float)L + 1e-6f);
    for (int i = tid; i < L; i += 256) pr[i] = w[i] * pr[i] * inv;
}

__global__ void kvpost_kernel(const float* __restrict__ kvfull, const float* __restrict__ w,
                              const float* __restrict__ fcos, const float* __restrict__ fsin,
                              float* __restrict__ kv, float* __restrict__ kpe) {
    int row = blockIdx.x, s = row & (S_-1), tid = threadIdx.x;
    const float* src = kvfull + (long)row * 576;
    float ss = 0.f;
    for (int i = tid; i < 512; i += 256) { float v = src[i]; ss += v*v; }
    __shared__ float red[256];
    red[tid] = ss; __syncthreads();
    for (int o = 128; o > 0; o >>= 1) { if (tid < o) red[tid] += red[tid+o]; __syncthreads(); }
    float inv = rsqrtf(red[0] / 512.f + 1e-6f);
    for (int i = tid; i < 512; i += 256) kv[(long)row*512 + i] = w[i] * src[i] * inv;
    if (tid < 32) {
        float x1 = src[512 + tid], x2 = src[544 + tid];
        float c = fcos[s*32 + tid], sn = fsin[s*32 + tid];
        kpe[(long)row*64 + tid]      = x1*c - x2*sn;
        kpe[(long)row*64 + 32 + tid] = x1*sn + x2*c;
    }
}

// split kv||kpe into bf16 hi/lo global arrays
__global__ void kvsplit_kernel(const float* __restrict__ kv, const float* __restrict__ kpe,
                               __nv_bfloat16* __restrict__ khi, __nv_bfloat16* __restrict__ klo) {
    int idx = blockIdx.x*256 + threadIdx.x;
    if (idx >= BS_*576) return;
    int r = idx / 576, d = idx - r*576;
    float v = (d < 512) ? kv[(long)r*512 + d] : kpe[(long)r*64 + d - 512];
    __nv_bfloat16 hi = __float2bfloat16_rn(v);
    khi[idx] = hi;
    klo[idx] = __float2bfloat16_rn(v - __bfloat162float(hi));
}

__global__ void kipost_kernel(float* __restrict__ ki, const float* __restrict__ w,
                              const float* __restrict__ bvec,
                              const float* __restrict__ fcos, const float* __restrict__ fsin) {
    int row = blockIdx.x, s = row & (S_-1), tid = threadIdx.x; // 128 threads
    float* pr = ki + (long)row * 128;
    float v = pr[tid];
    __shared__ float red[128];
    red[tid] = v; __syncthreads();
    for (int o = 64; o > 0; o >>= 1) { if (tid < o) red[tid] += red[tid+o]; __syncthreads(); }
    float mean = red[0] / 128.f;
    __syncthreads();
    float d = v - mean;
    red[tid] = d*d; __syncthreads();
    for (int o = 64; o > 0; o >>= 1) { if (tid < o) red[tid] += red[tid+o]; __syncthreads(); }
    float var = red[0] / 128.f;
    __syncthreads();
    float y = d * rsqrtf(var + 1e-6f) * w[tid] + bvec[tid];
    __shared__ float yb[128];
    yb[tid] = y; __syncthreads();
    float outv;
    if (tid < 32) {
        float c = fcos[s*32 + tid], sn = fsin[s*32 + tid];
        outv = yb[tid]*c - yb[tid+32]*sn;
    } else if (tid < 64) {
        int i = tid - 32;
        float c = fcos[s*32 + i], sn = fsin[s*32 + i];
        outv = yb[i]*sn + yb[tid]*c;
    } else {
        outv = y;
    }
    pr[tid] = outv;
}

__global__ void rope_q_kernel(float* __restrict__ q, const float* __restrict__ fcos,
                              const float* __restrict__ fsin) {
    int idx = blockIdx.x * blockDim.x + threadIdx.x;
    if (idx >= BS_*16*32) return;
    int i = idx & 31, h = (idx >> 5) & 15, bs = idx >> 9;
    int s = bs & (S_-1);
    long base = (long)bs*3072 + h*192 + 128;
    float x1 = q[base + i], x2 = q[base + 32 + i];
    float c = fcos[s*32 + i], sn = fsin[s*32 + i];
    q[base + i]      = x1*c - x2*sn;
    q[base + 32 + i] = x1*sn + x2*c;
}

__global__ void rope_qi_kernel(float* __restrict__ qi, const float* __restrict__ fcos,
                               const float* __restrict__ fsin) {
    int idx = blockIdx.x * blockDim.x + threadIdx.x;
    if (idx >= BS_*16*32) return;
    int i = idx & 31, h = (idx >> 5) & 15, bs = idx >> 9;
    int s = bs & (S_-1);
    long base = (long)bs*2048 + h*128;
    float x1 = qi[base + i], x2 = qi[base + 32 + i];
    float c = fcos[s*32 + i], sn = fsin[s*32 + i];
    qi[base + i]      = x1*c - x2*sn;
    qi[base + 32 + i] = x1*sn + x2*c;
}

// ---------------- indexer score (128s x 64t tile, 2 heads/pass, bit-exact) ----
__global__ void __launch_bounds__(256)
iscore_kernel(const float* __restrict__ qi, const float* __restrict__ ki,
              const float* __restrict__ wts, const float* __restrict__ mask,
              float* __restrict__ iscore) {
    int b = blockIdx.z;
    int s0 = blockIdx.y * 128, t0 = blockIdx.x * 64;
    int tid = threadIdx.x;
    if (t0 > s0 + 127) {
        for (int i = tid; i < 128*64; i += 256) {
            int m = i >> 6, n = i & 63;
            int s = s0 + m, t = t0 + n;
            iscore[((long)b*S_ + s)*S_ + t] = mask[(long)s*S_ + t];
        }
        return;
    }
    int tx = tid & 15, ty = tid >> 4;
    int kl = tid & 15, ml = tid >> 4;
    __shared__ float qs[2][16][129];
    __shared__ float ks[16][65];
    __shared__ float ws_s[16][128];
    const float IW_SCALE = rsqrtf(2048.0f);
    for (int i = tid; i < 16*128; i += 256) {
        int m = i >> 4, h = i & 15;
        ws_s[h][m] = wts[((long)(b*S_ + s0 + m))*16 + h] * IW_SCALE;
    }
    float acc[8][4];
#pragma unroll
    for (int i = 0; i < 8; i++)
#pragma unroll
        for (int j = 0; j < 4; j++) acc[i][j] = 0.f;
    __syncthreads();

    for (int h = 0; h < 16; h += 2) {
        float dot[2][8][4];
#pragma unroll
        for (int e = 0; e < 2; e++)
#pragma unroll
            for (int i = 0; i < 8; i++)
#pragma unroll
                for (int j = 0; j < 4; j++) dot[e][i][j] = 0.f;
        for (int d0 = 0; d0 < 128; d0 += 16) {
#pragma unroll
            for (int e = 0; e < 2; e++)
#pragma unroll
                for (int r = 0; r < 8; r++) {
                    int mm = ml + 16*r;
                    qs[e][kl][mm] = qi[((long)(b*S_ + s0 + mm))*2048 + (h+e)*128 + d0 + kl];
                }
#pragma unroll
            for (int r = 0; r < 4; r++) {
                int mm = ml + 16*r;
                ks[kl][mm] = ki[((long)(b*S_ + t0 + mm))*128 + d0 + kl];
            }
            __syncthreads();
#pragma unroll
            for (int kk = 0; kk < 16; kk++) {
                float a0[8], a1[8], bb[4];
#pragma unroll
                for (int i = 0; i < 8; i++) { a0[i] = qs[0][kk][ty + 16*i]; a1[i] = qs[1][kk][ty + 16*i]; }
#pragma unroll
                for (int j = 0; j < 4; j++) bb[j] = ks[kk][tx + 16*j];
#pragma unroll
                for (int i = 0; i < 8; i++)
#pragma unroll
                    for (int j = 0; j < 4; j++) {
                        dot[0][i][j] += a0[i]*bb[j];
                        dot[1][i][j] += a1[i]*bb[j];
                    }
            }
            __syncthreads();
        }
#pragma unroll
        for (int e = 0; e < 2; e++)
#pragma unroll
            for (int i = 0; i < 8; i++) {
                float w = ws_s[h+e][ty + 16*i];
#pragma unroll
                for (int j = 0; j < 4; j++) acc[i][j] += fmaxf(dot[e][i][j], 0.f) * w;
            }
    }
#pragma unroll
    for (int i = 0; i < 8; i++)
#pragma unroll
        for (int j = 0; j < 4; j++) {
            int s = s0 + ty + 16*i, t = t0 + tx + 16*j;
            iscore[((long)b*S_ + s)*S_ + t] = acc[i][j] + mask[(long)s*S_ + t];
        }
}

// ---------------- exact top-512 per row (radix select, deterministic) ---------
__global__ void topk_kernel(const float* __restrict__ iscore, int* __restrict__ out) {
    int row = blockIdx.x;
    const float* p = iscore + (long)row * S_;
    int tid = threadIdx.x; // 256
    __shared__ unsigned int hist[256];
    __shared__ unsigned int s_prefix;
    __shared__ int s_rem;
    __shared__ int sgt[257], seq[257];
    if (tid == 0) { s_prefix = 0u; s_rem = ITOPK_; }
    __syncthreads();
    for (int pass = 0; pass < 4; pass++) {
        hist[tid] = 0u;
        __syncthreads();
        int shift = 24 - 8*pass;
        unsigned int pref = s_prefix;
        for (int e = 0; e < 8; e++) {
            int j = tid*8 + e;
            unsigned int u = __float_as_uint(p[j]);
            unsigned int k = (u & 0x80000000u) ? ~u : (u | 0x80000000u);
            bool ok = (pass == 0) || (((k ^ pref) >> (shift + 8)) == 0u);
            if (ok) atomicAdd(&hist[(k >> shift) & 255u], 1u);
        }
        __syncthreads();
        if (tid == 0) {
            int rem = s_rem;
            unsigned int cum = 0; int bin = 0;
            for (int bb = 255; bb >= 0; bb--) {
                if (cum + hist[bb] >= (unsigned)rem) { bin = bb; break; }
                cum += hist[bb];
            }
            s_rem = rem - (int)cum;
            s_prefix = s_prefix | ((unsigned)bin << shift);
        }
        __syncthreads();
    }
    unsigned int kth = s_prefix;
    int cgt = 0, ceq = 0;
    for (int e = 0; e < 8; e++) {
        int j = tid*8 + e;
        unsigned int u = __float_as_uint(p[j]);
        unsigned int k = (u & 0x80000000u) ? ~u : (u | 0x80000000u);
        cgt += (k > kth); ceq += (k == kth);
    }
    sgt[tid] = cgt; seq[tid] = ceq;
    __syncthreads();
    if (tid == 0) {
        int ag = 0, ae = 0;
        for (int i = 0; i < 256; i++) {
            int tg = sgt[i], te = seq[i];
            sgt[i] = ag; seq[i] = ae;
            ag += tg; ae += te;
        }
        sgt[256] = ag;
    }
    __syncthreads();
    int total_gt = sgt[256];
    int pgt = sgt[tid];
    int peq = total_gt + seq[tid];
    int* o = out + (long)row * ITOPK_;
    for (int e = 0; e < 8; e++) {
        int j = tid*8 + e;
        unsigned int u = __float_as_uint(p[j]);
        unsigned int k = (u & 0x80000000u) ? ~u : (u | 0x80000000u);
        if (k > kth) { o[pgt++] = j; }
        else if (k == kth) { if (peq < ITOPK_) o[peq] = j; peq++; }
    }
}

// ---------------- fused flash-style tensor-core sparse attention ---------------
// 512 threads / 16 warps, Q hi-fragments hoisted into registers.
#define AT_SMEM 200448
#define AT_BUF0 50944
#define AT_BUFSZ 74752
#define AT_LO 37376

__device__ __forceinline__ void at_gather(const __nv_bfloat16* __restrict__ khi,
                                          const __nv_bfloat16* __restrict__ klo,
                                          long kb, const int* tl, int c,
                                          uint32_t bufaddr, int tid) {
    int jloc = tid >> 4, sg0 = tid & 15;   // 32 rows x 16 threads
    int t = tl[c*32 + jloc];
    const char* sh = (const char*)(khi + kb + (long)t*576);
    const char* sl = (const char*)(klo + kb + (long)t*576);
    uint32_t dh = bufaddr + jloc*1168;
#pragma unroll
    for (int u = 0; u < 9; u++) {
        int ch = sg0 + u*16;               // 0..143: 72 hi chunks then 72 lo
        if (ch < 72) CP_ASYNC16(dh + ch*16, sh + ch*16);
        else         CP_ASYNC16(dh + AT_LO + (ch-72)*16, sl + (ch-72)*16);
    }
    CP_COMMIT();
}

__global__ void __launch_bounds__(512, 1)
attn_tc(const float* __restrict__ qabs, const float* __restrict__ qfull,
        const __nv_bfloat16* __restrict__ khi, const __nv_bfloat16* __restrict__ klo,
        const int* __restrict__ topk, float* __restrict__ omid) {
    extern __shared__ char sm[];
    uint32_t sb = smem_u32(sm);
    int* tl = (int*)sm;
    float* m_s  = (float*)(sm + 2048);
    float* l_s  = (float*)(sm + 2112);
    float* al_s = (float*)(sm + 2176);
    float* sc   = (float*)(sm + 2304);       // [4][16][34]
    __nv_bfloat16* qh = (__nv_bfloat16*)(sm + 11008);
    __nv_bfloat16* ph = (__nv_bfloat16*)(sm + 48384);
    __nv_bfloat16* pl = (__nv_bfloat16*)(sm + 49664);
    int bs = blockIdx.x, b = bs >> 11, s = bs & (S_-1);
    int tid = threadIdx.x, lane = tid & 31, w = tid >> 5;
    const long kb = (long)b * 2048 * 576;

    for (int j = tid; j < 512; j += 512) tl[j] = topk[(long)bs*512 + j];
    if (tid < 16) { m_s[tid] = -1e30f; l_s[tid] = 0.f; }
    const float scale = 0.07216878364870322f;  // 1/sqrt(192)
    __syncthreads();
    for (int i = tid; i < 16*576; i += 512) {
        int h = i / 576, d = i - h*576;
        float v = (d < 512) ? qabs[(long)bs*8192 + h*512 + d]
                            : qfull[(long)bs*3072 + h*192 + 128 + (d - 512)];
        v *= scale;
        __nv_bfloat16 hi = __float2bfloat16_rn(v);
        qh[h*584 + d] = hi;
        qh[9344 + h*584 + d] = __float2bfloat16_rn(v - __bfloat162float(hi));  // ql region
    }
    at_gather(khi, klo, kb, tl, 0, sb + AT_BUF0, tid);
    __syncthreads();

    float oacc[4][4];
#pragma unroll
    for (int nt = 0; nt < 4; nt++)
#pragma unroll
        for (int r = 0; r < 4; r++) oacc[nt][r] = 0.f;

    int kh4 = w >> 2, nt4 = w & 3;
    int arow = lane & 15, ac = (lane >> 4) * 8;
    int brow = nt4*8 + (lane & 7), bc = ((lane >> 3) & 1) * 8;

    // ---- hoist Q hi fragments (loop-invariant across all 16 chunks)
    uint32_t ahq[9][4];
#pragma unroll
    for (int ks = 0; ks < 9; ks++) {
        int d = kh4*144 + ks*16;
        uint32_t ad = sb + 11008 + (arow*584 + d + ac)*2;
        LDSM_X4(ahq[ks], ad);
    }

    for (int c = 0; c < 16; c++) {
        uint32_t buf = sb + AT_BUF0 + (c & 1)*AT_BUFSZ;
        if (c < 15) {
            at_gather(khi, klo, kb, tl, c+1, sb + AT_BUF0 + ((c+1)&1)*AT_BUFSZ, tid);
            CP_WAIT(1);
        } else {
            CP_WAIT(0);
        }
        __syncthreads();

        // ---- QK partial: warp -> k-quarter kh4 (144 dims), token n-tile nt4
        float qk[4] = {0.f, 0.f, 0.f, 0.f};
#pragma unroll
        for (int ks = 0; ks < 9; ks++) {
            int d = kh4*144 + ks*16;
            uint32_t alr[4], bh[2], bl[2];
            uint32_t ad = sb + 11008 + (arow*584 + d + ac)*2;
            LDSM_X4(alr, ad + 18688);
            uint32_t bd = buf + (brow*584 + d + bc)*2;
            LDSM_X2(bh, bd);
            LDSM_X2(bl, bd + AT_LO);
            mma16816(qk, ahq[ks], bh);
            mma16816(qk, ahq[ks], bl);
            mma16816(qk, alr, bh);
        }
        {
            int m_ = lane >> 2, e0 = 2*(lane & 3);
            float* scr = sc + kh4*544;
            scr[m_*34 + nt4*8 + e0]       = qk[0];
            scr[m_*34 + nt4*8 + e0 + 1]   = qk[1];
            scr[(m_+8)*34 + nt4*8 + e0]   = qk[2];
            scr[(m_+8)*34 + nt4*8 + e0+1] = qk[3];
        }
        __syncthreads();

        // ---- online softmax: warp w handles head w; lane = local key
        {
            int t = tl[c*32 + lane];
            bool valid = (t <= s);
            int hh = w;
            float v = sc[hh*34 + lane] + sc[544 + hh*34 + lane]
                    + sc[1088 + hh*34 + lane] + sc[1632 + hh*34 + lane];
            float val = valid ? v : -1e30f;
            float mc = val;
#pragma unroll
            for (int o = 16; o > 0; o >>= 1) mc = fmaxf(mc, __shfl_xor_sync(0xffffffffu, mc, o));
            float m_old = m_s[hh];
            float m_new = fmaxf(m_old, mc);
            float a = expf(m_old - m_new);
            float p = valid ? expf(val - m_new) : 0.f;
            float psum = p;
#pragma unroll
            for (int o = 16; o > 0; o >>= 1) psum += __shfl_xor_sync(0xffffffffu, psum, o);
            if (lane == 0) { m_s[hh] = m_new; l_s[hh] = l_s[hh]*a + psum; al_s[hh] = a; }
            __nv_bfloat16 phi = __float2bfloat16_rn(p);
            ph[hh*40 + lane] = phi;
            pl[hh*40 + lane] = __float2bfloat16_rn(p - __bfloat162float(phi));
        }
        __syncthreads();

        // ---- rescale O and PV accumulate (warp w owns cols w*32..w*32+31)
        {
            float a0 = al_s[lane >> 2], a1 = al_s[(lane >> 2) + 8];
#pragma unroll
            for (int nt = 0; nt < 4; nt++) {
                oacc[nt][0] *= a0; oacc[nt][1] *= a0;
                oacc[nt][2] *= a1; oacc[nt][3] *= a1;
            }
            uint32_t ph4[2][4], pl4[2][4];
#pragma unroll
            for (int ks = 0; ks < 2; ks++) {
                uint32_t ad = sb + 48384 + (arow*40 + ks*16 + ac)*2;
                LDSM_X4(ph4[ks], ad);
                LDSM_X4(pl4[ks], ad + 1280);
            }
#pragma unroll
            for (int nt = 0; nt < 4; nt++) {
                int n0 = w*32 + nt*8;
#pragma unroll
                for (int ks = 0; ks < 2; ks++) {
                    uint32_t bd = buf + ((ks*16 + (lane & 15))*584 + n0)*2;
                    uint32_t vh[2], vl[2];
                    LDSM_X2T(vh, bd);
                    LDSM_X2T(vl, bd + AT_LO);
                    mma16816(oacc[nt], ph4[ks], vh);
                    mma16816(oacc[nt], ph4[ks], vl);
                    mma16816(oacc[nt], pl4[ks], vh);
                }
            }
        }
        __syncthreads();
    }

    {
        int m_ = lane >> 2, e0 = 2*(lane & 3);
        float li0 = 1.f / l_s[m_];
        float li1 = 1.f / l_s[m_ + 8];
#pragma unroll
        for (int nt = 0; nt < 4; nt++) {
            int c0 = w*32 + nt*8 + e0;
            *(float2*)(omid + (long)bs*8192 + m_*512 + c0)     = make_float2(oacc[nt][0]*li0, oacc[nt][1]*li0);
            *(float2*)(omid + (long)bs*8192 + (m_+8)*512 + c0) = make_float2(oacc[nt][2]*li1, oacc[nt][3]*li1);
        }
    }
}

// ---------------- host orchestration (3-stream fork/join DAG) ------------------
extern "C" void kernel_launch(void* const* d_in, const int* in_sizes, int n_in,
                              void* d_out, int out_size) {
    const float* x      = (const float*)d_in[0];
    const float* fcos   = (const float*)d_in[1];
    const float* fsin   = (const float*)d_in[2];
    const float* mask   = (const float*)d_in[3];
    const float* wq_a   = (const float*)d_in[4];
    const float* qnw    = (const float*)d_in[5];
    const float* wq_b   = (const float*)d_in[6];
    const float* wkv_a  = (const float*)d_in[7];
    const float* kvnw   = (const float*)d_in[8];
    const float* wkv_b  = (const float*)d_in[9];
    const float* wo     = (const float*)d_in[10];
    const float* iwqb   = (const float*)d_in[11];
    const float* iwk    = (const float*)d_in[12];
    const float* iknw   = (const float*)d_in[13];
    const float* iknb   = (const float*)d_in[14];
    const float* iwp    = (const float*)d_in[15];
    float* out = (float*)d_out;

    float *qr, *q, *kvfull, *kv, *kpe, *qabs, *qi, *ki, *wts, *iscore, *omid, *o2, *wt;
    __nv_bfloat16 *khi, *klo;
    int* topkb;
    cudaGetSymbolAddress((void**)&qr,     g_qr);
    cudaGetSymbolAddress((void**)&q,      g_q);
    cudaGetSymbolAddress((void**)&kvfull, g_kvfull);
    cudaGetSymbolAddress((void**)&kv,     g_kv);
    cudaGetSymbolAddress((void**)&kpe,    g_kpe);
    cudaGetSymbolAddress((void**)&qabs,   g_qabs);
    cudaGetSymbolAddress((void**)&qi,     g_qi);
    cudaGetSymbolAddress((void**)&ki,     g_ki);
    cudaGetSymbolAddress((void**)&wts,    g_wts);
    cudaGetSymbolAddress((void**)&iscore, g_iscore);
    cudaGetSymbolAddress((void**)&topkb,  g_topk);
    cudaGetSymbolAddress((void**)&omid,   g_omid);
    cudaGetSymbolAddress((void**)&o2,     g_o2);
    cudaGetSymbolAddress((void**)&wt,     g_wkvbT);
    cudaGetSymbolAddress((void**)&khi,    g_khi);
    cudaGetSymbolAddress((void**)&klo,    g_klo);

    cudaFuncSetAttribute(gemm_mma, cudaFuncAttributeMaxDynamicSharedMemorySize, GM_SMEM);
    cudaFuncSetAttribute(attn_tc,  cudaFuncAttributeMaxDynamicSharedMemorySize, AT_SMEM);

    static cudaStream_t s1 = 0, s2 = 0;
    static cudaEvent_t eF = 0, eQR = 0, eWT = 0, eJ1 = 0;
    if (s1 == 0) {
        cudaStreamCreateWithFlags(&s1, cudaStreamNonBlocking);
        cudaStreamCreateWithFlags(&s2, cudaStreamNonBlocking);
        cudaEventCreateWithFlags(&eF,  cudaEventDisableTiming);
        cudaEventCreateWithFlags(&eQR, cudaEventDisableTiming);
        cudaEventCreateWithFlags(&eWT, cudaEventDisableTiming);
        cudaEventCreateWithFlags(&eJ1, cudaEventDisableTiming);
    }
    cudaStream_t s0 = 0;

    cudaEventRecord(eF, s0);
    cudaStreamWaitEvent(s1, eF, 0);
    cudaStreamWaitEvent(s2, eF, 0);

    // ---- s0: qr chain -> q chain -> attention -> output
    gemm_bt<<<dim3(6, 32, 1), 256, 0, s0>>>(x, 2048, 0, wq_a, 2048, 0, qr, 768, 0, 4096, 768, 2048);
    rmsnorm_kernel<<<4096, 256, 0, s0>>>(qr, qnw, 768);
    cudaEventRecord(eQR, s0);

    // ---- s2: kv path + weight transpose
    gemm_mma<<<dim3(5, 32, 1), 256, GM_SMEM, s2>>>(x, 2048, 0, wkv_a, 2048, 0, kvfull, 576, 0, 4096, 576, 2048);
    kvpost_kernel<<<4096, 256, 0, s2>>>(kvfull, kvnw, fcos, fsin, kv, kpe);
    kvsplit_kernel<<<(BS_*576 + 255)/256, 256, 0, s2>>>(kv, kpe, khi, klo);
    transpose_wkvb<<<(16*128*512 + 255)/256, 256, 0, s2>>>(wkv_b, wt);
    cudaEventRecord(eWT, s2);

    // ---- s1: indexer path
    gemm_bt<<<dim3(1, 32, 1), 256, 0, s1>>>(x, 2048, 0, iwk, 2048, 0, ki, 128, 0, 4096, 128, 2048);
    kipost_kernel<<<4096, 128, 0, s1>>>(ki, iknw, iknb, fcos, fsin);
    gemm_bt<<<dim3(1, 32, 1), 256, 0, s1>>>(x, 2048, 0, iwp, 2048, 0, wts, 16, 0, 4096, 16, 2048);
    cudaStreamWaitEvent(s1, eQR, 0);
    gemm_bt<<<dim3(16, 32, 1), 256, 0, s1>>>(qr, 768, 0, iwqb, 768, 0, qi, 2048, 0, 4096, 2048, 768);
    rope_qi_kernel<<<(BS_*16*32 + 255)/256, 256, 0, s1>>>(qi, fcos, fsin);
    iscore_kernel<<<dim3(32, 16, 2), 256, 0, s1>>>(qi, ki, wts, mask, iscore);
    topk_kernel<<<4096, 256, 0, s1>>>(iscore, topkb);
    cudaEventRecord(eJ1, s1);

    // ---- s0 continues
    gemm_mma<<<dim3(24, 32, 1), 256, GM_SMEM, s0>>>(qr, 768, 0, wq_b, 768, 0, q, 3072, 0, 4096, 3072, 768);
    rope_q_kernel<<<(BS_*16*32 + 255)/256, 256, 0, s0>>>(q, fcos, fsin);
    cudaStreamWaitEvent(s0, eWT, 0);
    gemm_mma<<<dim3(4, 32, 16), 256, GM_SMEM, s0>>>(q, 3072, 192, wt, 128, 65536, qabs, 8192, 512,
                                                    4096, 512, 128);
    cudaStreamWaitEvent(s0, eJ1, 0);
    attn_tc<<<4096, 512, AT_SMEM, s0>>>(qabs, q, khi, klo, topkb, omid);
    gemm_mma<<<dim3(1, 32, 16), 256, GM_SMEM, s0>>>(omid, 8192, 512, wkv_b + 128*512, 512, 256*512,
                                                    o2, 2048, 128, 4096, 128, 512);
    gemm_mma<<<dim3(16, 32, 1), 256, GM_SMEM, s0>>>(o2, 2048, 0, wo, 2048, 0, out, 2048, 0, 4096, 2048, 2048);
}

// round 9
// speedup vs baseline: 1.9571x; 1.0050x over previous
#include <cuda_runtime.h>
#include <cuda_bf16.h>
#include <math.h>
#include <stdint.h>

// Problem constants
#define B_    2
#define S_    2048
#define DIM_  2048
#define NH_   16
#define QLR_  768
#define KVLR_ 512
#define NOPE_ 128
#define ROPE_ 64
#define VDIM_ 128
#define IH_   16
#define IHD_  128
#define ITOPK_ 512
#define BS_   (B_*S_)   // 4096

// ---------------- scratch (device globals; no allocation allowed) -------------
__device__ float g_qr[BS_*QLR_];
__device__ float g_q[BS_*NH_*(NOPE_+ROPE_)];
__device__ float g_kvfull[BS_*(KVLR_+ROPE_)];
__device__ float g_kv[BS_*KVLR_];
__device__ float g_kpe[BS_*ROPE_];
__device__ float g_qabs[BS_*NH_*KVLR_];
__device__ float g_qi[BS_*IH_*IHD_];
__device__ float g_ki[BS_*IHD_];
__device__ float g_wts[BS_*IH_];
__device__ float g_iscore[B_*S_*S_];
__device__ int   g_topk[BS_*ITOPK_];
__device__ float g_omid[BS_*NH_*KVLR_];
__device__ float g_o2[BS_*NH_*VDIM_];
__device__ float g_wkvbT[16*512*128];            // transposed wkv_b[:, :128, :] -> [h][c][d]
__device__ __nv_bfloat16 g_khi[BS_*576];         // kv||kpe hi split
__device__ __nv_bfloat16 g_klo[BS_*576];         // kv||kpe lo split

// =================== helpers ==================================================
__device__ __forceinline__ uint32_t smem_u32(const void* p) {
    uint32_t a;
    asm("{ .reg .u64 t; cvta.to.shared.u64 t, %1; cvt.u32.u64 %0, t; }" : "=r"(a) : "l"(p));
    return a;
}
__device__ __forceinline__ uint32_t pack_hi(float x, float y) {
    __nv_bfloat162 p;
    p.x = __float2bfloat16_rn(x);
    p.y = __float2bfloat16_rn(y);
    return *(uint32_t*)&p;
}
__device__ __forceinline__ uint32_t pack_lo(float x, float y) {
    __nv_bfloat16 hx = __float2bfloat16_rn(x);
    __nv_bfloat16 hy = __float2bfloat16_rn(y);
    __nv_bfloat162 p;
    p.x = __float2bfloat16_rn(x - __bfloat162float(hx));
    p.y = __float2bfloat16_rn(y - __bfloat162float(hy));
    return *(uint32_t*)&p;
}
__device__ __forceinline__ void mma16816(float* c, const uint32_t* a, const uint32_t* b) {
    asm volatile("mma.sync.aligned.m16n8k16.row.col.f32.bf16.bf16.f32 "
        "{%0,%1,%2,%3}, {%4,%5,%6,%7}, {%8,%9}, {%0,%1,%2,%3};"
        : "+f"(c[0]), "+f"(c[1]), "+f"(c[2]), "+f"(c[3])
        : "r"(a[0]), "r"(a[1]), "r"(a[2]), "r"(a[3]), "r"(b[0]), "r"(b[1]));
}
#define LDSM_X4(r, a) asm volatile("ldmatrix.sync.aligned.m8n8.x4.shared.b16 {%0,%1,%2,%3}, [%4];" \
    : "=r"((r)[0]),"=r"((r)[1]),"=r"((r)[2]),"=r"((r)[3]) : "r"(a))
#define LDSM_X2(r, a) asm volatile("ldmatrix.sync.aligned.m8n8.x2.shared.b16 {%0,%1}, [%2];" \
    : "=r"((r)[0]),"=r"((r)[1]) : "r"(a))
#define LDSM_X2T(r, a) asm volatile("ldmatrix.sync.aligned.m8n8.x2.trans.shared.b16 {%0,%1}, [%2];" \
    : "=r"((r)[0]),"=r"((r)[1]) : "r"(a))
#define CP_ASYNC16(dst, src) asm volatile("cp.async.cg.shared.global [%0], [%1], 16;" :: "r"(dst), "l"(src))
#define CP_COMMIT() asm volatile("cp.async.commit_group;" ::: "memory")
#define CP_WAIT(n)  asm volatile("cp.async.wait_group %0;" :: "n"(n) : "memory")

// word-granularity swizzled smem address for gemm_mma tiles (128 rows x 16 words)
__device__ __forceinline__ int sw_addr(int row, int w) {
    return row*16 + (w ^ ((((row)>>1)&3)<<2));
}

// =================== tensor-core GEMM (bf16x3): C[M,N]=A[M,K]@B[N,K]^T ========
#define GM_SMEM 65536

__global__ void __launch_bounds__(256, 1)
gemm_mma(const float* __restrict__ A, int lda, long aZ,
         const float* __restrict__ Bm, int ldb, long bZ,
         float* __restrict__ C, int ldc, long cZ,
         int M, int N, int K) {
    extern __shared__ uint32_t smw[];
    A  += (long)blockIdx.z * aZ;
    Bm += (long)blockIdx.z * bZ;
    C  += (long)blockIdx.z * cZ;
    int m0 = blockIdx.y * 128, n0 = blockIdx.x * 128;
    int tid = threadIdx.x, lane = tid & 31, wid = tid >> 5;
    int wm = wid >> 2, wn = wid & 3;
    int g = lane >> 2, tig = lane & 3;

    float acc[4][4][4];
#pragma unroll
    for (int i = 0; i < 4; i++)
#pragma unroll
        for (int j = 0; j < 4; j++)
#pragma unroll
            for (int r = 0; r < 4; r++) acc[i][j][r] = 0.f;

    int arow = tid >> 1, acol = (tid & 1) * 16;
    int nch = K >> 5;

    float4 ra[4], rb[4];
    {
        const float* ap = A + (long)(m0 + arow)*lda + acol;
        bool aok = (m0 + arow) < M;
#pragma unroll
        for (int i = 0; i < 4; i++)
            ra[i] = aok ? *(const float4*)(ap + i*4) : make_float4(0.f,0.f,0.f,0.f);
        const float* bp = Bm + (long)(n0 + arow)*ldb + acol;
        bool bok = (n0 + arow) < N;
#pragma unroll
        for (int i = 0; i < 4; i++)
            rb[i] = bok ? *(const float4*)(bp + i*4) : make_float4(0.f,0.f,0.f,0.f);
    }

    for (int it = 0; it < nch; it++) {
        int stg = it & 1;
        uint32_t* sAhi = smw + stg*8192;
        uint32_t* sAlo = sAhi + 2048;
        uint32_t* sBhi = sAhi + 4096;
        uint32_t* sBlo = sAhi + 6144;
        {
            uint32_t hw[8], lw[8];
#pragma unroll
            for (int i = 0; i < 4; i++) {
                hw[i*2]   = pack_hi(ra[i].x, ra[i].y);
                hw[i*2+1] = pack_hi(ra[i].z, ra[i].w);
                lw[i*2]   = pack_lo(ra[i].x, ra[i].y);
                lw[i*2+1] = pack_lo(ra[i].z, ra[i].w);
            }
            int g0 = (((tid&1)*2 + 0) ^ ((arow>>1)&3)) * 4;
            int g1 = (((tid&1)*2 + 1) ^ ((arow>>1)&3)) * 4;
            uint32_t* dst = sAhi + arow*16;
            *(uint4*)(dst + g0) = make_uint4(hw[0],hw[1],hw[2],hw[3]);
            *(uint4*)(dst + g1) = make_uint4(hw[4],hw[5],hw[6],hw[7]);
            dst = sAlo + arow*16;
            *(uint4*)(dst + g0) = make_uint4(lw[0],lw[1],lw[2],lw[3]);
            *(uint4*)(dst + g1) = make_uint4(lw[4],lw[5],lw[6],lw[7]);
#pragma unroll
            for (int i = 0; i < 4; i++) {
                hw[i*2]   = pack_hi(rb[i].x, rb[i].y);
                hw[i*2+1] = pack_hi(rb[i].z, rb[i].w);
                lw[i*2]   = pack_lo(rb[i].x, rb[i].y);
                lw[i*2+1] = pack_lo(rb[i].z, rb[i].w);
            }
            dst = sBhi + arow*16;
            *(uint4*)(dst + g0) = make_uint4(hw[0],hw[1],hw[2],hw[3]);
            *(uint4*)(dst + g1) = make_uint4(hw[4],hw[5],hw[6],hw[7]);
            dst = sBlo + arow*16;
            *(uint4*)(dst + g0) = make_uint4(lw[0],lw[1],lw[2],lw[3]);
            *(uint4*)(dst + g1) = make_uint4(lw[4],lw[5],lw[6],lw[7]);
        }
        __syncthreads();
        if (it + 1 < nch) {
            int gk = (it + 1) << 5;
            const float* ap = A + (long)(m0 + arow)*lda + gk + acol;
            bool aok = (m0 + arow) < M;
#pragma unroll
            for (int i = 0; i < 4; i++)
                ra[i] = aok ? *(const float4*)(ap + i*4) : make_float4(0.f,0.f,0.f,0.f);
            const float* bp = Bm + (long)(n0 + arow)*ldb + gk + acol;
            bool bok = (n0 + arow) < N;
#pragma unroll
            for (int i = 0; i < 4; i++)
                rb[i] = bok ? *(const float4*)(bp + i*4) : make_float4(0.f,0.f,0.f,0.f);
        }
#pragma unroll
        for (int ks = 0; ks < 2; ks++) {
            uint32_t bh[4][2], bl[4][2];
#pragma unroll
            for (int nt = 0; nt < 4; nt++) {
                int nrow = wn*32 + nt*8 + g;
                int w0 = ks*8 + tig;
                bh[nt][0] = sBhi[sw_addr(nrow, w0)];
                bh[nt][1] = sBhi[sw_addr(nrow, w0+4)];
                bl[nt][0] = sBlo[sw_addr(nrow, w0)];
                bl[nt][1] = sBlo[sw_addr(nrow, w0+4)];
            }
#pragma unroll
            for (int mt = 0; mt < 4; mt++) {
                int ar = wm*64 + mt*16 + g;
                int w0 = ks*8 + tig;
                uint32_t ah[4], al[4];
                ah[0] = sAhi[sw_addr(ar,   w0)];
                ah[1] = sAhi[sw_addr(ar+8, w0)];
                ah[2] = sAhi[sw_addr(ar,   w0+4)];
                ah[3] = sAhi[sw_addr(ar+8, w0+4)];
                al[0] = sAlo[sw_addr(ar,   w0)];
                al[1] = sAlo[sw_addr(ar+8, w0)];
                al[2] = sAlo[sw_addr(ar,   w0+4)];
                al[3] = sAlo[sw_addr(ar+8, w0+4)];
#pragma unroll
                for (int nt = 0; nt < 4; nt++) {
                    mma16816(acc[mt][nt], ah, bh[nt]);
                    mma16816(acc[mt][nt], ah, bl[nt]);
                    mma16816(acc[mt][nt], al, bh[nt]);
                }
            }
        }
        __syncthreads();
    }
#pragma unroll
    for (int mt = 0; mt < 4; mt++) {
#pragma unroll
        for (int nt = 0; nt < 4; nt++) {
            int r0 = m0 + wm*64 + mt*16 + g;
            int c0 = n0 + wn*32 + nt*8 + tig*2;
            if (c0 < N) {
                if (r0 < M)
                    *(float2*)(C + (long)r0*ldc + c0) = make_float2(acc[mt][nt][0], acc[mt][nt][1]);
                if (r0 + 8 < M)
                    *(float2*)(C + (long)(r0+8)*ldc + c0) = make_float2(acc[mt][nt][2], acc[mt][nt][3]);
            }
        }
    }
}

// transpose wkv_b[:, :128, :] -> wt[h][c][d]
__global__ void transpose_wkvb(const float* __restrict__ w, float* __restrict__ wt) {
    int idx = blockIdx.x * 256 + threadIdx.x;
    if (idx >= 16*128*512) return;
    int c = idx & 511, d = (idx >> 9) & 127, h = idx >> 16;
    wt[h*65536 + c*128 + d] = w[h*131072 + d*512 + c];
}

// ---------------- fp32 GEMM (bit-exact k-order): C[M,N] = A[M,K] @ B[N,K]^T ---
__global__ void __launch_bounds__(256)
gemm_bt(const float* __restrict__ A, int lda, long aZ,
        const float* __restrict__ Bm, int ldb, long bZ,
        float* __restrict__ C, int ldc, long cZ,
        int M, int N, int K) {
    A  += (long)blockIdx.z * aZ;
    Bm += (long)blockIdx.z * bZ;
    C  += (long)blockIdx.z * cZ;
    int n0 = blockIdx.x * 128, m0 = blockIdx.y * 128;
    __shared__ float As[16][129];
    __shared__ float Bs[16][129];
    int tid = threadIdx.x;
    int tx = tid & 15, ty = tid >> 4;
    int kl = tid & 15, ml = tid >> 4;
    float acc[8][8];
#pragma unroll
    for (int i = 0; i < 8; i++)
#pragma unroll
        for (int j = 0; j < 8; j++) acc[i][j] = 0.f;

    for (int k0 = 0; k0 < K; k0 += 16) {
#pragma unroll
        for (int r = 0; r < 8; r++) {
            int mm = ml + 16*r;
            int gm = m0 + mm, gk = k0 + kl;
            As[kl][mm] = (gm < M && gk < K) ? A[(long)gm*lda + gk] : 0.f;
            int gn = n0 + mm;
            Bs[kl][mm] = (gn < N && gk < K) ? Bm[(long)gn*ldb + gk] : 0.f;
        }
        __syncthreads();
#pragma unroll
        for (int kk = 0; kk < 16; kk++) {
            float a[8], bb[8];
#pragma unroll
            for (int i = 0; i < 8; i++) a[i]  = As[kk][ty + 16*i];
#pragma unroll
            for (int j = 0; j < 8; j++) bb[j] = Bs[kk][tx + 16*j];
#pragma unroll
            for (int i = 0; i < 8; i++)
#pragma unroll
                for (int j = 0; j < 8; j++) acc[i][j] += a[i]*bb[j];
        }
        __syncthreads();
    }
#pragma unroll
    for (int i = 0; i < 8; i++)
#pragma unroll
        for (int j = 0; j < 8; j++) {
            int gm = m0 + ty + 16*i, gn = n0 + tx + 16*j;
            if (gm < M && gn < N) C[(long)gm*ldc + gn] = acc[i][j];
        }
}

// ---------------- elementwise / norm / rope -----------------------------------
__global__ void rmsnorm_kernel(float* __restrict__ x, const float* __restrict__ w, int L) {
    int row = blockIdx.x, tid = threadIdx.x;
    float* pr = x + (long)row * L;
    float ss = 0.f;
    for (int i = tid; i < L; i += 256) { float v = pr[i]; ss += v*v; }
    __shared__ float red[256];
    red[tid] = ss; __syncthreads();
    for (int o = 128; o > 0; o >>= 1) { if (tid < o) red[tid] += red[tid+o]; __syncthreads(); }
    float inv = rsqrtf(red[0] / (float)L + 1e-6f);
    for (int i = tid; i < L; i += 256) pr[i] = w[i] * pr[i] * inv;
}

__global__ void kvpost_kernel(const float* __restrict__ kvfull, const float* __restrict__ w,
                              const float* __restrict__ fcos, const float* __restrict__ fsin,
                              float* __restrict__ kv, float* __restrict__ kpe) {
    int row = blockIdx.x, s = row & (S_-1), tid = threadIdx.x;
    const float* src = kvfull + (long)row * 576;
    float ss = 0.f;
    for (int i = tid; i < 512; i += 256) { float v = src[i]; ss += v*v; }
    __shared__ float red[256];
    red[tid] = ss; __syncthreads();
    for (int o = 128; o > 0; o >>= 1) { if (tid < o) red[tid] += red[tid+o]; __syncthreads(); }
    float inv = rsqrtf(red[0] / 512.f + 1e-6f);
    for (int i = tid; i < 512; i += 256) kv[(long)row*512 + i] = w[i] * src[i] * inv;
    if (tid < 32) {
        float x1 = src[512 + tid], x2 = src[544 + tid];
        float c = fcos[s*32 + tid], sn = fsin[s*32 + tid];
        kpe[(long)row*64 + tid]      = x1*c - x2*sn;
        kpe[(long)row*64 + 32 + tid] = x1*sn + x2*c;
    }
}

// split kv||kpe into bf16 hi/lo global arrays
__global__ void kvsplit_kernel(const float* __restrict__ kv, const float* __restrict__ kpe,
                               __nv_bfloat16* __restrict__ khi, __nv_bfloat16* __restrict__ klo) {
    int idx = blockIdx.x*256 + threadIdx.x;
    if (idx >= BS_*576) return;
    int r = idx / 576, d = idx - r*576;
    float v = (d < 512) ? kv[(long)r*512 + d] : kpe[(long)r*64 + d - 512];
    __nv_bfloat16 hi = __float2bfloat16_rn(v);
    khi[idx] = hi;
    klo[idx] = __float2bfloat16_rn(v - __bfloat162float(hi));
}

__global__ void kipost_kernel(float* __restrict__ ki, const float* __restrict__ w,
                              const float* __restrict__ bvec,
                              const float* __restrict__ fcos, const float* __restrict__ fsin) {
    int row = blockIdx.x, s = row & (S_-1), tid = threadIdx.x; // 128 threads
    float* pr = ki + (long)row * 128;
    float v = pr[tid];
    __shared__ float red[128];
    red[tid] = v; __syncthreads();
    for (int o = 64; o > 0; o >>= 1) { if (tid < o) red[tid] += red[tid+o]; __syncthreads(); }
    float mean = red[0] / 128.f;
    __syncthreads();
    float d = v - mean;
    red[tid] = d*d; __syncthreads();
    for (int o = 64; o > 0; o >>= 1) { if (tid < o) red[tid] += red[tid+o]; __syncthreads(); }
    float var = red[0] / 128.f;
    __syncthreads();
    float y = d * rsqrtf(var + 1e-6f) * w[tid] + bvec[tid];
    __shared__ float yb[128];
    yb[tid] = y; __syncthreads();
    float outv;
    if (tid < 32) {
        float c = fcos[s*32 + tid], sn = fsin[s*32 + tid];
        outv = yb[tid]*c - yb[tid+32]*sn;
    } else if (tid < 64) {
        int i = tid - 32;
        float c = fcos[s*32 + i], sn = fsin[s*32 + i];
        outv = yb[i]*sn + yb[tid]*c;
    } else {
        outv = y;
    }
    pr[tid] = outv;
}

__global__ void rope_q_kernel(float* __restrict__ q, const float* __restrict__ fcos,
                              const float* __restrict__ fsin) {
    int idx = blockIdx.x * blockDim.x + threadIdx.x;
    if (idx >= BS_*16*32) return;
    int i = idx & 31, h = (idx >> 5) & 15, bs = idx >> 9;
    int s = bs & (S_-1);
    long base = (long)bs*3072 + h*192 + 128;
    float x1 = q[base + i], x2 = q[base + 32 + i];
    float c = fcos[s*32 + i], sn = fsin[s*32 + i];
    q[base + i]      = x1*c - x2*sn;
    q[base + 32 + i] = x1*sn + x2*c;
}

__global__ void rope_qi_kernel(float* __restrict__ qi, const float* __restrict__ fcos,
                               const float* __restrict__ fsin) {
    int idx = blockIdx.x * blockDim.x + threadIdx.x;
    if (idx >= BS_*16*32) return;
    int i = idx & 31, h = (idx >> 5) & 15, bs = idx >> 9;
    int s = bs & (S_-1);
    long base = (long)bs*2048 + h*128;
    float x1 = qi[base + i], x2 = qi[base + 32 + i];
    float c = fcos[s*32 + i], sn = fsin[s*32 + i];
    qi[base + i]      = x1*c - x2*sn;
    qi[base + 32 + i] = x1*sn + x2*c;
}

// ---------------- indexer score (128s x 64t tile, 2 heads/pass, bit-exact) ----
// Pointers are pre-offset per batch; masked tiles are skipped entirely (their
// region of iscore is never read by the prefix-only topk).
__global__ void __launch_bounds__(256)
iscore_kernel(const float* __restrict__ qi, const float* __restrict__ ki,
              const float* __restrict__ wts, const float* __restrict__ mask,
              float* __restrict__ iscore) {
    int s0 = blockIdx.y * 128, t0 = blockIdx.x * 64;
    int tid = threadIdx.x;
    if (t0 > s0 + 127) return;   // fully-masked tile: never read downstream
    int tx = tid & 15, ty = tid >> 4;
    int kl = tid & 15, ml = tid >> 4;
    __shared__ float qs[2][16][129];
    __shared__ float ks[16][65];
    __shared__ float ws_s[16][128];
    const float IW_SCALE = rsqrtf(2048.0f);
    for (int i = tid; i < 16*128; i += 256) {
        int m = i >> 4, h = i & 15;
        ws_s[h][m] = wts[((long)(s0 + m))*16 + h] * IW_SCALE;
    }
    float acc[8][4];
#pragma unroll
    for (int i = 0; i < 8; i++)
#pragma unroll
        for (int j = 0; j < 4; j++) acc[i][j] = 0.f;
    __syncthreads();

    for (int h = 0; h < 16; h += 2) {
        float dot[2][8][4];
#pragma unroll
        for (int e = 0; e < 2; e++)
#pragma unroll
            for (int i = 0; i < 8; i++)
#pragma unroll
                for (int j = 0; j < 4; j++) dot[e][i][j] = 0.f;
        for (int d0 = 0; d0 < 128; d0 += 16) {
#pragma unroll
            for (int e = 0; e < 2; e++)
#pragma unroll
                for (int r = 0; r < 8; r++) {
                    int mm = ml + 16*r;
                    qs[e][kl][mm] = qi[((long)(s0 + mm))*2048 + (h+e)*128 + d0 + kl];
                }
#pragma unroll
            for (int r = 0; r < 4; r++) {
                int mm = ml + 16*r;
                ks[kl][mm] = ki[((long)(t0 + mm))*128 + d0 + kl];
            }
            __syncthreads();
#pragma unroll
            for (int kk = 0; kk < 16; kk++) {
                float a0[8], a1[8], bb[4];
#pragma unroll
                for (int i = 0; i < 8; i++) { a0[i] = qs[0][kk][ty + 16*i]; a1[i] = qs[1][kk][ty + 16*i]; }
#pragma unroll
                for (int j = 0; j < 4; j++) bb[j] = ks[kk][tx + 16*j];
#pragma unroll
                for (int i = 0; i < 8; i++)
#pragma unroll
                    for (int j = 0; j < 4; j++) {
                        dot[0][i][j] += a0[i]*bb[j];
                        dot[1][i][j] += a1[i]*bb[j];
                    }
            }
            __syncthreads();
        }
#pragma unroll
        for (int e = 0; e < 2; e++)
#pragma unroll
            for (int i = 0; i < 8; i++) {
                float w = ws_s[h+e][ty + 16*i];
#pragma unroll
                for (int j = 0; j < 4; j++) acc[i][j] += fmaxf(dot[e][i][j], 0.f) * w;
            }
    }
#pragma unroll
    for (int i = 0; i < 8; i++)
#pragma unroll
        for (int j = 0; j < 4; j++) {
            int s = s0 + ty + 16*i, t = t0 + tx + 16*j;
            iscore[((long)s)*S_ + t] = acc[i][j] + mask[(long)s*S_ + t];
        }
}

// ---------------- exact top-512 per row (prefix-only radix, deterministic) ----
// Pointers pre-offset per batch; row index = blockIdx.x = s.
// Entries t>s are exactly NEG (-1e9) and strictly below the 512th real value
// when s>=512; when s<512 the answer is indices 0..511 (real + index-ordered
// tie fill) — both cases bit-identical to the full-row scan.
__global__ void topk_kernel(const float* __restrict__ iscore, int* __restrict__ out) {
    int s = blockIdx.x;
    int tid = threadIdx.x; // 256
    int* o = out + (long)s * ITOPK_;
    if (s < ITOPK_) {
        for (int j = tid; j < ITOPK_; j += 256) o[j] = j;
        return;
    }
    const float* p = iscore + (long)s * S_;
    __shared__ unsigned int hist[256];
    __shared__ unsigned int s_prefix;
    __shared__ int s_rem;
    __shared__ int sgt[257], seq[257];
    if (tid == 0) { s_prefix = 0u; s_rem = ITOPK_; }
    __syncthreads();
    for (int pass = 0; pass < 4; pass++) {
        hist[tid] = 0u;
        __syncthreads();
        int shift = 24 - 8*pass;
        unsigned int pref = s_prefix;
        for (int e = 0; e < 8; e++) {
            int j = tid*8 + e;
            if (j > s) break;
            unsigned int u = __float_as_uint(p[j]);
            unsigned int k = (u & 0x80000000u) ? ~u : (u | 0x80000000u);
            bool ok = (pass == 0) || (((k ^ pref) >> (shift + 8)) == 0u);
            if (ok) atomicAdd(&hist[(k >> shift) & 255u], 1u);
        }
        __syncthreads();
        if (tid == 0) {
            int rem = s_rem;
            unsigned int cum = 0; int bin = 0;
            for (int bb = 255; bb >= 0; bb--) {
                if (cum + hist[bb] >= (unsigned)rem) { bin = bb; break; }
                cum += hist[bb];
            }
            s_rem = rem - (int)cum;
            s_prefix = s_prefix | ((unsigned)bin << shift);
        }
        __syncthreads();
    }
    unsigned int kth = s_prefix;
    int cgt = 0, ceq = 0;
    for (int e = 0; e < 8; e++) {
        int j = tid*8 + e;
        if (j > s) break;
        unsigned int u = __float_as_uint(p[j]);
        unsigned int k = (u & 0x80000000u) ? ~u : (u | 0x80000000u);
        cgt += (k > kth); ceq += (k == kth);
    }
    sgt[tid] = cgt; seq[tid] = ceq;
    __syncthreads();
    if (tid == 0) {
        int ag = 0, ae = 0;
        for (int i = 0; i < 256; i++) {
            int tg = sgt[i], te = seq[i];
            sgt[i] = ag; seq[i] = ae;
            ag += tg; ae += te;
        }
        sgt[256] = ag;
    }
    __syncthreads();
    int total_gt = sgt[256];
    int pgt = sgt[tid];
    int peq = total_gt + seq[tid];
    for (int e = 0; e < 8; e++) {
        int j = tid*8 + e;
        if (j > s) break;
        unsigned int u = __float_as_uint(p[j]);
        unsigned int k = (u & 0x80000000u) ? ~u : (u | 0x80000000u);
        if (k > kth) { o[pgt++] = j; }
        else if (k == kth) { if (peq < ITOPK_) o[peq] = j; peq++; }
    }
}

// ---------------- fused flash-style tensor-core sparse attention ---------------
// 512 threads / 16 warps, Q hi-fragments hoisted. b0 selects the batch half.
#define AT_SMEM 200448
#define AT_BUF0 50944
#define AT_BUFSZ 74752
#define AT_LO 37376

__device__ __forceinline__ void at_gather(const __nv_bfloat16* __restrict__ khi,
                                          const __nv_bfloat16* __restrict__ klo,
                                          long kb, const int* tl, int c,
                                          uint32_t bufaddr, int tid) {
    int jloc = tid >> 4, sg0 = tid & 15;   // 32 rows x 16 threads
    int t = tl[c*32 + jloc];
    const char* sh = (const char*)(khi + kb + (long)t*576);
    const char* sl = (const char*)(klo + kb + (long)t*576);
    uint32_t dh = bufaddr + jloc*1168;
#pragma unroll
    for (int u = 0; u < 9; u++) {
        int ch = sg0 + u*16;               // 0..143: 72 hi chunks then 72 lo
        if (ch < 72) CP_ASYNC16(dh + ch*16, sh + ch*16);
        else         CP_ASYNC16(dh + AT_LO + (ch-72)*16, sl + (ch-72)*16);
    }
    CP_COMMIT();
}

__global__ void __launch_bounds__(512, 1)
attn_tc(const float* __restrict__ qabs, const float* __restrict__ qfull,
        const __nv_bfloat16* __restrict__ khi, const __nv_bfloat16* __restrict__ klo,
        const int* __restrict__ topk, float* __restrict__ omid, int b0) {
    extern __shared__ char sm[];
    uint32_t sb = smem_u32(sm);
    int* tl = (int*)sm;
    float* m_s  = (float*)(sm + 2048);
    float* l_s  = (float*)(sm + 2112);
    float* al_s = (float*)(sm + 2176);
    float* sc   = (float*)(sm + 2304);       // [4][16][34]
    __nv_bfloat16* qh = (__nv_bfloat16*)(sm + 11008);
    __nv_bfloat16* ph = (__nv_bfloat16*)(sm + 48384);
    __nv_bfloat16* pl = (__nv_bfloat16*)(sm + 49664);
    int s = blockIdx.x;
    int bs = b0*S_ + s;
    int tid = threadIdx.x, lane = tid & 31, w = tid >> 5;
    const long kb = (long)b0 * 2048 * 576;

    for (int j = tid; j < 512; j += 512) tl[j] = topk[(long)bs*512 + j];
    if (tid < 16) { m_s[tid] = -1e30f; l_s[tid] = 0.f; }
    const float scale = 0.07216878364870322f;  // 1/sqrt(192)
    __syncthreads();
    for (int i = tid; i < 16*576; i += 512) {
        int h = i / 576, d = i - h*576;
        float v = (d < 512) ? qabs[(long)bs*8192 + h*512 + d]
                            : qfull[(long)bs*3072 + h*192 + 128 + (d - 512)];
        v *= scale;
        __nv_bfloat16 hi = __float2bfloat16_rn(v);
        qh[h*584 + d] = hi;
        qh[9344 + h*584 + d] = __float2bfloat16_rn(v - __bfloat162float(hi));  // ql region
    }
    at_gather(khi, klo, kb, tl, 0, sb + AT_BUF0, tid);
    __syncthreads();

    float oacc[4][4];
#pragma unroll
    for (int nt = 0; nt < 4; nt++)
#pragma unroll
        for (int r = 0; r < 4; r++) oacc[nt][r] = 0.f;

    int kh4 = w >> 2, nt4 = w & 3;
    int arow = lane & 15, ac = (lane >> 4) * 8;
    int brow = nt4*8 + (lane & 7), bc = ((lane >> 3) & 1) * 8;

    // ---- hoist Q hi fragments (loop-invariant across all 16 chunks)
    uint32_t ahq[9][4];
#pragma unroll
    for (int ks = 0; ks < 9; ks++) {
        int d = kh4*144 + ks*16;
        uint32_t ad = sb + 11008 + (arow*584 + d + ac)*2;
        LDSM_X4(ahq[ks], ad);
    }

    for (int c = 0; c < 16; c++) {
        uint32_t buf = sb + AT_BUF0 + (c & 1)*AT_BUFSZ;
        if (c < 15) {
            at_gather(khi, klo, kb, tl, c+1, sb + AT_BUF0 + ((c+1)&1)*AT_BUFSZ, tid);
            CP_WAIT(1);
        } else {
            CP_WAIT(0);
        }
        __syncthreads();

        // ---- QK partial: warp -> k-quarter kh4 (144 dims), token n-tile nt4
        float qk[4] = {0.f, 0.f, 0.f, 0.f};
#pragma unroll
        for (int ks = 0; ks < 9; ks++) {
            int d = kh4*144 + ks*16;
            uint32_t alr[4], bh[2], bl[2];
            uint32_t ad = sb + 11008 + (arow*584 + d + ac)*2;
            LDSM_X4(alr, ad + 18688);
            uint32_t bd = buf + (brow*584 + d + bc)*2;
            LDSM_X2(bh, bd);
            LDSM_X2(bl, bd + AT_LO);
            mma16816(qk, ahq[ks], bh);
            mma16816(qk, ahq[ks], bl);
            mma16816(qk, alr, bh);
        }
        {
            int m_ = lane >> 2, e0 = 2*(lane & 3);
            float* scr = sc + kh4*544;
            scr[m_*34 + nt4*8 + e0]       = qk[0];
            scr[m_*34 + nt4*8 + e0 + 1]   = qk[1];
            scr[(m_+8)*34 + nt4*8 + e0]   = qk[2];
            scr[(m_+8)*34 + nt4*8 + e0+1] = qk[3];
        }
        __syncthreads();

        // ---- online softmax: warp w handles head w; lane = local key
        {
            int t = tl[c*32 + lane];
            bool valid = (t <= s);
            int hh = w;
            float v = sc[hh*34 + lane] + sc[544 + hh*34 + lane]
                    + sc[1088 + hh*34 + lane] + sc[1632 + hh*34 + lane];
            float val = valid ? v : -1e30f;
            float mc = val;
#pragma unroll
            for (int o = 16; o > 0; o >>= 1) mc = fmaxf(mc, __shfl_xor_sync(0xffffffffu, mc, o));
            float m_old = m_s[hh];
            float m_new = fmaxf(m_old, mc);
            float a = expf(m_old - m_new);
            float p = valid ? expf(val - m_new) : 0.f;
            float psum = p;
#pragma unroll
            for (int o = 16; o > 0; o >>= 1) psum += __shfl_xor_sync(0xffffffffu, psum, o);
            if (lane == 0) { m_s[hh] = m_new; l_s[hh] = l_s[hh]*a + psum; al_s[hh] = a; }
            __nv_bfloat16 phi = __float2bfloat16_rn(p);
            ph[hh*40 + lane] = phi;
            pl[hh*40 + lane] = __float2bfloat16_rn(p - __bfloat162float(phi));
        }
        __syncthreads();

        // ---- rescale O and PV accumulate (warp w owns cols w*32..w*32+31)
        {
            float a0 = al_s[lane >> 2], a1 = al_s[(lane >> 2) + 8];
#pragma unroll
            for (int nt = 0; nt < 4; nt++) {
                oacc[nt][0] *= a0; oacc[nt][1] *= a0;
                oacc[nt][2] *= a1; oacc[nt][3] *= a1;
            }
            uint32_t ph4[2][4], pl4[2][4];
#pragma unroll
            for (int ks = 0; ks < 2; ks++) {
                uint32_t ad = sb + 48384 + (arow*40 + ks*16 + ac)*2;
                LDSM_X4(ph4[ks], ad);
                LDSM_X4(pl4[ks], ad + 1280);
            }
#pragma unroll
            for (int nt = 0; nt < 4; nt++) {
                int n0 = w*32 + nt*8;
#pragma unroll
                for (int ks = 0; ks < 2; ks++) {
                    uint32_t bd = buf + ((ks*16 + (lane & 15))*584 + n0)*2;
                    uint32_t vh[2], vl[2];
                    LDSM_X2T(vh, bd);
                    LDSM_X2T(vl, bd + AT_LO);
                    mma16816(oacc[nt], ph4[ks], vh);
                    mma16816(oacc[nt], ph4[ks], vl);
                    mma16816(oacc[nt], pl4[ks], vh);
                }
            }
        }
        __syncthreads();
    }

    {
        int m_ = lane >> 2, e0 = 2*(lane & 3);
        float li0 = 1.f / l_s[m_];
        float li1 = 1.f / l_s[m_ + 8];
#pragma unroll
        for (int nt = 0; nt < 4; nt++) {
            int c0 = w*32 + nt*8 + e0;
            *(float2*)(omid + (long)bs*8192 + m_*512 + c0)     = make_float2(oacc[nt][0]*li0, oacc[nt][1]*li0);
            *(float2*)(omid + (long)bs*8192 + (m_+8)*512 + c0) = make_float2(oacc[nt][2]*li1, oacc[nt][3]*li1);
        }
    }
}

// ---------------- host orchestration (batch-pipelined fork/join DAG) -----------
extern "C" void kernel_launch(void* const* d_in, const int* in_sizes, int n_in,
                              void* d_out, int out_size) {
    const float* x      = (const float*)d_in[0];
    const float* fcos   = (const float*)d_in[1];
    const float* fsin   = (const float*)d_in[2];
    const float* mask   = (const float*)d_in[3];
    const float* wq_a   = (const float*)d_in[4];
    const float* qnw    = (const float*)d_in[5];
    const float* wq_b   = (const float*)d_in[6];
    const float* wkv_a  = (const float*)d_in[7];
    const float* kvnw   = (const float*)d_in[8];
    const float* wkv_b  = (const float*)d_in[9];
    const float* wo     = (const float*)d_in[10];
    const float* iwqb   = (const float*)d_in[11];
    const float* iwk    = (const float*)d_in[12];
    const float* iknw   = (const float*)d_in[13];
    const float* iknb   = (const float*)d_in[14];
    const float* iwp    = (const float*)d_in[15];
    float* out = (float*)d_out;

    float *qr, *q, *kvfull, *kv, *kpe, *qabs, *qi, *ki, *wts, *iscore, *omid, *o2, *wt;
    __nv_bfloat16 *khi, *klo;
    int* topkb;
    cudaGetSymbolAddress((void**)&qr,     g_qr);
    cudaGetSymbolAddress((void**)&q,      g_q);
    cudaGetSymbolAddress((void**)&kvfull, g_kvfull);
    cudaGetSymbolAddress((void**)&kv,     g_kv);
    cudaGetSymbolAddress((void**)&kpe,    g_kpe);
    cudaGetSymbolAddress((void**)&qabs,   g_qabs);
    cudaGetSymbolAddress((void**)&qi,     g_qi);
    cudaGetSymbolAddress((void**)&ki,     g_ki);
    cudaGetSymbolAddress((void**)&wts,    g_wts);
    cudaGetSymbolAddress((void**)&iscore, g_iscore);
    cudaGetSymbolAddress((void**)&topkb,  g_topk);
    cudaGetSymbolAddress((void**)&omid,   g_omid);
    cudaGetSymbolAddress((void**)&o2,     g_o2);
    cudaGetSymbolAddress((void**)&wt,     g_wkvbT);
    cudaGetSymbolAddress((void**)&khi,    g_khi);
    cudaGetSymbolAddress((void**)&klo,    g_klo);

    cudaFuncSetAttribute(gemm_mma, cudaFuncAttributeMaxDynamicSharedMemorySize, GM_SMEM);
    cudaFuncSetAttribute(attn_tc,  cudaFuncAttributeMaxDynamicSharedMemorySize, AT_SMEM);

    static cudaStream_t s1 = 0, s2 = 0;
    static cudaEvent_t eF = 0, eQR = 0, eWT = 0, eT0 = 0, eT1 = 0;
    if (s1 == 0) {
        cudaStreamCreateWithFlags(&s1, cudaStreamNonBlocking);
        cudaStreamCreateWithFlags(&s2, cudaStreamNonBlocking);
        cudaEventCreateWithFlags(&eF,  cudaEventDisableTiming);
        cudaEventCreateWithFlags(&eQR, cudaEventDisableTiming);
        cudaEventCreateWithFlags(&eWT, cudaEventDisableTiming);
        cudaEventCreateWithFlags(&eT0, cudaEventDisableTiming);
        cudaEventCreateWithFlags(&eT1, cudaEventDisableTiming);
    }
    cudaStream_t s0 = 0;

    cudaEventRecord(eF, s0);
    cudaStreamWaitEvent(s1, eF, 0);
    cudaStreamWaitEvent(s2, eF, 0);

    // ---- s0: qr chain
    gemm_bt<<<dim3(6, 32, 1), 256, 0, s0>>>(x, 2048, 0, wq_a, 2048, 0, qr, 768, 0, 4096, 768, 2048);
    rmsnorm_kernel<<<4096, 256, 0, s0>>>(qr, qnw, 768);
    cudaEventRecord(eQR, s0);

    // ---- s2: kv path + weight transpose
    gemm_mma<<<dim3(5, 32, 1), 256, GM_SMEM, s2>>>(x, 2048, 0, wkv_a, 2048, 0, kvfull, 576, 0, 4096, 576, 2048);
    kvpost_kernel<<<4096, 256, 0, s2>>>(kvfull, kvnw, fcos, fsin, kv, kpe);
    kvsplit_kernel<<<(BS_*576 + 255)/256, 256, 0, s2>>>(kv, kpe, khi, klo);
    transpose_wkvb<<<(16*128*512 + 255)/256, 256, 0, s2>>>(wkv_b, wt);
    cudaEventRecord(eWT, s2);

    // ---- s1: indexer path, batch-split
    gemm_bt<<<dim3(1, 32, 1), 256, 0, s1>>>(x, 2048, 0, iwk, 2048, 0, ki, 128, 0, 4096, 128, 2048);
    kipost_kernel<<<4096, 128, 0, s1>>>(ki, iknw, iknb, fcos, fsin);
    gemm_bt<<<dim3(1, 32, 1), 256, 0, s1>>>(x, 2048, 0, iwp, 2048, 0, wts, 16, 0, 4096, 16, 2048);
    cudaStreamWaitEvent(s1, eQR, 0);
    gemm_bt<<<dim3(16, 32, 1), 256, 0, s1>>>(qr, 768, 0, iwqb, 768, 0, qi, 2048, 0, 4096, 2048, 768);
    rope_qi_kernel<<<(BS_*16*32 + 255)/256, 256, 0, s1>>>(qi, fcos, fsin);
    // batch 0
    iscore_kernel<<<dim3(32, 16, 1), 256, 0, s1>>>(qi, ki, wts, mask, iscore);
    topk_kernel<<<2048, 256, 0, s1>>>(iscore, topkb);
    cudaEventRecord(eT0, s1);
    // batch 1 (pre-offset pointers)
    iscore_kernel<<<dim3(32, 16, 1), 256, 0, s1>>>(qi + (long)S_*2048, ki + (long)S_*128,
                                                   wts + (long)S_*16, mask, iscore + (long)S_*S_);
    topk_kernel<<<2048, 256, 0, s1>>>(iscore + (long)S_*S_, topkb + (long)S_*ITOPK_);
    cudaEventRecord(eT1, s1);

    // ---- s0 continues: q chain, qabs, then attention per batch
    gemm_mma<<<dim3(24, 32, 1), 256, GM_SMEM, s0>>>(qr, 768, 0, wq_b, 768, 0, q, 3072, 0, 4096, 3072, 768);
    rope_q_kernel<<<(BS_*16*32 + 255)/256, 256, 0, s0>>>(q, fcos, fsin);
    cudaStreamWaitEvent(s0, eWT, 0);
    gemm_mma<<<dim3(4, 32, 16), 256, GM_SMEM, s0>>>(q, 3072, 192, wt, 128, 65536, qabs, 8192, 512,
                                                    4096, 512, 128);
    cudaStreamWaitEvent(s0, eT0, 0);
    attn_tc<<<2048, 512, AT_SMEM, s0>>>(qabs, q, khi, klo, topkb, omid, 0);
    cudaStreamWaitEvent(s0, eT1, 0);
    attn_tc<<<2048, 512, AT_SMEM, s0>>>(qabs, q, khi, klo, topkb, omid, 1);
    gemm_mma<<<dim3(1, 32, 16), 256, GM_SMEM, s0>>>(omid, 8192, 512, wkv_b + 128*512, 512, 256*512,
                                                    o2, 2048, 128, 4096, 128, 512);
    gemm_mma<<<dim3(16, 32, 1), 256, GM_SMEM, s0>>>(o2, 2048, 0, wo, 2048, 0, out, 2048, 0, 4096, 2048, 2048);
}